// round 2
// baseline (speedup 1.0000x reference)
#include <cuda_runtime.h>
#include <float.h>
#include <math.h>

// Problem constants
#define B_    4
#define T_    1024
#define FEAT_ 512
#define H_    8
#define DK_   64
#define SPAN_ 100
#define PADL_ 50

// Attention tiling
#define TT_   16                    // t-positions per block (1 warp each)
#define ROWS_ (TT_ + SPAN_ - 1)     // 115 K/V rows needed per block
#define KSTR_ 68                    // padded row stride (floats)
#define SCSTR_ 104

// Scratch (allocation-free rule: __device__ globals)
__device__ float g_q[B_*T_*FEAT_];
__device__ float g_k[B_*T_*FEAT_];
__device__ float g_v[B_*T_*FEAT_];
__device__ float g_x[B_*T_*FEAT_];

// ---------------------------------------------------------------------------
// SGEMM: C[M,N] = A[M,K] @ W[K,N] + bias ; M=4096, N=K=512
// 64x64 block tile, BK=16, 256 threads, 4x4 per-thread microtile.
// ---------------------------------------------------------------------------
__global__ __launch_bounds__(256)
void gemm_bias_kernel(const float* __restrict__ A,
                      const float* __restrict__ W,
                      const float* __restrict__ bias,
                      float* __restrict__ C)
{
    const int N = 512, K = 512;
    __shared__ float As[16][64];   // As[k][m]
    __shared__ float Ws[16][64];   // Ws[k][n]

    const int tid = threadIdx.x;
    const int bm = blockIdx.x;     // 64 tiles of M
    const int bn = blockIdx.y;     // 8 tiles of N
    const int ty = tid >> 4;       // 0..15
    const int tx = tid & 15;       // 0..15

    const int arow = tid >> 2;     // 0..63
    const int ac4  = tid & 3;      // 0..3

    const float* Ablk = A + (size_t)(bm * 64) * K;
    const float* Wblk = W + bn * 64;

    float acc[4][4];
#pragma unroll
    for (int i = 0; i < 4; i++)
#pragma unroll
        for (int j = 0; j < 4; j++) acc[i][j] = 0.f;

    for (int kt = 0; kt < K; kt += 16) {
        float4 av = *(const float4*)(Ablk + (size_t)arow * K + kt + ac4 * 4);
        float4 wv = *(const float4*)(Wblk + (size_t)(kt + ty) * N + tx * 4);

        __syncthreads();
        As[ac4*4+0][arow] = av.x;
        As[ac4*4+1][arow] = av.y;
        As[ac4*4+2][arow] = av.z;
        As[ac4*4+3][arow] = av.w;
        *(float4*)(&Ws[ty][tx*4]) = wv;
        __syncthreads();

#pragma unroll
        for (int kk = 0; kk < 16; kk++) {
            float4 a4 = *(const float4*)(&As[kk][ty*4]);
            float4 b4 = *(const float4*)(&Ws[kk][tx*4]);
            acc[0][0] += a4.x*b4.x; acc[0][1] += a4.x*b4.y; acc[0][2] += a4.x*b4.z; acc[0][3] += a4.x*b4.w;
            acc[1][0] += a4.y*b4.x; acc[1][1] += a4.y*b4.y; acc[1][2] += a4.y*b4.z; acc[1][3] += a4.y*b4.w;
            acc[2][0] += a4.z*b4.x; acc[2][1] += a4.z*b4.y; acc[2][2] += a4.z*b4.z; acc[2][3] += a4.z*b4.w;
            acc[3][0] += a4.w*b4.x; acc[3][1] += a4.w*b4.y; acc[3][2] += a4.w*b4.z; acc[3][3] += a4.w*b4.w;
        }
    }

    const float4 bi = *(const float4*)(bias + bn*64 + tx*4);
#pragma unroll
    for (int i = 0; i < 4; i++) {
        float4 o;
        o.x = acc[i][0] + bi.x;
        o.y = acc[i][1] + bi.y;
        o.z = acc[i][2] + bi.z;
        o.w = acc[i][3] + bi.w;
        *(float4*)(C + (size_t)(bm*64 + ty*4 + i) * N + bn*64 + tx*4) = o;
    }
}

// ---------------------------------------------------------------------------
// Banded adaptive-span attention.
// grid = (T/TT_, B*H), block = 512 (16 warps, one t-position per warp).
// Q/K/V layout: [(b*T + t)*FEAT + h*DK + d]  (GEMM-natural, no transpose).
// ---------------------------------------------------------------------------
__global__ __launch_bounds__(512)
void attn_kernel(const int* __restrict__ mask,
                 const float* __restrict__ span)
{
    const int tb = blockIdx.x;
    const int bh = blockIdx.y;
    const int b = bh >> 3;          // / H_
    const int h = bh & 7;           // % H_
    const int t0 = tb * TT_;
    const int tid = threadIdx.x;
    const int wid = tid >> 5;
    const int lane = tid & 31;

    extern __shared__ float smem[];
    float* kt = smem;                         // [ROWS_][KSTR_]
    float* vt = kt + ROWS_ * KSTR_;           // [ROWS_][KSTR_]
    float* qt = vt + ROWS_ * KSTR_;           // [TT_][DK_]
    float* sc = qt + TT_ * DK_;               // [TT_][SCSTR_]

    const int j0 = t0 - PADL_;
    const size_t hd = (size_t)h * DK_;
    const float* kbase = g_k + (size_t)b * T_ * FEAT_ + hd;
    const float* vbase = g_v + (size_t)b * T_ * FEAT_ + hd;
    const float* qbase = g_q + (size_t)b * T_ * FEAT_ + hd;

    // Load K/V window (zero-fill OOB rows)
    for (int i = tid; i < ROWS_ * 16; i += 512) {
        int r = i >> 4, c4 = i & 15;
        int j = j0 + r;
        float4 k4 = make_float4(0.f, 0.f, 0.f, 0.f);
        float4 v4 = make_float4(0.f, 0.f, 0.f, 0.f);
        if (j >= 0 && j < T_) {
            k4 = *(const float4*)(kbase + (size_t)j * FEAT_ + c4 * 4);
            v4 = *(const float4*)(vbase + (size_t)j * FEAT_ + c4 * 4);
        }
        *(float4*)(kt + r * KSTR_ + c4 * 4) = k4;
        *(float4*)(vt + r * KSTR_ + c4 * 4) = v4;
    }
    // Load Q tile
    for (int i = tid; i < TT_ * 16; i += 512) {
        int r = i >> 4, c4 = i & 15;
        *(float4*)(qt + r * DK_ + c4 * 4) =
            *(const float4*)(qbase + (size_t)(t0 + r) * FEAT_ + c4 * 4);
    }
    __syncthreads();

    const int t = t0 + wid;
    const float spanv = span[h];

    // Phase 1: each lane owns s = lane, lane+32, lane+64, lane+96
    float scores[4];
    int   validf[4];
    float mx = -FLT_MAX;
    const float4* qrow = (const float4*)(qt + wid * DK_);
#pragma unroll
    for (int i = 0; i < 4; i++) {
        const int s = lane + 32 * i;
        scores[i] = -FLT_MAX;
        validf[i] = 0;
        if (s < SPAN_) {
            const int j = t + s - PADL_;
            if (j >= 0 && j < T_ && mask[b * T_ + j] != 0) {
                validf[i] = 1;
                const float4* krow = (const float4*)(kt + (wid + s) * KSTR_);
                float acc = 0.f;
#pragma unroll
                for (int c = 0; c < 16; c++) {
                    float4 k4 = krow[c];
                    float4 q4 = qrow[c];
                    acc += q4.x*k4.x + q4.y*k4.y + q4.z*k4.z + q4.w*k4.w;
                }
                scores[i] = acc * 0.125f;   // 1/sqrt(64)
                mx = fmaxf(mx, scores[i]);
            }
        }
    }
#pragma unroll
    for (int o = 16; o; o >>= 1) mx = fmaxf(mx, __shfl_xor_sync(0xffffffffu, mx, o));

    // e = exp(score-max); soft mask; E = sum e; S = sum e*soft
    float num[4];
    float E = 0.f, S = 0.f;
#pragma unroll
    for (int i = 0; i < 4; i++) {
        const int s = lane + 32 * i;
        float ev = 0.f, w = 0.f;
        if (validf[i]) {
            ev = __expf(scores[i] - mx);
            float tmpl = (float)s - 99.0f;  // linspace(1-100, 0, 100)
            float sft = fminf(fmaxf((tmpl + spanv * 100.0f) * 0.5f + 1.0f, 0.f), 1.f);
            w = ev * sft;
        }
        E += ev; S += w;
        num[i] = w;
    }
#pragma unroll
    for (int o = 16; o; o >>= 1) {
        E += __shfl_xor_sync(0xffffffffu, E, o);
        S += __shfl_xor_sync(0xffffffffu, S, o);
    }
    // attn/(sum(attn*soft)+1e-8)  ==  e*soft / (S + 1e-8*E)
    const float denom = S + 1e-8f * E;
    const float inv = denom > 0.f ? 1.0f / denom : 0.f;

    float* scrow = sc + wid * SCSTR_;
#pragma unroll
    for (int i = 0; i < 4; i++) {
        const int s = lane + 32 * i;
        if (s < SPAN_) scrow[s] = num[i] * inv;
    }
    __syncwarp();

    // Phase 2: lane owns d = lane and d = lane+32 (stride-1, conflict-free)
    float a0 = 0.f, a1 = 0.f;
#pragma unroll 4
    for (int s = 0; s < SPAN_; s++) {
        const float w = scrow[s];
        const float* vrow = vt + (wid + s) * KSTR_;
        a0 += w * vrow[lane];
        a1 += w * vrow[lane + 32];
    }
    float* orow = g_x + (size_t)(b * T_ + t) * FEAT_ + hd;
    orow[lane]      = a0;
    orow[lane + 32] = a1;
}

// ---------------------------------------------------------------------------
// Launch
// ---------------------------------------------------------------------------
extern "C" void kernel_launch(void* const* d_in, const int* in_sizes, int n_in,
                              void* d_out, int out_size)
{
    (void)in_sizes; (void)n_in; (void)out_size;
    const float* query = (const float*)d_in[0];
    const float* key   = (const float*)d_in[1];
    const float* value = (const float*)d_in[2];
    const int*   mask  = (const int*)  d_in[3];
    const float* Wq    = (const float*)d_in[4];
    const float* bq    = (const float*)d_in[5];
    const float* Wk    = (const float*)d_in[6];
    const float* bk    = (const float*)d_in[7];
    const float* Wv    = (const float*)d_in[8];
    const float* bv    = (const float*)d_in[9];
    const float* Wo    = (const float*)d_in[10];
    const float* bo    = (const float*)d_in[11];
    const float* span  = (const float*)d_in[12];
    float* out = (float*)d_out;

    float *gq, *gk, *gv, *gx;
    cudaGetSymbolAddress((void**)&gq, g_q);
    cudaGetSymbolAddress((void**)&gk, g_k);
    cudaGetSymbolAddress((void**)&gv, g_v);
    cudaGetSymbolAddress((void**)&gx, g_x);

    const int smem_attn = (2 * ROWS_ * KSTR_ + TT_ * DK_ + TT_ * SCSTR_) * (int)sizeof(float);
    static int smem_set = 0;
    if (!smem_set) {
        cudaFuncSetAttribute(attn_kernel, cudaFuncAttributeMaxDynamicSharedMemorySize, smem_attn);
        smem_set = 1;
    }

    dim3 gg(64, 8);          // M/64, N/64
    gemm_bias_kernel<<<gg, 256>>>(query, Wq, bq, gq);
    gemm_bias_kernel<<<gg, 256>>>(key,   Wk, bk, gk);
    gemm_bias_kernel<<<gg, 256>>>(value, Wv, bv, gv);

    dim3 ga(T_ / TT_, B_ * H_);
    attn_kernel<<<ga, 512, smem_attn>>>(mask, span);

    gemm_bias_kernel<<<gg, 256>>>(gx, Wo, bo, out);
}

// round 3
// speedup vs baseline: 1.2420x; 1.2420x over previous
#include <cuda_runtime.h>
#include <float.h>
#include <math.h>
#include <string.h>

// Problem constants
#define B_    4
#define T_    1024
#define FEAT_ 512
#define H_    8
#define DK_   64
#define SPAN_ 100
#define PADL_ 50

// Attention tiling
#define TT_   16
#define ROWS_ (TT_ + SPAN_ - 1)     // 115
#define KSTR_ 68
#define SCSTR_ 104

// GEMM tiling
#define BM_ 128
#define BN_ 128
#define BK_ 16

// Scratch (allocation-free rule: __device__ globals)
__device__ float g_q[B_*T_*FEAT_];
__device__ float g_k[B_*T_*FEAT_];
__device__ float g_v[B_*T_*FEAT_];
__device__ float g_x[B_*T_*FEAT_];

// ---------------------------------------------------------------------------
// Packed fp32x2 helpers (SASS FFMA2 — only reachable via PTX f32x2 ops)
// ---------------------------------------------------------------------------
__device__ __forceinline__ void ffma2(unsigned long long& d,
                                      unsigned long long a,
                                      unsigned long long b) {
    asm("fma.rn.f32x2 %0, %1, %2, %0;" : "+l"(d) : "l"(a), "l"(b));
}
__device__ __forceinline__ unsigned long long pack2(float x) {
    unsigned long long r;
    asm("mov.b64 %0, {%1, %1};" : "=l"(r) : "f"(x));
    return r;
}

// ---------------------------------------------------------------------------
// SGEMM core: C[M,N] = A[M,K] @ W[K,N] + bias ; M=4096, N=K=512
// 128x128 tile, BK=16, 256 threads, 8x8 microtile via f32x2 packed FMA.
// ---------------------------------------------------------------------------
__device__ __forceinline__
void gemm_body(const float* __restrict__ A,
               const float* __restrict__ W,
               const float* __restrict__ bias,
               float* __restrict__ C,
               int bm, int bn)
{
    const int N = 512, K = 512;
    __shared__ float As[BK_][BM_];   // transposed A: As[k][m]
    __shared__ float Ws[BK_][BN_];   // Ws[k][n]

    const int tid = threadIdx.x;
    const int ty = tid >> 4;         // 0..15 -> 8 M rows each
    const int tx = tid & 15;         // 0..15 -> 8 N cols each

    // A loads: 2 float4 per thread (row = tid>>1, k-offset 8*(tid&1))
    const int arow = tid >> 1;
    const int akb  = (tid & 1) * 8;
    // W loads: 2 float4 per thread (row = tid>>4, float4-col tid&15 and +16)
    const int wrow = tid >> 4;
    const int wc   = tid & 15;

    const float* Ab = A + (size_t)(bm * BM_) * K;
    const float* Wb = W + bn * BN_;

    unsigned long long acc[8][4];
#pragma unroll
    for (int i = 0; i < 8; i++)
#pragma unroll
        for (int p = 0; p < 4; p++) acc[i][p] = 0ull;

    for (int kt = 0; kt < K; kt += BK_) {
        float4 av0 = *(const float4*)(Ab + (size_t)arow * K + kt + akb);
        float4 av1 = *(const float4*)(Ab + (size_t)arow * K + kt + akb + 4);
        float4 wv0 = *(const float4*)(Wb + (size_t)(kt + wrow) * N + wc * 4);
        float4 wv1 = *(const float4*)(Wb + (size_t)(kt + wrow) * N + wc * 4 + 64);

        __syncthreads();
        As[akb+0][arow] = av0.x;  As[akb+1][arow] = av0.y;
        As[akb+2][arow] = av0.z;  As[akb+3][arow] = av0.w;
        As[akb+4][arow] = av1.x;  As[akb+5][arow] = av1.y;
        As[akb+6][arow] = av1.z;  As[akb+7][arow] = av1.w;
        *(float4*)(&Ws[wrow][wc*4])      = wv0;
        *(float4*)(&Ws[wrow][wc*4 + 64]) = wv1;
        __syncthreads();

#pragma unroll
        for (int kk = 0; kk < BK_; kk++) {
            const float4 a03 = *(const float4*)(&As[kk][ty*8]);
            const float4 a47 = *(const float4*)(&As[kk][ty*8 + 4]);
            const ulonglong2 b01 = *(const ulonglong2*)(&Ws[kk][tx*8]);
            const ulonglong2 b23 = *(const ulonglong2*)(&Ws[kk][tx*8 + 4]);
            float a[8] = {a03.x, a03.y, a03.z, a03.w, a47.x, a47.y, a47.z, a47.w};
#pragma unroll
            for (int i = 0; i < 8; i++) {
                const unsigned long long ap = pack2(a[i]);
                ffma2(acc[i][0], ap, b01.x);
                ffma2(acc[i][1], ap, b01.y);
                ffma2(acc[i][2], ap, b23.x);
                ffma2(acc[i][3], ap, b23.y);
            }
        }
    }

    const float4 bi0 = *(const float4*)(bias + bn*BN_ + tx*8);
    const float4 bi1 = *(const float4*)(bias + bn*BN_ + tx*8 + 4);
#pragma unroll
    for (int i = 0; i < 8; i++) {
        float2 p0, p1, p2, p3;
        memcpy(&p0, &acc[i][0], 8); memcpy(&p1, &acc[i][1], 8);
        memcpy(&p2, &acc[i][2], 8); memcpy(&p3, &acc[i][3], 8);
        float4 o0 = make_float4(p0.x + bi0.x, p0.y + bi0.y, p1.x + bi0.z, p1.y + bi0.w);
        float4 o1 = make_float4(p2.x + bi1.x, p2.y + bi1.y, p3.x + bi1.z, p3.y + bi1.w);
        float* crow = C + (size_t)(bm*BM_ + ty*8 + i) * N + bn*BN_ + tx*8;
        *(float4*)(crow)     = o0;
        *(float4*)(crow + 4) = o1;
    }
}

// Batched Q/K/V projection: blockIdx.z selects which projection.
__global__ __launch_bounds__(256, 1)
void qkv_gemm_kernel(const float* __restrict__ q_in, const float* __restrict__ k_in,
                     const float* __restrict__ v_in,
                     const float* __restrict__ Wq, const float* __restrict__ Wk,
                     const float* __restrict__ Wv,
                     const float* __restrict__ bq, const float* __restrict__ bk,
                     const float* __restrict__ bv,
                     float* __restrict__ oq, float* __restrict__ ok,
                     float* __restrict__ ov)
{
    const float* A; const float* W; const float* bi; float* C;
    if (blockIdx.z == 0)      { A = q_in; W = Wq; bi = bq; C = oq; }
    else if (blockIdx.z == 1) { A = k_in; W = Wk; bi = bk; C = ok; }
    else                      { A = v_in; W = Wv; bi = bv; C = ov; }
    gemm_body(A, W, bi, C, blockIdx.x, blockIdx.y);
}

__global__ __launch_bounds__(256, 1)
void gemm_bias_kernel(const float* __restrict__ A,
                      const float* __restrict__ W,
                      const float* __restrict__ bias,
                      float* __restrict__ C)
{
    gemm_body(A, W, bias, C, blockIdx.x, blockIdx.y);
}

// ---------------------------------------------------------------------------
// Banded adaptive-span attention.
// grid = (T/TT_, B*H), block = 512 (16 warps, one t-position per warp).
// ---------------------------------------------------------------------------
__global__ __launch_bounds__(512)
void attn_kernel(const int* __restrict__ mask,
                 const float* __restrict__ span)
{
    const int tb = blockIdx.x;
    const int bh = blockIdx.y;
    const int b = bh >> 3;
    const int h = bh & 7;
    const int t0 = tb * TT_;
    const int tid = threadIdx.x;
    const int wid = tid >> 5;
    const int lane = tid & 31;

    extern __shared__ float smem[];
    float* kt = smem;                         // [ROWS_][KSTR_]
    float* vt = kt + ROWS_ * KSTR_;           // [ROWS_][KSTR_]
    float* qt = vt + ROWS_ * KSTR_;           // [TT_][DK_]
    float* sc = qt + TT_ * DK_;               // [TT_][SCSTR_]

    const int j0 = t0 - PADL_;
    const size_t hd = (size_t)h * DK_;
    const float* kbase = g_k + (size_t)b * T_ * FEAT_ + hd;
    const float* vbase = g_v + (size_t)b * T_ * FEAT_ + hd;
    const float* qbase = g_q + (size_t)b * T_ * FEAT_ + hd;

    for (int i = tid; i < ROWS_ * 16; i += 512) {
        int r = i >> 4, c4 = i & 15;
        int j = j0 + r;
        float4 k4 = make_float4(0.f, 0.f, 0.f, 0.f);
        float4 v4 = make_float4(0.f, 0.f, 0.f, 0.f);
        if (j >= 0 && j < T_) {
            k4 = *(const float4*)(kbase + (size_t)j * FEAT_ + c4 * 4);
            v4 = *(const float4*)(vbase + (size_t)j * FEAT_ + c4 * 4);
        }
        *(float4*)(kt + r * KSTR_ + c4 * 4) = k4;
        *(float4*)(vt + r * KSTR_ + c4 * 4) = v4;
    }
    for (int i = tid; i < TT_ * 16; i += 512) {
        int r = i >> 4, c4 = i & 15;
        *(float4*)(qt + r * DK_ + c4 * 4) =
            *(const float4*)(qbase + (size_t)(t0 + r) * FEAT_ + c4 * 4);
    }
    __syncthreads();

    const int t = t0 + wid;
    const float spanv = span[h];

    // Phase 1: lane owns s = lane, lane+32, lane+64, lane+96
    float scores[4];
    int   validf[4];
    float mx = -FLT_MAX;
    const float4* qrow = (const float4*)(qt + wid * DK_);
#pragma unroll
    for (int i = 0; i < 4; i++) {
        const int s = lane + 32 * i;
        scores[i] = -FLT_MAX;
        validf[i] = 0;
        if (s < SPAN_) {
            const int j = t + s - PADL_;
            if (j >= 0 && j < T_ && mask[b * T_ + j] != 0) {
                validf[i] = 1;
                const float4* krow = (const float4*)(kt + (wid + s) * KSTR_);
                float acc = 0.f;
#pragma unroll
                for (int c = 0; c < 16; c++) {
                    float4 k4 = krow[c];
                    float4 q4 = qrow[c];
                    acc += q4.x*k4.x + q4.y*k4.y + q4.z*k4.z + q4.w*k4.w;
                }
                scores[i] = acc * 0.125f;
                mx = fmaxf(mx, scores[i]);
            }
        }
    }
#pragma unroll
    for (int o = 16; o; o >>= 1) mx = fmaxf(mx, __shfl_xor_sync(0xffffffffu, mx, o));

    float num[4];
    float E = 0.f, S = 0.f;
#pragma unroll
    for (int i = 0; i < 4; i++) {
        const int s = lane + 32 * i;
        float ev = 0.f, w = 0.f;
        if (validf[i]) {
            ev = __expf(scores[i] - mx);
            float tmpl = (float)s - 99.0f;
            float sft = fminf(fmaxf((tmpl + spanv * 100.0f) * 0.5f + 1.0f, 0.f), 1.f);
            w = ev * sft;
        }
        E += ev; S += w;
        num[i] = w;
    }
#pragma unroll
    for (int o = 16; o; o >>= 1) {
        E += __shfl_xor_sync(0xffffffffu, E, o);
        S += __shfl_xor_sync(0xffffffffu, S, o);
    }
    const float denom = S + 1e-8f * E;
    const float inv = denom > 0.f ? 1.0f / denom : 0.f;

    float* scrow = sc + wid * SCSTR_;
#pragma unroll
    for (int i = 0; i < 4; i++) {
        const int s = lane + 32 * i;
        if (s < SPAN_) scrow[s] = num[i] * inv;
    }
    __syncwarp();

    // Phase 2: lane owns d = 2*lane, 2*lane+1 (conflict-free LDS.64 row reads)
    float a0 = 0.f, a1 = 0.f;
    const int d = 2 * lane;
#pragma unroll 4
    for (int s = 0; s < SPAN_; s++) {
        const float w = scrow[s];
        const float2 v2 = *(const float2*)(vt + (wid + s) * KSTR_ + d);
        a0 += w * v2.x;
        a1 += w * v2.y;
    }
    *(float2*)(g_x + (size_t)(b * T_ + t) * FEAT_ + hd + d) = make_float2(a0, a1);
}

// ---------------------------------------------------------------------------
// Launch
// ---------------------------------------------------------------------------
extern "C" void kernel_launch(void* const* d_in, const int* in_sizes, int n_in,
                              void* d_out, int out_size)
{
    (void)in_sizes; (void)n_in; (void)out_size;
    const float* query = (const float*)d_in[0];
    const float* key   = (const float*)d_in[1];
    const float* value = (const float*)d_in[2];
    const int*   mask  = (const int*)  d_in[3];
    const float* Wq    = (const float*)d_in[4];
    const float* bq    = (const float*)d_in[5];
    const float* Wk    = (const float*)d_in[6];
    const float* bk    = (const float*)d_in[7];
    const float* Wv    = (const float*)d_in[8];
    const float* bv    = (const float*)d_in[9];
    const float* Wo    = (const float*)d_in[10];
    const float* bo    = (const float*)d_in[11];
    const float* span  = (const float*)d_in[12];
    float* out = (float*)d_out;

    float *gq, *gk, *gv, *gx;
    cudaGetSymbolAddress((void**)&gq, g_q);
    cudaGetSymbolAddress((void**)&gk, g_k);
    cudaGetSymbolAddress((void**)&gv, g_v);
    cudaGetSymbolAddress((void**)&gx, g_x);

    const int smem_attn = (2 * ROWS_ * KSTR_ + TT_ * DK_ + TT_ * SCSTR_) * (int)sizeof(float);
    static int smem_set = 0;
    if (!smem_set) {
        cudaFuncSetAttribute(attn_kernel, cudaFuncAttributeMaxDynamicSharedMemorySize, smem_attn);
        smem_set = 1;
    }

    dim3 gqkv(BM_ == 128 ? 32 : 64, 512 / BN_, 3);   // (M/128, N/128, 3)
    qkv_gemm_kernel<<<gqkv, 256>>>(query, key, value, Wq, Wk, Wv, bq, bk, bv, gq, gk, gv);

    dim3 ga(T_ / TT_, B_ * H_);
    attn_kernel<<<ga, 512, smem_attn>>>(mask, span);

    dim3 go(32, 512 / BN_);
    gemm_bias_kernel<<<go, 256>>>(gx, Wo, bo, out);
}

// round 6
// speedup vs baseline: 1.8935x; 1.5245x over previous
#include <cuda_runtime.h>
#include <cuda_bf16.h>
#include <cstdint>
#include <stdint.h>
#include <float.h>
#include <math.h>

// Problem constants
#define B_    4
#define T_    1024
#define FEAT_ 512
#define H_    8
#define DK_   64
#define SPAN_ 100
#define PADL_ 50
#define NTOK_ (B_*T_)            // 4096
#define NEL_  (NTOK_*FEAT_)      // 2M elements

// Attention tiling
#define TT_   16
#define ROWS_ (TT_ + SPAN_ - 1)  // 115
#define KSTR_ 68
#define SCSTR_ 104

// HMMA GEMM tiling
#define BKg  32
#define PADK 40                  // smem row stride in bf16 (80B: conflict-free ldmatrix)

// ---------------------------------------------------------------------------
// Device scratch (__device__ globals; referenced directly from kernels)
// ---------------------------------------------------------------------------
__device__ float g_q[NEL_];
__device__ float g_k[NEL_];
__device__ float g_v[NEL_];
__device__ __nv_bfloat16 g_qh[NEL_];
__device__ __nv_bfloat16 g_ql[NEL_];
__device__ __nv_bfloat16 g_kh[NEL_];
__device__ __nv_bfloat16 g_kl[NEL_];
__device__ __nv_bfloat16 g_vh[NEL_];
__device__ __nv_bfloat16 g_vl[NEL_];
__device__ __nv_bfloat16 g_xh[NEL_];
__device__ __nv_bfloat16 g_xl[NEL_];
__device__ __nv_bfloat16 g_wth[4 * FEAT_ * FEAT_];   // transposed weights hi: [z][n][k]
__device__ __nv_bfloat16 g_wtl[4 * FEAT_ * FEAT_];   // transposed weights lo

// ---------------------------------------------------------------------------
// PTX helpers (arch-agnostic: mma.sync + ldmatrix, sm_80+)
// ---------------------------------------------------------------------------
__device__ __forceinline__ unsigned smem_u32(const void* p) {
    unsigned a;
    asm("{ .reg .u64 t; cvta.to.shared.u64 t, %1; cvt.u32.u64 %0, t; }" : "=r"(a) : "l"(p));
    return a;
}

__device__ __forceinline__ void mma_bf16(float* c, const unsigned* a, const unsigned* b) {
    asm volatile(
        "mma.sync.aligned.m16n8k16.row.col.f32.bf16.bf16.f32 "
        "{%0,%1,%2,%3}, {%4,%5,%6,%7}, {%8,%9}, {%0,%1,%2,%3};"
        : "+f"(c[0]), "+f"(c[1]), "+f"(c[2]), "+f"(c[3])
        : "r"(a[0]), "r"(a[1]), "r"(a[2]), "r"(a[3]), "r"(b[0]), "r"(b[1]));
}

__device__ __forceinline__ void ldsm4(unsigned* r, unsigned addr) {
    asm volatile("ldmatrix.sync.aligned.m8n8.x4.shared.b16 {%0,%1,%2,%3}, [%4];"
        : "=r"(r[0]), "=r"(r[1]), "=r"(r[2]), "=r"(r[3]) : "r"(addr));
}

// ---------------------------------------------------------------------------
// Split fp32 -> bf16 hi/lo (elementwise). blockIdx.y selects q/k/v.
// ---------------------------------------------------------------------------
__global__ __launch_bounds__(256)
void split_inputs_kernel(const float* __restrict__ q, const float* __restrict__ k,
                         const float* __restrict__ v)
{
    const float* src;
    __nv_bfloat16 *dh, *dl;
    if (blockIdx.y == 0)      { src = q; dh = g_qh; dl = g_ql; }
    else if (blockIdx.y == 1) { src = k; dh = g_kh; dl = g_kl; }
    else                      { src = v; dh = g_vh; dl = g_vl; }

    const int n4 = NEL_ / 4;
    for (int i = blockIdx.x * blockDim.x + threadIdx.x; i < n4; i += gridDim.x * blockDim.x) {
        float4 x = ((const float4*)src)[i];
        __nv_bfloat16 h0 = __float2bfloat16_rn(x.x);
        __nv_bfloat16 h1 = __float2bfloat16_rn(x.y);
        __nv_bfloat16 h2 = __float2bfloat16_rn(x.z);
        __nv_bfloat16 h3 = __float2bfloat16_rn(x.w);
        __nv_bfloat162 hA; hA.x = h0; hA.y = h1;
        __nv_bfloat162 hB; hB.x = h2; hB.y = h3;
        __nv_bfloat162 lA, lB;
        lA.x = __float2bfloat16_rn(x.x - __bfloat162float(h0));
        lA.y = __float2bfloat16_rn(x.y - __bfloat162float(h1));
        lB.x = __float2bfloat16_rn(x.z - __bfloat162float(h2));
        lB.y = __float2bfloat16_rn(x.w - __bfloat162float(h3));
        ((__nv_bfloat162*)dh)[i*2]   = hA;
        ((__nv_bfloat162*)dh)[i*2+1] = hB;
        ((__nv_bfloat162*)dl)[i*2]   = lA;
        ((__nv_bfloat162*)dl)[i*2+1] = lB;
    }
}

// ---------------------------------------------------------------------------
// Transpose + split weights: W[k][n] fp32 -> Wt[n][k] bf16 hi/lo. z = weight id.
// ---------------------------------------------------------------------------
__global__ __launch_bounds__(256)
void split_weights_kernel(const float* __restrict__ Wq, const float* __restrict__ Wk,
                          const float* __restrict__ Wv, const float* __restrict__ Wo)
{
    const int z = blockIdx.z;
    const float* W = (z == 0) ? Wq : (z == 1) ? Wk : (z == 2) ? Wv : Wo;
    __nv_bfloat16* Th = g_wth + (size_t)z * FEAT_ * FEAT_;
    __nv_bfloat16* Tl = g_wtl + (size_t)z * FEAT_ * FEAT_;

    __shared__ float tile[32][33];
    const int tx = threadIdx.x, ty = threadIdx.y;   // 32 x 8
    const int kb = blockIdx.y * 32, nb = blockIdx.x * 32;
#pragma unroll
    for (int i = 0; i < 4; i++)
        tile[ty + i*8][tx] = W[(size_t)(kb + ty + i*8) * FEAT_ + nb + tx];
    __syncthreads();
#pragma unroll
    for (int i = 0; i < 4; i++) {
        const int n = nb + ty + i*8;
        const int kk = kb + tx;
        float x = tile[tx][ty + i*8];
        __nv_bfloat16 h = __float2bfloat16_rn(x);
        Th[(size_t)n * FEAT_ + kk] = h;
        Tl[(size_t)n * FEAT_ + kk] = __float2bfloat16_rn(x - __bfloat162float(h));
    }
}

// ---------------------------------------------------------------------------
// bf16-split HMMA GEMM: C[4096,512] = A @ W^T + bias (fp32 out)
// A: [m][k] bf16 hi/lo. W: transposed [n][k] bf16 hi/lo.
// Block tile 128x128, BK=32, 8 warps (2M x 4N), warp tile 64x32.
// ---------------------------------------------------------------------------
__device__ __forceinline__
void hmma_gemm_body(const __nv_bfloat16* __restrict__ Ah, const __nv_bfloat16* __restrict__ Al,
                    const __nv_bfloat16* __restrict__ Wh, const __nv_bfloat16* __restrict__ Wl,
                    const float* __restrict__ bias, float* __restrict__ C,
                    int bm, int bn)
{
    __shared__ __nv_bfloat16 sAh[128 * PADK];
    __shared__ __nv_bfloat16 sAl[128 * PADK];
    __shared__ __nv_bfloat16 sWh[128 * PADK];
    __shared__ __nv_bfloat16 sWl[128 * PADK];

    const int tid = threadIdx.x;
    const int wid = tid >> 5;
    const int lane = tid & 31;
    const int wm = (wid & 1) * 64;     // warp M offset within tile
    const int wn = (wid >> 1) * 32;    // warp N offset within tile

    const unsigned bAh = smem_u32(sAh);
    const unsigned bAl = smem_u32(sAl);
    const unsigned bWh = smem_u32(sWh);
    const unsigned bWl = smem_u32(sWl);

    float acc[4][4][4] = {};

    const int q = lane >> 3;           // ldmatrix quadrant 0..3
    const int l7 = lane & 7;

    for (int kt = 0; kt < FEAT_; kt += BKg) {
        __syncthreads();
#pragma unroll
        for (int p = 0; p < 2; p++) {
            const int idx = tid + p * 256;
            const int row = idx >> 2;
            const int seg = idx & 3;
            const size_t ga = (size_t)(bm * 128 + row) * FEAT_ + kt + seg * 8;
            const size_t gw = (size_t)(bn * 128 + row) * FEAT_ + kt + seg * 8;
            const int so = row * PADK + seg * 8;
            *(uint4*)(sAh + so) = *(const uint4*)(Ah + ga);
            *(uint4*)(sAl + so) = *(const uint4*)(Al + ga);
            *(uint4*)(sWh + so) = *(const uint4*)(Wh + gw);
            *(uint4*)(sWl + so) = *(const uint4*)(Wl + gw);
        }
        __syncthreads();

#pragma unroll
        for (int ks = 0; ks < 2; ks++) {
            const int ko = ks * 16;
            unsigned ah[4][4], al[4][4], bh[4][2], bl[4][2];

            // A fragments: quadrants (m0-7,k0),(m8-15,k0),(m0-7,k8),(m8-15,k8)
#pragma unroll
            for (int mf = 0; mf < 4; mf++) {
                const unsigned arow = (unsigned)(wm + mf * 16 + (q & 1) * 8 + l7);
                const unsigned ab = arow * (PADK * 2) + (unsigned)(ko + (q >> 1) * 8) * 2;
                ldsm4(ah[mf], bAh + ab);
                ldsm4(al[mf], bAl + ab);
            }
            // B fragments: x4 covers two n-frags (16 n-rows x 16 k)
#pragma unroll
            for (int nh = 0; nh < 2; nh++) {
                const unsigned nrow = (unsigned)(wn + nh * 16 + (q >> 1) * 8 + l7);
                const unsigned bb = nrow * (PADK * 2) + (unsigned)(ko + (q & 1) * 8) * 2;
                ldsm4(&bh[nh * 2][0], bWh + bb);
                ldsm4(&bl[nh * 2][0], bWl + bb);
            }

#pragma unroll
            for (int mf = 0; mf < 4; mf++)
#pragma unroll
                for (int nf = 0; nf < 4; nf++) {
                    mma_bf16(acc[mf][nf], ah[mf], bh[nf]);
                    mma_bf16(acc[mf][nf], ah[mf], bl[nf]);
                    mma_bf16(acc[mf][nf], al[mf], bh[nf]);
                }
        }
    }

    // Epilogue: c0,c1 at (row, col..col+1); c2,c3 at (row+8, col..col+1)
#pragma unroll
    for (int mf = 0; mf < 4; mf++) {
        const int r0 = bm * 128 + wm + mf * 16 + (lane >> 2);
#pragma unroll
        for (int nf = 0; nf < 4; nf++) {
            const int col = bn * 128 + wn + nf * 8 + 2 * (lane & 3);
            const float b0 = bias[col], b1 = bias[col + 1];
            *(float2*)(C + (size_t)r0 * FEAT_ + col) =
                make_float2(acc[mf][nf][0] + b0, acc[mf][nf][1] + b1);
            *(float2*)(C + (size_t)(r0 + 8) * FEAT_ + col) =
                make_float2(acc[mf][nf][2] + b0, acc[mf][nf][3] + b1);
        }
    }
}

// Batched Q/K/V projections: blockIdx.z selects which.
__global__ __launch_bounds__(256, 2)
void hmma_gemm_qkv(const float* __restrict__ bq, const float* __restrict__ bk,
                   const float* __restrict__ bv)
{
    const __nv_bfloat16 *Ah, *Al;
    const float* bi;
    float* C;
    int wz;
    if (blockIdx.z == 0)      { Ah = g_qh; Al = g_ql; bi = bq; C = g_q; wz = 0; }
    else if (blockIdx.z == 1) { Ah = g_kh; Al = g_kl; bi = bk; C = g_k; wz = 1; }
    else                      { Ah = g_vh; Al = g_vl; bi = bv; C = g_v; wz = 2; }
    hmma_gemm_body(Ah, Al,
                   g_wth + (size_t)wz * FEAT_ * FEAT_,
                   g_wtl + (size_t)wz * FEAT_ * FEAT_,
                   bi, C, blockIdx.x, blockIdx.y);
}

// Output projection.
__global__ __launch_bounds__(256, 2)
void hmma_gemm_out(const float* __restrict__ bo, float* __restrict__ out)
{
    hmma_gemm_body(g_xh, g_xl,
                   g_wth + (size_t)3 * FEAT_ * FEAT_,
                   g_wtl + (size_t)3 * FEAT_ * FEAT_,
                   bo, out, blockIdx.x, blockIdx.y);
}

// ---------------------------------------------------------------------------
// Banded adaptive-span attention (epilogue emits bf16 hi/lo context).
// ---------------------------------------------------------------------------
__global__ __launch_bounds__(512)
void attn_kernel(const int* __restrict__ mask,
                 const float* __restrict__ span)
{
    const int tb = blockIdx.x;
    const int bh = blockIdx.y;
    const int b = bh >> 3;
    const int h = bh & 7;
    const int t0 = tb * TT_;
    const int tid = threadIdx.x;
    const int wid = tid >> 5;
    const int lane = tid & 31;

    extern __shared__ float smf[];
    float* kt = smf;                          // [ROWS_][KSTR_]
    float* vt = kt + ROWS_ * KSTR_;           // [ROWS_][KSTR_]
    float* qt = vt + ROWS_ * KSTR_;           // [TT_][DK_]
    float* sc = qt + TT_ * DK_;               // [TT_][SCSTR_]

    const int j0 = t0 - PADL_;
    const size_t hd = (size_t)h * DK_;
    const float* kbase = g_k + (size_t)b * T_ * FEAT_ + hd;
    const float* vbase = g_v + (size_t)b * T_ * FEAT_ + hd;
    const float* qbase = g_q + (size_t)b * T_ * FEAT_ + hd;

    for (int i = tid; i < ROWS_ * 16; i += 512) {
        int r = i >> 4, c4 = i & 15;
        int j = j0 + r;
        float4 k4 = make_float4(0.f, 0.f, 0.f, 0.f);
        float4 v4 = make_float4(0.f, 0.f, 0.f, 0.f);
        if (j >= 0 && j < T_) {
            k4 = *(const float4*)(kbase + (size_t)j * FEAT_ + c4 * 4);
            v4 = *(const float4*)(vbase + (size_t)j * FEAT_ + c4 * 4);
        }
        *(float4*)(kt + r * KSTR_ + c4 * 4) = k4;
        *(float4*)(vt + r * KSTR_ + c4 * 4) = v4;
    }
    for (int i = tid; i < TT_ * 16; i += 512) {
        int r = i >> 4, c4 = i & 15;
        *(float4*)(qt + r * DK_ + c4 * 4) =
            *(const float4*)(qbase + (size_t)(t0 + r) * FEAT_ + c4 * 4);
    }
    __syncthreads();

    const int t = t0 + wid;
    const float spanv = span[h];

    float scores[4];
    int   validf[4];
    float mx = -FLT_MAX;
    const float4* qrow = (const float4*)(qt + wid * DK_);
#pragma unroll
    for (int i = 0; i < 4; i++) {
        const int s = lane + 32 * i;
        scores[i] = -FLT_MAX;
        validf[i] = 0;
        if (s < SPAN_) {
            const int j = t + s - PADL_;
            if (j >= 0 && j < T_ && mask[b * T_ + j] != 0) {
                validf[i] = 1;
                const float4* krow = (const float4*)(kt + (wid + s) * KSTR_);
                float acc = 0.f;
#pragma unroll
                for (int c = 0; c < 16; c++) {
                    float4 k4 = krow[c];
                    float4 q4 = qrow[c];
                    acc += q4.x*k4.x + q4.y*k4.y + q4.z*k4.z + q4.w*k4.w;
                }
                scores[i] = acc * 0.125f;
                mx = fmaxf(mx, scores[i]);
            }
        }
    }
#pragma unroll
    for (int o = 16; o; o >>= 1) mx = fmaxf(mx, __shfl_xor_sync(0xffffffffu, mx, o));

    float num[4];
    float E = 0.f, S = 0.f;
#pragma unroll
    for (int i = 0; i < 4; i++) {
        const int s = lane + 32 * i;
        float ev = 0.f, w = 0.f;
        if (validf[i]) {
            ev = __expf(scores[i] - mx);
            float tmpl = (float)s - 99.0f;
            float sft = fminf(fmaxf((tmpl + spanv * 100.0f) * 0.5f + 1.0f, 0.f), 1.f);
            w = ev * sft;
        }
        E += ev; S += w;
        num[i] = w;
    }
#pragma unroll
    for (int o = 16; o; o >>= 1) {
        E += __shfl_xor_sync(0xffffffffu, E, o);
        S += __shfl_xor_sync(0xffffffffu, S, o);
    }
    const float denom = S + 1e-8f * E;
    const float inv = denom > 0.f ? 1.0f / denom : 0.f;

    float* scrow = sc + wid * SCSTR_;
#pragma unroll
    for (int i = 0; i < 4; i++) {
        const int s = lane + 32 * i;
        if (s < SPAN_) scrow[s] = num[i] * inv;
    }
    __syncwarp();

    float a0 = 0.f, a1 = 0.f;
    const int d = 2 * lane;
#pragma unroll 4
    for (int s = 0; s < SPAN_; s++) {
        const float w = scrow[s];
        const float2 v2 = *(const float2*)(vt + (wid + s) * KSTR_ + d);
        a0 += w * v2.x;
        a1 += w * v2.y;
    }

    // Split context directly to bf16 hi/lo for the output GEMM
    const size_t oidx = (size_t)(b * T_ + t) * FEAT_ + hd + d;
    __nv_bfloat16 h0 = __float2bfloat16_rn(a0);
    __nv_bfloat16 h1 = __float2bfloat16_rn(a1);
    __nv_bfloat162 hp; hp.x = h0; hp.y = h1;
    __nv_bfloat162 lp;
    lp.x = __float2bfloat16_rn(a0 - __bfloat162float(h0));
    lp.y = __float2bfloat16_rn(a1 - __bfloat162float(h1));
    *(__nv_bfloat162*)(g_xh + oidx) = hp;
    *(__nv_bfloat162*)(g_xl + oidx) = lp;
}

// ---------------------------------------------------------------------------
// Launch
// ---------------------------------------------------------------------------
extern "C" void kernel_launch(void* const* d_in, const int* in_sizes, int n_in,
                              void* d_out, int out_size)
{
    (void)in_sizes; (void)n_in; (void)out_size;
    const float* query = (const float*)d_in[0];
    const float* key   = (const float*)d_in[1];
    const float* value = (const float*)d_in[2];
    const int*   mask  = (const int*)  d_in[3];
    const float* Wq    = (const float*)d_in[4];
    const float* bq    = (const float*)d_in[5];
    const float* Wk    = (const float*)d_in[6];
    const float* bk    = (const float*)d_in[7];
    const float* Wv    = (const float*)d_in[8];
    const float* bv    = (const float*)d_in[9];
    const float* Wo    = (const float*)d_in[10];
    const float* bo    = (const float*)d_in[11];
    const float* span  = (const float*)d_in[12];
    float* out = (float*)d_out;

    const int smem_attn = (2 * ROWS_ * KSTR_ + TT_ * DK_ + TT_ * SCSTR_) * (int)sizeof(float);
    static int attr_set = 0;
    if (!attr_set) {
        cudaFuncSetAttribute(attn_kernel, cudaFuncAttributeMaxDynamicSharedMemorySize, smem_attn);
        attr_set = 1;
    }

    // 1) split inputs to bf16 hi/lo
    split_inputs_kernel<<<dim3(256, 3), 256>>>(query, key, value);

    // 2) transpose + split weights
    split_weights_kernel<<<dim3(16, 16, 4), dim3(32, 8)>>>(Wq, Wk, Wv, Wo);

    // 3) Q/K/V projections on tensor cores (HMMA)
    hmma_gemm_qkv<<<dim3(NTOK_/128, FEAT_/128, 3), 256>>>(bq, bk, bv);

    // 4) attention (emits bf16 hi/lo context)
    attn_kernel<<<dim3(T_/TT_, B_*H_), 512, smem_attn>>>(mask, span);

    // 5) output projection
    hmma_gemm_out<<<dim3(NTOK_/128, FEAT_/128), 256>>>(bo, out);
}

// round 7
// speedup vs baseline: 2.6357x; 1.3920x over previous
#include <cuda_runtime.h>
#include <cuda_bf16.h>
#include <cstdint>
#include <stdint.h>
#include <float.h>
#include <math.h>

// Problem constants
#define B_    4
#define T_    1024
#define FEAT_ 512
#define H_    8
#define DK_   64
#define SPAN_ 100
#define PADL_ 50
#define NTOK_ (B_*T_)
#define NEL_  (NTOK_*FEAT_)

// HMMA GEMM tiling
#define BKg  32
#define PADK 40

// MMA attention tiling
#define AW_    8          // warps per block
#define ABT_   128        // t per block (16 per warp)
#define AROWS_ 240        // staged K/V window rows
#define ASTR_  72         // smem row stride (bf16) — conflict-free ldmatrix
// smem byte offsets
#define SQH_OFF 0
#define SQL_OFF (SQH_OFF + ABT_*ASTR_*2)
#define SKH_OFF (SQL_OFF + ABT_*ASTR_*2)
#define SKL_OFF (SKH_OFF + AROWS_*ASTR_*2)
#define SVH_OFF (SKL_OFF + AROWS_*ASTR_*2)
#define SVL_OFF (SVH_OFF + AROWS_*ASTR_*2)
#define SMK_OFF (SVL_OFF + AROWS_*ASTR_*2)
#define ATT_SMEM (SMK_OFF + AROWS_*4)

// ---------------------------------------------------------------------------
// Device scratch
// ---------------------------------------------------------------------------
__device__ __nv_bfloat16 g_qh[NEL_];   // GEMM inputs (split)
__device__ __nv_bfloat16 g_ql[NEL_];
__device__ __nv_bfloat16 g_kh[NEL_];
__device__ __nv_bfloat16 g_kl[NEL_];
__device__ __nv_bfloat16 g_vh[NEL_];
__device__ __nv_bfloat16 g_vl[NEL_];
__device__ __nv_bfloat16 g_pqh[NEL_];  // projected q/k/v (split)
__device__ __nv_bfloat16 g_pql[NEL_];
__device__ __nv_bfloat16 g_pkh[NEL_];
__device__ __nv_bfloat16 g_pkl[NEL_];
__device__ __nv_bfloat16 g_pvh[NEL_];
__device__ __nv_bfloat16 g_pvl[NEL_];
__device__ __nv_bfloat16 g_xh[NEL_];   // context (split)
__device__ __nv_bfloat16 g_xl[NEL_];
__device__ __nv_bfloat16 g_wth[4 * FEAT_ * FEAT_];
__device__ __nv_bfloat16 g_wtl[4 * FEAT_ * FEAT_];

// ---------------------------------------------------------------------------
// PTX helpers
// ---------------------------------------------------------------------------
__device__ __forceinline__ unsigned smem_u32(const void* p) {
    unsigned a;
    asm("{ .reg .u64 t; cvta.to.shared.u64 t, %1; cvt.u32.u64 %0, t; }" : "=r"(a) : "l"(p));
    return a;
}
__device__ __forceinline__ void mma_bf16(float* c, const unsigned* a, const unsigned* b) {
    asm volatile(
        "mma.sync.aligned.m16n8k16.row.col.f32.bf16.bf16.f32 "
        "{%0,%1,%2,%3}, {%4,%5,%6,%7}, {%8,%9}, {%0,%1,%2,%3};"
        : "+f"(c[0]), "+f"(c[1]), "+f"(c[2]), "+f"(c[3])
        : "r"(a[0]), "r"(a[1]), "r"(a[2]), "r"(a[3]), "r"(b[0]), "r"(b[1]));
}
__device__ __forceinline__ void ldsm4(unsigned* r, unsigned addr) {
    asm volatile("ldmatrix.sync.aligned.m8n8.x4.shared.b16 {%0,%1,%2,%3}, [%4];"
        : "=r"(r[0]), "=r"(r[1]), "=r"(r[2]), "=r"(r[3]) : "r"(addr));
}
__device__ __forceinline__ void ldsm4t(unsigned* r, unsigned addr) {
    asm volatile("ldmatrix.sync.aligned.m8n8.x4.trans.shared.b16 {%0,%1,%2,%3}, [%4];"
        : "=r"(r[0]), "=r"(r[1]), "=r"(r[2]), "=r"(r[3]) : "r"(addr));
}
__device__ __forceinline__ unsigned pack_split_hi(float a, float b, unsigned& lo_out) {
    __nv_bfloat162 hp, lp;
    hp.x = __float2bfloat16_rn(a);
    hp.y = __float2bfloat16_rn(b);
    lp.x = __float2bfloat16_rn(a - __bfloat162float(hp.x));
    lp.y = __float2bfloat16_rn(b - __bfloat162float(hp.y));
    lo_out = *(unsigned*)&lp;
    return *(unsigned*)&hp;
}

// ---------------------------------------------------------------------------
// Split fp32 -> bf16 hi/lo (GEMM inputs). blockIdx.y selects q/k/v.
// ---------------------------------------------------------------------------
__global__ __launch_bounds__(256)
void split_inputs_kernel(const float* __restrict__ q, const float* __restrict__ k,
                         const float* __restrict__ v)
{
    const float* src;
    __nv_bfloat16 *dh, *dl;
    if (blockIdx.y == 0)      { src = q; dh = g_qh; dl = g_ql; }
    else if (blockIdx.y == 1) { src = k; dh = g_kh; dl = g_kl; }
    else                      { src = v; dh = g_vh; dl = g_vl; }

    const int n4 = NEL_ / 4;
    for (int i = blockIdx.x * blockDim.x + threadIdx.x; i < n4; i += gridDim.x * blockDim.x) {
        float4 x = ((const float4*)src)[i];
        unsigned lA, lB;
        unsigned hA = pack_split_hi(x.x, x.y, lA);
        unsigned hB = pack_split_hi(x.z, x.w, lB);
        ((unsigned*)dh)[i*2]   = hA;
        ((unsigned*)dh)[i*2+1] = hB;
        ((unsigned*)dl)[i*2]   = lA;
        ((unsigned*)dl)[i*2+1] = lB;
    }
}

// ---------------------------------------------------------------------------
// Transpose + split weights: W[k][n] fp32 -> Wt[n][k] bf16 hi/lo.
// ---------------------------------------------------------------------------
__global__ __launch_bounds__(256)
void split_weights_kernel(const float* __restrict__ Wq, const float* __restrict__ Wk,
                          const float* __restrict__ Wv, const float* __restrict__ Wo)
{
    const int z = blockIdx.z;
    const float* W = (z == 0) ? Wq : (z == 1) ? Wk : (z == 2) ? Wv : Wo;
    __nv_bfloat16* Th = g_wth + (size_t)z * FEAT_ * FEAT_;
    __nv_bfloat16* Tl = g_wtl + (size_t)z * FEAT_ * FEAT_;

    __shared__ float tile[32][33];
    const int tx = threadIdx.x, ty = threadIdx.y;
    const int kb = blockIdx.y * 32, nb = blockIdx.x * 32;
#pragma unroll
    for (int i = 0; i < 4; i++)
        tile[ty + i*8][tx] = W[(size_t)(kb + ty + i*8) * FEAT_ + nb + tx];
    __syncthreads();
#pragma unroll
    for (int i = 0; i < 4; i++) {
        const int n = nb + ty + i*8;
        const int kk = kb + tx;
        float x = tile[tx][ty + i*8];
        __nv_bfloat16 h = __float2bfloat16_rn(x);
        Th[(size_t)n * FEAT_ + kk] = h;
        Tl[(size_t)n * FEAT_ + kk] = __float2bfloat16_rn(x - __bfloat162float(h));
    }
}

// ---------------------------------------------------------------------------
// bf16-split HMMA GEMM. SPLIT_OUT: write bf16 hi/lo, else fp32 + bias.
// ---------------------------------------------------------------------------
template<bool SPLIT_OUT>
__device__ __forceinline__
void hmma_gemm_body(const __nv_bfloat16* __restrict__ Ah, const __nv_bfloat16* __restrict__ Al,
                    const __nv_bfloat16* __restrict__ Wh, const __nv_bfloat16* __restrict__ Wl,
                    const float* __restrict__ bias, float* __restrict__ C,
                    __nv_bfloat16* __restrict__ Ch, __nv_bfloat16* __restrict__ Cl,
                    int bm, int bn)
{
    __shared__ __nv_bfloat16 sAh[128 * PADK];
    __shared__ __nv_bfloat16 sAl[128 * PADK];
    __shared__ __nv_bfloat16 sWh[128 * PADK];
    __shared__ __nv_bfloat16 sWl[128 * PADK];

    const int tid = threadIdx.x;
    const int wid = tid >> 5;
    const int lane = tid & 31;
    const int wm = (wid & 1) * 64;
    const int wn = (wid >> 1) * 32;

    const unsigned bAh = smem_u32(sAh);
    const unsigned bAl = smem_u32(sAl);
    const unsigned bWh = smem_u32(sWh);
    const unsigned bWl = smem_u32(sWl);

    float acc[4][4][4] = {};

    const int q = lane >> 3;
    const int l7 = lane & 7;

    for (int kt = 0; kt < FEAT_; kt += BKg) {
        __syncthreads();
#pragma unroll
        for (int p = 0; p < 2; p++) {
            const int idx = tid + p * 256;
            const int row = idx >> 2;
            const int seg = idx & 3;
            const size_t ga = (size_t)(bm * 128 + row) * FEAT_ + kt + seg * 8;
            const size_t gw = (size_t)(bn * 128 + row) * FEAT_ + kt + seg * 8;
            const int so = row * PADK + seg * 8;
            *(uint4*)(sAh + so) = *(const uint4*)(Ah + ga);
            *(uint4*)(sAl + so) = *(const uint4*)(Al + ga);
            *(uint4*)(sWh + so) = *(const uint4*)(Wh + gw);
            *(uint4*)(sWl + so) = *(const uint4*)(Wl + gw);
        }
        __syncthreads();

#pragma unroll
        for (int ks = 0; ks < 2; ks++) {
            const int ko = ks * 16;
            unsigned ah[4][4], al[4][4], bh[4][2], bl[4][2];
#pragma unroll
            for (int mf = 0; mf < 4; mf++) {
                const unsigned arow = (unsigned)(wm + mf * 16 + (q & 1) * 8 + l7);
                const unsigned ab = arow * (PADK * 2) + (unsigned)(ko + (q >> 1) * 8) * 2;
                ldsm4(ah[mf], bAh + ab);
                ldsm4(al[mf], bAl + ab);
            }
#pragma unroll
            for (int nh = 0; nh < 2; nh++) {
                const unsigned nrow = (unsigned)(wn + nh * 16 + (q >> 1) * 8 + l7);
                const unsigned bb = nrow * (PADK * 2) + (unsigned)(ko + (q & 1) * 8) * 2;
                ldsm4(&bh[nh * 2][0], bWh + bb);
                ldsm4(&bl[nh * 2][0], bWl + bb);
            }
#pragma unroll
            for (int mf = 0; mf < 4; mf++)
#pragma unroll
                for (int nf = 0; nf < 4; nf++) {
                    mma_bf16(acc[mf][nf], ah[mf], bh[nf]);
                    mma_bf16(acc[mf][nf], ah[mf], bl[nf]);
                    mma_bf16(acc[mf][nf], al[mf], bh[nf]);
                }
        }
    }

#pragma unroll
    for (int mf = 0; mf < 4; mf++) {
        const int r0 = bm * 128 + wm + mf * 16 + (lane >> 2);
#pragma unroll
        for (int nf = 0; nf < 4; nf++) {
            const int col = bn * 128 + wn + nf * 8 + 2 * (lane & 3);
            const float b0 = bias[col], b1 = bias[col + 1];
            const float v00 = acc[mf][nf][0] + b0, v01 = acc[mf][nf][1] + b1;
            const float v10 = acc[mf][nf][2] + b0, v11 = acc[mf][nf][3] + b1;
            if (SPLIT_OUT) {
                const size_t i0 = (size_t)r0 * FEAT_ + col;
                const size_t i1 = (size_t)(r0 + 8) * FEAT_ + col;
                unsigned lo;
                unsigned hi = pack_split_hi(v00, v01, lo);
                *(unsigned*)(Ch + i0) = hi;  *(unsigned*)(Cl + i0) = lo;
                hi = pack_split_hi(v10, v11, lo);
                *(unsigned*)(Ch + i1) = hi;  *(unsigned*)(Cl + i1) = lo;
            } else {
                *(float2*)(C + (size_t)r0 * FEAT_ + col) = make_float2(v00, v01);
                *(float2*)(C + (size_t)(r0 + 8) * FEAT_ + col) = make_float2(v10, v11);
            }
        }
    }
}

// Q/K/V projections: write projected values as bf16 hi/lo.
__global__ __launch_bounds__(256, 2)
void hmma_gemm_qkv(const float* __restrict__ bq, const float* __restrict__ bk,
                   const float* __restrict__ bv)
{
    const __nv_bfloat16 *Ah, *Al;
    const float* bi;
    __nv_bfloat16 *Ch, *Cl;
    int wz;
    if (blockIdx.z == 0)      { Ah = g_qh; Al = g_ql; bi = bq; Ch = g_pqh; Cl = g_pql; wz = 0; }
    else if (blockIdx.z == 1) { Ah = g_kh; Al = g_kl; bi = bk; Ch = g_pkh; Cl = g_pkl; wz = 1; }
    else                      { Ah = g_vh; Al = g_vl; bi = bv; Ch = g_pvh; Cl = g_pvl; wz = 2; }
    hmma_gemm_body<true>(Ah, Al,
                         g_wth + (size_t)wz * FEAT_ * FEAT_,
                         g_wtl + (size_t)wz * FEAT_ * FEAT_,
                         bi, nullptr, Ch, Cl, blockIdx.x, blockIdx.y);
}

// Output projection: fp32 out.
__global__ __launch_bounds__(256, 2)
void hmma_gemm_out(const float* __restrict__ bo, float* __restrict__ out)
{
    hmma_gemm_body<false>(g_xh, g_xl,
                          g_wth + (size_t)3 * FEAT_ * FEAT_,
                          g_wtl + (size_t)3 * FEAT_ * FEAT_,
                          bo, out, nullptr, nullptr, blockIdx.x, blockIdx.y);
}

// ---------------------------------------------------------------------------
// MMA band attention. Block = 256 thr (8 warps x 16 t). Window 240 rows.
// ---------------------------------------------------------------------------
__global__ __launch_bounds__(256, 1)
void attn_mma_kernel(const int* __restrict__ mask, const float* __restrict__ span)
{
    extern __shared__ char sm[];
    const unsigned uQh = smem_u32(sm + SQH_OFF);
    const unsigned uQl = smem_u32(sm + SQL_OFF);
    const unsigned uKh = smem_u32(sm + SKH_OFF);
    const unsigned uKl = smem_u32(sm + SKL_OFF);
    const unsigned uVh = smem_u32(sm + SVH_OFF);
    const unsigned uVl = smem_u32(sm + SVL_OFF);
    int* smk = (int*)(sm + SMK_OFF);

    const int bx = blockIdx.x, bhz = blockIdx.y;
    const int b = bhz >> 3, h = bhz & 7;
    const int t0 = bx * ABT_;
    const int j0 = t0 - PADL_;
    const int tid = threadIdx.x;
    const int w = tid >> 5, lane = tid & 31;

    __nv_bfloat16* sQh = (__nv_bfloat16*)(sm + SQH_OFF);
    __nv_bfloat16* sQl = (__nv_bfloat16*)(sm + SQL_OFF);
    __nv_bfloat16* sKh = (__nv_bfloat16*)(sm + SKH_OFF);
    __nv_bfloat16* sKl = (__nv_bfloat16*)(sm + SKL_OFF);
    __nv_bfloat16* sVh = (__nv_bfloat16*)(sm + SVH_OFF);
    __nv_bfloat16* sVl = (__nv_bfloat16*)(sm + SVL_OFF);

    // Stage Q (128 rows)
    for (int u = tid; u < ABT_ * 8; u += 256) {
        const int rr = u >> 3, g = u & 7;
        const size_t gi = (size_t)(b * T_ + t0 + rr) * FEAT_ + h * DK_ + g * 8;
        *(uint4*)(sQh + rr * ASTR_ + g * 8) = *(const uint4*)(g_pqh + gi);
        *(uint4*)(sQl + rr * ASTR_ + g * 8) = *(const uint4*)(g_pql + gi);
    }
    // Stage K/V window (240 rows, zero-fill OOB)
    for (int u = tid; u < AROWS_ * 8; u += 256) {
        const int rr = u >> 3, g = u & 7;
        const int j = j0 + rr;
        uint4 kh4 = {0,0,0,0}, kl4 = {0,0,0,0}, vh4 = {0,0,0,0}, vl4 = {0,0,0,0};
        if (j >= 0 && j < T_) {
            const size_t gi = (size_t)(b * T_ + j) * FEAT_ + h * DK_ + g * 8;
            kh4 = *(const uint4*)(g_pkh + gi);
            kl4 = *(const uint4*)(g_pkl + gi);
            vh4 = *(const uint4*)(g_pvh + gi);
            vl4 = *(const uint4*)(g_pvl + gi);
        }
        *(uint4*)(sKh + rr * ASTR_ + g * 8) = kh4;
        *(uint4*)(sKl + rr * ASTR_ + g * 8) = kl4;
        *(uint4*)(sVh + rr * ASTR_ + g * 8) = vh4;
        *(uint4*)(sVl + rr * ASTR_ + g * 8) = vl4;
    }
    for (int rr = tid; rr < AROWS_; rr += 256) {
        const int j = j0 + rr;
        smk[rr] = (j >= 0 && j < T_) ? mask[b * T_ + j] : 0;
    }
    __syncthreads();

    const int q3 = lane >> 3;
    const int l7 = lane & 7;

    // Q fragments (4 k-steps)
    unsigned qfh[4][4], qfl[4][4];
    {
        const unsigned rbase = (unsigned)(w * 16 + (q3 & 1) * 8 + l7);
#pragma unroll
        for (int kk = 0; kk < 4; kk++) {
            const unsigned off = (rbase * ASTR_ + (unsigned)(kk * 16 + (q3 >> 1) * 8)) * 2;
            ldsm4(qfh[kk], uQh + off);
            ldsm4(qfl[kk], uQl + off);
        }
    }

    // Scores: S[16][128] over window rows [w*16, w*16+127]
    float sacc[16][4] = {};
#pragma unroll
    for (int nt = 0; nt < 8; nt++) {
        const unsigned nrow = (unsigned)(w * 16 + nt * 16 + (q3 >> 1) * 8 + l7);
#pragma unroll
        for (int kk = 0; kk < 4; kk++) {
            const unsigned off = (nrow * ASTR_ + (unsigned)(kk * 16 + (q3 & 1) * 8)) * 2;
            unsigned kbh[4], kbl[4];
            ldsm4(kbh, uKh + off);
            ldsm4(kbl, uKl + off);
            mma_bf16(sacc[2*nt],   qfh[kk], &kbh[0]);
            mma_bf16(sacc[2*nt],   qfh[kk], &kbl[0]);
            mma_bf16(sacc[2*nt],   qfl[kk], &kbh[0]);
            mma_bf16(sacc[2*nt+1], qfh[kk], &kbh[2]);
            mma_bf16(sacc[2*nt+1], qfh[kk], &kbl[2]);
            mma_bf16(sacc[2*nt+1], qfl[kk], &kbh[2]);
        }
    }

    // Softmax + adaptive span, rows r and r+8
    const int r = lane >> 2;
    const int c2 = 2 * (lane & 3);
    const float spanv = span[h];
    float mx0 = -1e30f, mx1 = -1e30f;
#pragma unroll
    for (int nt8 = 0; nt8 < 16; nt8++) {
#pragma unroll
        for (int e = 0; e < 2; e++) {
            const int c = 8 * nt8 + c2 + e;
            const int mv = smk[w * 16 + c];
            const int s0 = c - r;
            const int s1 = c - r - 8;
            const bool v0 = (s0 >= 0) && (s0 < SPAN_) && (mv != 0);
            const bool v1 = (s1 >= 0) && (s1 < SPAN_) && (mv != 0);
            const float x0 = v0 ? sacc[nt8][e]     * 0.125f : -1e30f;
            const float x1 = v1 ? sacc[nt8][2 + e] * 0.125f : -1e30f;
            sacc[nt8][e] = x0;
            sacc[nt8][2 + e] = x1;
            mx0 = fmaxf(mx0, x0);
            mx1 = fmaxf(mx1, x1);
        }
    }
    mx0 = fmaxf(mx0, __shfl_xor_sync(0xffffffffu, mx0, 1));
    mx0 = fmaxf(mx0, __shfl_xor_sync(0xffffffffu, mx0, 2));
    mx1 = fmaxf(mx1, __shfl_xor_sync(0xffffffffu, mx1, 1));
    mx1 = fmaxf(mx1, __shfl_xor_sync(0xffffffffu, mx1, 2));

    float E0 = 0.f, S0 = 0.f, E1 = 0.f, S1 = 0.f;
#pragma unroll
    for (int nt8 = 0; nt8 < 16; nt8++) {
#pragma unroll
        for (int e = 0; e < 2; e++) {
            const int c = 8 * nt8 + c2 + e;
            const int s0 = c - r;
            const int s1 = c - r - 8;
            const float sf0 = fminf(fmaxf(((float)s0 - 99.0f + spanv * 100.0f) * 0.5f + 1.0f, 0.f), 1.f);
            const float sf1 = fminf(fmaxf(((float)s1 - 99.0f + spanv * 100.0f) * 0.5f + 1.0f, 0.f), 1.f);
            const float e0 = __expf(sacc[nt8][e] - mx0);
            const float e1 = __expf(sacc[nt8][2 + e] - mx1);
            E0 += e0; S0 += e0 * sf0;
            E1 += e1; S1 += e1 * sf1;
            sacc[nt8][e] = e0 * sf0;
            sacc[nt8][2 + e] = e1 * sf1;
        }
    }
    E0 += __shfl_xor_sync(0xffffffffu, E0, 1);  E0 += __shfl_xor_sync(0xffffffffu, E0, 2);
    S0 += __shfl_xor_sync(0xffffffffu, S0, 1);  S0 += __shfl_xor_sync(0xffffffffu, S0, 2);
    E1 += __shfl_xor_sync(0xffffffffu, E1, 1);  E1 += __shfl_xor_sync(0xffffffffu, E1, 2);
    S1 += __shfl_xor_sync(0xffffffffu, S1, 1);  S1 += __shfl_xor_sync(0xffffffffu, S1, 2);
    const float inv0 = (mx0 > -1e29f) ? 1.0f / (S0 + 1e-8f * E0) : 0.f;
    const float inv1 = (mx1 > -1e29f) ? 1.0f / (S1 + 1e-8f * E1) : 0.f;

    // Repack P -> bf16-split A-fragments (C layout of 2 n8 tiles == A layout)
    unsigned pah[8][4], pal[8][4];
#pragma unroll
    for (int j8 = 0; j8 < 8; j8++) {
        pah[j8][0] = pack_split_hi(sacc[2*j8][0]*inv0,   sacc[2*j8][1]*inv0,   pal[j8][0]);
        pah[j8][1] = pack_split_hi(sacc[2*j8][2]*inv1,   sacc[2*j8][3]*inv1,   pal[j8][1]);
        pah[j8][2] = pack_split_hi(sacc[2*j8+1][0]*inv0, sacc[2*j8+1][1]*inv0, pal[j8][2]);
        pah[j8][3] = pack_split_hi(sacc[2*j8+1][2]*inv1, sacc[2*j8+1][3]*inv1, pal[j8][3]);
    }

    // O = P · V  (V via ldmatrix.trans: B[n][k] = V[k][n])
    float oacc[8][4] = {};
#pragma unroll
    for (int kk2 = 0; kk2 < 8; kk2++) {
        const unsigned krow = (unsigned)(w * 16 + kk2 * 16 + (q3 & 1) * 8 + l7);
#pragma unroll
        for (int nt = 0; nt < 4; nt++) {
            const unsigned off = (krow * ASTR_ + (unsigned)(nt * 16 + (q3 >> 1) * 8)) * 2;
            unsigned vbh[4], vbl[4];
            ldsm4t(vbh, uVh + off);
            ldsm4t(vbl, uVl + off);
            mma_bf16(oacc[2*nt],   pah[kk2], &vbh[0]);
            mma_bf16(oacc[2*nt],   pah[kk2], &vbl[0]);
            mma_bf16(oacc[2*nt],   pal[kk2], &vbh[0]);
            mma_bf16(oacc[2*nt+1], pah[kk2], &vbh[2]);
            mma_bf16(oacc[2*nt+1], pah[kk2], &vbl[2]);
            mma_bf16(oacc[2*nt+1], pal[kk2], &vbh[2]);
        }
    }

    // Write context split bf16
    const int tr = t0 + w * 16 + r;
#pragma unroll
    for (int nf = 0; nf < 8; nf++) {
        const int col = 8 * nf + c2;
        const size_t i0 = (size_t)(b * T_ + tr) * FEAT_ + h * DK_ + col;
        const size_t i1 = (size_t)(b * T_ + tr + 8) * FEAT_ + h * DK_ + col;
        unsigned lo;
        unsigned hi = pack_split_hi(oacc[nf][0], oacc[nf][1], lo);
        *(unsigned*)(g_xh + i0) = hi;  *(unsigned*)(g_xl + i0) = lo;
        hi = pack_split_hi(oacc[nf][2], oacc[nf][3], lo);
        *(unsigned*)(g_xh + i1) = hi;  *(unsigned*)(g_xl + i1) = lo;
    }
}

// ---------------------------------------------------------------------------
// Launch
// ---------------------------------------------------------------------------
extern "C" void kernel_launch(void* const* d_in, const int* in_sizes, int n_in,
                              void* d_out, int out_size)
{
    (void)in_sizes; (void)n_in; (void)out_size;
    const float* query = (const float*)d_in[0];
    const float* key   = (const float*)d_in[1];
    const float* value = (const float*)d_in[2];
    const int*   mask  = (const int*)  d_in[3];
    const float* Wq    = (const float*)d_in[4];
    const float* bq    = (const float*)d_in[5];
    const float* Wk    = (const float*)d_in[6];
    const float* bk    = (const float*)d_in[7];
    const float* Wv    = (const float*)d_in[8];
    const float* bv    = (const float*)d_in[9];
    const float* Wo    = (const float*)d_in[10];
    const float* bo    = (const float*)d_in[11];
    const float* span  = (const float*)d_in[12];
    float* out = (float*)d_out;

    static int attr_set = 0;
    if (!attr_set) {
        cudaFuncSetAttribute(attn_mma_kernel, cudaFuncAttributeMaxDynamicSharedMemorySize, ATT_SMEM);
        attr_set = 1;
    }

    split_inputs_kernel<<<dim3(256, 3), 256>>>(query, key, value);
    split_weights_kernel<<<dim3(16, 16, 4), dim3(32, 8)>>>(Wq, Wk, Wv, Wo);
    hmma_gemm_qkv<<<dim3(NTOK_/128, FEAT_/128, 3), 256>>>(bq, bk, bv);
    attn_mma_kernel<<<dim3(T_/ABT_, B_*H_), 256, ATT_SMEM>>>(mask, span);
    hmma_gemm_out<<<dim3(NTOK_/128, FEAT_/128), 256>>>(bo, out);
}

// round 10
// speedup vs baseline: 2.6712x; 1.0135x over previous
#include <cuda_runtime.h>
#include <cuda_bf16.h>
#include <cstdint>
#include <stdint.h>
#include <float.h>
#include <math.h>

// Problem constants
#define B_    4
#define T_    1024
#define FEAT_ 512
#define H_    8
#define DK_   64
#define SPAN_ 100
#define PADL_ 50
#define NTOK_ (B_*T_)
#define NEL_  (NTOK_*FEAT_)

// HMMA GEMM tiling: 128x64 block tile, BK=32, double-buffered cp.async
#define GBM_  128
#define GBN_  64
#define BKg   32
#define PADK  40                 // smem row stride (bf16) — conflict-free ldmatrix
#define SA_BYTES (GBM_*PADK*2)   // 10240
#define SW_BYTES (GBN_*PADK*2)   // 5120
#define BUF_BYTES (2*SA_BYTES + 2*SW_BYTES)   // 30720
#define GEMM_SMEM (2*BUF_BYTES)               // 61440

// MMA attention tiling
#define ABT_   128
#define AROWS_ 240
#define ASTR_  72
#define SQH_OFF 0
#define SQL_OFF (SQH_OFF + ABT_*ASTR_*2)
#define SKH_OFF (SQL_OFF + ABT_*ASTR_*2)
#define SKL_OFF (SKH_OFF + AROWS_*ASTR_*2)
#define SVH_OFF (SKL_OFF + AROWS_*ASTR_*2)
#define SVL_OFF (SVH_OFF + AROWS_*ASTR_*2)
#define SMK_OFF (SVL_OFF + AROWS_*ASTR_*2)
#define ATT_SMEM (SMK_OFF + AROWS_*4)

// ---------------------------------------------------------------------------
// Device scratch
// ---------------------------------------------------------------------------
__device__ __nv_bfloat16 g_qh[NEL_];
__device__ __nv_bfloat16 g_ql[NEL_];
__device__ __nv_bfloat16 g_kh[NEL_];
__device__ __nv_bfloat16 g_kl[NEL_];
__device__ __nv_bfloat16 g_vh[NEL_];
__device__ __nv_bfloat16 g_vl[NEL_];
__device__ __nv_bfloat16 g_pqh[NEL_];
__device__ __nv_bfloat16 g_pql[NEL_];
__device__ __nv_bfloat16 g_pkh[NEL_];
__device__ __nv_bfloat16 g_pkl[NEL_];
__device__ __nv_bfloat16 g_pvh[NEL_];
__device__ __nv_bfloat16 g_pvl[NEL_];
__device__ __nv_bfloat16 g_xh[NEL_];
__device__ __nv_bfloat16 g_xl[NEL_];
__device__ __nv_bfloat16 g_wth[4 * FEAT_ * FEAT_];
__device__ __nv_bfloat16 g_wtl[4 * FEAT_ * FEAT_];

// ---------------------------------------------------------------------------
// PTX helpers
// ---------------------------------------------------------------------------
__device__ __forceinline__ unsigned smem_u32(const void* p) {
    unsigned a;
    asm("{ .reg .u64 t; cvta.to.shared.u64 t, %1; cvt.u32.u64 %0, t; }" : "=r"(a) : "l"(p));
    return a;
}
__device__ __forceinline__ void mma_bf16(float* c, const unsigned* a, const unsigned* b) {
    asm volatile(
        "mma.sync.aligned.m16n8k16.row.col.f32.bf16.bf16.f32 "
        "{%0,%1,%2,%3}, {%4,%5,%6,%7}, {%8,%9}, {%0,%1,%2,%3};"
        : "+f"(c[0]), "+f"(c[1]), "+f"(c[2]), "+f"(c[3])
        : "r"(a[0]), "r"(a[1]), "r"(a[2]), "r"(a[3]), "r"(b[0]), "r"(b[1]));
}
__device__ __forceinline__ void ldsm4(unsigned* r, unsigned addr) {
    asm volatile("ldmatrix.sync.aligned.m8n8.x4.shared.b16 {%0,%1,%2,%3}, [%4];"
        : "=r"(r[0]), "=r"(r[1]), "=r"(r[2]), "=r"(r[3]) : "r"(addr));
}
__device__ __forceinline__ void ldsm4t(unsigned* r, unsigned addr) {
    asm volatile("ldmatrix.sync.aligned.m8n8.x4.trans.shared.b16 {%0,%1,%2,%3}, [%4];"
        : "=r"(r[0]), "=r"(r[1]), "=r"(r[2]), "=r"(r[3]) : "r"(addr));
}
__device__ __forceinline__ void cp16(unsigned dst, const void* src) {
    asm volatile("cp.async.cg.shared.global [%0], [%1], 16;" :: "r"(dst), "l"(src));
}
__device__ __forceinline__ void cp_commit() {
    asm volatile("cp.async.commit_group;" ::: "memory");
}
__device__ __forceinline__ void cp_wait1() {
    asm volatile("cp.async.wait_group 1;" ::: "memory");
}
__device__ __forceinline__ void cp_wait0() {
    asm volatile("cp.async.wait_group 0;" ::: "memory");
}
__device__ __forceinline__ unsigned pack_split_hi(float a, float b, unsigned& lo_out) {
    __nv_bfloat162 hp, lp;
    hp.x = __float2bfloat16_rn(a);
    hp.y = __float2bfloat16_rn(b);
    lp.x = __float2bfloat16_rn(a - __bfloat162float(hp.x));
    lp.y = __float2bfloat16_rn(b - __bfloat162float(hp.y));
    lo_out = *(unsigned*)&lp;
    return *(unsigned*)&hp;
}

// ---------------------------------------------------------------------------
// Split fp32 -> bf16 hi/lo (GEMM inputs). blockIdx.y selects q/k/v.
// ---------------------------------------------------------------------------
__global__ __launch_bounds__(256)
void split_inputs_kernel(const float* __restrict__ q, const float* __restrict__ k,
                         const float* __restrict__ v)
{
    const float* src;
    __nv_bfloat16 *dh, *dl;
    if (blockIdx.y == 0)      { src = q; dh = g_qh; dl = g_ql; }
    else if (blockIdx.y == 1) { src = k; dh = g_kh; dl = g_kl; }
    else                      { src = v; dh = g_vh; dl = g_vl; }

    const int n4 = NEL_ / 4;
    for (int i = blockIdx.x * blockDim.x + threadIdx.x; i < n4; i += gridDim.x * blockDim.x) {
        float4 x = ((const float4*)src)[i];
        unsigned lA, lB;
        unsigned hA = pack_split_hi(x.x, x.y, lA);
        unsigned hB = pack_split_hi(x.z, x.w, lB);
        ((unsigned*)dh)[i*2]   = hA;
        ((unsigned*)dh)[i*2+1] = hB;
        ((unsigned*)dl)[i*2]   = lA;
        ((unsigned*)dl)[i*2+1] = lB;
    }
}

// ---------------------------------------------------------------------------
// Transpose + split weights: W[k][n] fp32 -> Wt[n][k] bf16 hi/lo.
// ---------------------------------------------------------------------------
__global__ __launch_bounds__(256)
void split_weights_kernel(const float* __restrict__ Wq, const float* __restrict__ Wk,
                          const float* __restrict__ Wv, const float* __restrict__ Wo)
{
    const int z = blockIdx.z;
    const float* W = (z == 0) ? Wq : (z == 1) ? Wk : (z == 2) ? Wv : Wo;
    __nv_bfloat16* Th = g_wth + (size_t)z * FEAT_ * FEAT_;
    __nv_bfloat16* Tl = g_wtl + (size_t)z * FEAT_ * FEAT_;

    __shared__ float tile[32][33];
    const int tx = threadIdx.x, ty = threadIdx.y;
    const int kb = blockIdx.y * 32, nb = blockIdx.x * 32;
#pragma unroll
    for (int i = 0; i < 4; i++)
        tile[ty + i*8][tx] = W[(size_t)(kb + ty + i*8) * FEAT_ + nb + tx];
    __syncthreads();
#pragma unroll
    for (int i = 0; i < 4; i++) {
        const int n = nb + ty + i*8;
        const int kk = kb + tx;
        float x = tile[tx][ty + i*8];
        __nv_bfloat16 h = __float2bfloat16_rn(x);
        Th[(size_t)n * FEAT_ + kk] = h;
        Tl[(size_t)n * FEAT_ + kk] = __float2bfloat16_rn(x - __bfloat162float(h));
    }
}

// ---------------------------------------------------------------------------
// bf16-split HMMA GEMM, 128x64 tile, cp.async double-buffered.
// 8 warps as 4M x 2N (warp tile 32x32).
// ---------------------------------------------------------------------------
template<bool SPLIT_OUT>
__device__ __forceinline__
void hmma_gemm_body(const __nv_bfloat16* __restrict__ Ah, const __nv_bfloat16* __restrict__ Al,
                    const __nv_bfloat16* __restrict__ Wh, const __nv_bfloat16* __restrict__ Wl,
                    const float* __restrict__ bias, float* __restrict__ C,
                    __nv_bfloat16* __restrict__ Ch, __nv_bfloat16* __restrict__ Cl,
                    int bm, int bn)
{
    extern __shared__ char smg[];
    const unsigned sb = smem_u32(smg);

    const int tid = threadIdx.x;
    const int wid = tid >> 5;
    const int lane = tid & 31;
    const int wm = (wid & 3) * 32;
    const int wn = (wid >> 2) * 32;

    const int q3 = lane >> 3;
    const int l7 = lane & 7;

    const int ar0 = tid >> 2, as0 = tid & 3;
    const int ar1 = (tid + 256) >> 2;
    const int wr0 = tid >> 2, ws0 = tid & 3;

    float acc[2][4][4] = {};

    // ---- stage chunk 0 ----
    {
        const unsigned base = sb;
        cp16(base + (unsigned)(ar0 * PADK + as0 * 8) * 2,
             Ah + (size_t)(bm * GBM_ + ar0) * FEAT_ + as0 * 8);
        cp16(base + (unsigned)(ar1 * PADK + as0 * 8) * 2,
             Ah + (size_t)(bm * GBM_ + ar1) * FEAT_ + as0 * 8);
        cp16(base + SA_BYTES + (unsigned)(ar0 * PADK + as0 * 8) * 2,
             Al + (size_t)(bm * GBM_ + ar0) * FEAT_ + as0 * 8);
        cp16(base + SA_BYTES + (unsigned)(ar1 * PADK + as0 * 8) * 2,
             Al + (size_t)(bm * GBM_ + ar1) * FEAT_ + as0 * 8);
        cp16(base + 2 * SA_BYTES + (unsigned)(wr0 * PADK + ws0 * 8) * 2,
             Wh + (size_t)(bn * GBN_ + wr0) * FEAT_ + ws0 * 8);
        cp16(base + 2 * SA_BYTES + SW_BYTES + (unsigned)(wr0 * PADK + ws0 * 8) * 2,
             Wl + (size_t)(bn * GBN_ + wr0) * FEAT_ + ws0 * 8);
        cp_commit();
    }

    const int NIT = FEAT_ / BKg;   // 16
    for (int it = 0; it < NIT; it++) {
        if (it + 1 < NIT) {
            const int kt = (it + 1) * BKg;
            const unsigned base = sb + (unsigned)(((it + 1) & 1) * BUF_BYTES);
            cp16(base + (unsigned)(ar0 * PADK + as0 * 8) * 2,
                 Ah + (size_t)(bm * GBM_ + ar0) * FEAT_ + kt + as0 * 8);
            cp16(base + (unsigned)(ar1 * PADK + as0 * 8) * 2,
                 Ah + (size_t)(bm * GBM_ + ar1) * FEAT_ + kt + as0 * 8);
            cp16(base + SA_BYTES + (unsigned)(ar0 * PADK + as0 * 8) * 2,
                 Al + (size_t)(bm * GBM_ + ar0) * FEAT_ + kt + as0 * 8);
            cp16(base + SA_BYTES + (unsigned)(ar1 * PADK + as0 * 8) * 2,
                 Al + (size_t)(bm * GBM_ + ar1) * FEAT_ + kt + as0 * 8);
            cp16(base + 2 * SA_BYTES + (unsigned)(wr0 * PADK + ws0 * 8) * 2,
                 Wh + (size_t)(bn * GBN_ + wr0) * FEAT_ + kt + ws0 * 8);
            cp16(base + 2 * SA_BYTES + SW_BYTES + (unsigned)(wr0 * PADK + ws0 * 8) * 2,
                 Wl + (size_t)(bn * GBN_ + wr0) * FEAT_ + kt + ws0 * 8);
            cp_commit();
            cp_wait1();
        } else {
            cp_wait0();
        }
        __syncthreads();

        const unsigned uA = sb + (unsigned)((it & 1) * BUF_BYTES);
        const unsigned uAh = uA;
        const unsigned uAl = uA + SA_BYTES;
        const unsigned uWh = uA + 2 * SA_BYTES;
        const unsigned uWl = uA + 2 * SA_BYTES + SW_BYTES;

#pragma unroll
        for (int ks = 0; ks < 2; ks++) {
            const int ko = ks * 16;
            unsigned ah[2][4], al[2][4];
            unsigned bh[8], bl[8];     // 2 x ldmatrix.x4 -> 8 regs each (R8 bug: was 4)
#pragma unroll
            for (int mf = 0; mf < 2; mf++) {
                const unsigned arow = (unsigned)(wm + mf * 16 + (q3 & 1) * 8 + l7);
                const unsigned ab = (arow * PADK + (unsigned)(ko + (q3 >> 1) * 8)) * 2;
                ldsm4(ah[mf], uAh + ab);
                ldsm4(al[mf], uAl + ab);
            }
            {
                const unsigned nrow = (unsigned)(wn + (q3 >> 1) * 8 + l7);
                const unsigned bb = (nrow * PADK + (unsigned)(ko + (q3 & 1) * 8)) * 2;
                ldsm4(bh, uWh + bb);            // frags nf=0 (regs 0,1), nf=1 (regs 2,3)
                ldsm4(bl, uWl + bb);
                const unsigned bb2 = ((nrow + 16) * PADK + (unsigned)(ko + (q3 & 1) * 8)) * 2;
                ldsm4(bh + 4, uWh + bb2);       // frags nf=2 (regs 4,5), nf=3 (regs 6,7)
                ldsm4(bl + 4, uWl + bb2);
            }
#pragma unroll
            for (int mf = 0; mf < 2; mf++)
#pragma unroll
                for (int nf = 0; nf < 4; nf++) {
                    mma_bf16(acc[mf][nf], ah[mf], bh + 2 * nf);
                    mma_bf16(acc[mf][nf], ah[mf], bl + 2 * nf);
                    mma_bf16(acc[mf][nf], al[mf], bh + 2 * nf);
                }
        }
        __syncthreads();
    }

    // Epilogue
#pragma unroll
    for (int mf = 0; mf < 2; mf++) {
        const int r0 = bm * GBM_ + wm + mf * 16 + (lane >> 2);
#pragma unroll
        for (int nf = 0; nf < 4; nf++) {
            const int col = bn * GBN_ + wn + nf * 8 + 2 * (lane & 3);
            const float b0 = bias[col], b1 = bias[col + 1];
            const float v00 = acc[mf][nf][0] + b0, v01 = acc[mf][nf][1] + b1;
            const float v10 = acc[mf][nf][2] + b0, v11 = acc[mf][nf][3] + b1;
            if (SPLIT_OUT) {
                const size_t i0 = (size_t)r0 * FEAT_ + col;
                const size_t i1 = (size_t)(r0 + 8) * FEAT_ + col;
                unsigned lo;
                unsigned hi = pack_split_hi(v00, v01, lo);
                *(unsigned*)(Ch + i0) = hi;  *(unsigned*)(Cl + i0) = lo;
                hi = pack_split_hi(v10, v11, lo);
                *(unsigned*)(Ch + i1) = hi;  *(unsigned*)(Cl + i1) = lo;
            } else {
                *(float2*)(C + (size_t)r0 * FEAT_ + col) = make_float2(v00, v01);
                *(float2*)(C + (size_t)(r0 + 8) * FEAT_ + col) = make_float2(v10, v11);
            }
        }
    }
}

// Q/K/V projections.
__global__ __launch_bounds__(256, 2)
void hmma_gemm_qkv(const float* __restrict__ bq, const float* __restrict__ bk,
                   const float* __restrict__ bv)
{
    const __nv_bfloat16 *Ah, *Al;
    const float* bi;
    __nv_bfloat16 *Ch, *Cl;
    int wz;
    if (blockIdx.z == 0)      { Ah = g_qh; Al = g_ql; bi = bq; Ch = g_pqh; Cl = g_pql; wz = 0; }
    else if (blockIdx.z == 1) { Ah = g_kh; Al = g_kl; bi = bk; Ch = g_pkh; Cl = g_pkl; wz = 1; }
    else                      { Ah = g_vh; Al = g_vl; bi = bv; Ch = g_pvh; Cl = g_pvl; wz = 2; }
    hmma_gemm_body<true>(Ah, Al,
                         g_wth + (size_t)wz * FEAT_ * FEAT_,
                         g_wtl + (size_t)wz * FEAT_ * FEAT_,
                         bi, nullptr, Ch, Cl, blockIdx.x, blockIdx.y);
}

// Output projection.
__global__ __launch_bounds__(256, 2)
void hmma_gemm_out(const float* __restrict__ bo, float* __restrict__ out)
{
    hmma_gemm_body<false>(g_xh, g_xl,
                          g_wth + (size_t)3 * FEAT_ * FEAT_,
                          g_wtl + (size_t)3 * FEAT_ * FEAT_,
                          bo, out, nullptr, nullptr, blockIdx.x, blockIdx.y);
}

// ---------------------------------------------------------------------------
// MMA band attention (unchanged, proven in R7).
// ---------------------------------------------------------------------------
__global__ __launch_bounds__(256, 1)
void attn_mma_kernel(const int* __restrict__ mask, const float* __restrict__ span)
{
    extern __shared__ char sm[];
    const unsigned uQh = smem_u32(sm + SQH_OFF);
    const unsigned uQl = smem_u32(sm + SQL_OFF);
    const unsigned uKh = smem_u32(sm + SKH_OFF);
    const unsigned uKl = smem_u32(sm + SKL_OFF);
    const unsigned uVh = smem_u32(sm + SVH_OFF);
    const unsigned uVl = smem_u32(sm + SVL_OFF);
    int* smk = (int*)(sm + SMK_OFF);

    const int bx = blockIdx.x, bhz = blockIdx.y;
    const int b = bhz >> 3, h = bhz & 7;
    const int t0 = bx * ABT_;
    const int j0 = t0 - PADL_;
    const int tid = threadIdx.x;
    const int w = tid >> 5, lane = tid & 31;

    __nv_bfloat16* sQh = (__nv_bfloat16*)(sm + SQH_OFF);
    __nv_bfloat16* sQl = (__nv_bfloat16*)(sm + SQL_OFF);
    __nv_bfloat16* sKh = (__nv_bfloat16*)(sm + SKH_OFF);
    __nv_bfloat16* sKl = (__nv_bfloat16*)(sm + SKL_OFF);
    __nv_bfloat16* sVh = (__nv_bfloat16*)(sm + SVH_OFF);
    __nv_bfloat16* sVl = (__nv_bfloat16*)(sm + SVL_OFF);

    for (int u = tid; u < ABT_ * 8; u += 256) {
        const int rr = u >> 3, g = u & 7;
        const size_t gi = (size_t)(b * T_ + t0 + rr) * FEAT_ + h * DK_ + g * 8;
        *(uint4*)(sQh + rr * ASTR_ + g * 8) = *(const uint4*)(g_pqh + gi);
        *(uint4*)(sQl + rr * ASTR_ + g * 8) = *(const uint4*)(g_pql + gi);
    }
    for (int u = tid; u < AROWS_ * 8; u += 256) {
        const int rr = u >> 3, g = u & 7;
        const int j = j0 + rr;
        uint4 kh4 = {0,0,0,0}, kl4 = {0,0,0,0}, vh4 = {0,0,0,0}, vl4 = {0,0,0,0};
        if (j >= 0 && j < T_) {
            const size_t gi = (size_t)(b * T_ + j) * FEAT_ + h * DK_ + g * 8;
            kh4 = *(const uint4*)(g_pkh + gi);
            kl4 = *(const uint4*)(g_pkl + gi);
            vh4 = *(const uint4*)(g_pvh + gi);
            vl4 = *(const uint4*)(g_pvl + gi);
        }
        *(uint4*)(sKh + rr * ASTR_ + g * 8) = kh4;
        *(uint4*)(sKl + rr * ASTR_ + g * 8) = kl4;
        *(uint4*)(sVh + rr * ASTR_ + g * 8) = vh4;
        *(uint4*)(sVl + rr * ASTR_ + g * 8) = vl4;
    }
    for (int rr = tid; rr < AROWS_; rr += 256) {
        const int j = j0 + rr;
        smk[rr] = (j >= 0 && j < T_) ? mask[b * T_ + j] : 0;
    }
    __syncthreads();

    const int q3 = lane >> 3;
    const int l7 = lane & 7;

    unsigned qfh[4][4], qfl[4][4];
    {
        const unsigned rbase = (unsigned)(w * 16 + (q3 & 1) * 8 + l7);
#pragma unroll
        for (int kk = 0; kk < 4; kk++) {
            const unsigned off = (rbase * ASTR_ + (unsigned)(kk * 16 + (q3 >> 1) * 8)) * 2;
            ldsm4(qfh[kk], uQh + off);
            ldsm4(qfl[kk], uQl + off);
        }
    }

    float sacc[16][4] = {};
#pragma unroll
    for (int nt = 0; nt < 8; nt++) {
        const unsigned nrow = (unsigned)(w * 16 + nt * 16 + (q3 >> 1) * 8 + l7);
#pragma unroll
        for (int kk = 0; kk < 4; kk++) {
            const unsigned off = (nrow * ASTR_ + (unsigned)(kk * 16 + (q3 & 1) * 8)) * 2;
            unsigned kbh[4], kbl[4];
            ldsm4(kbh, uKh + off);
            ldsm4(kbl, uKl + off);
            mma_bf16(sacc[2*nt],   qfh[kk], &kbh[0]);
            mma_bf16(sacc[2*nt],   qfh[kk], &kbl[0]);
            mma_bf16(sacc[2*nt],   qfl[kk], &kbh[0]);
            mma_bf16(sacc[2*nt+1], qfh[kk], &kbh[2]);
            mma_bf16(sacc[2*nt+1], qfh[kk], &kbl[2]);
            mma_bf16(sacc[2*nt+1], qfl[kk], &kbh[2]);
        }
    }

    const int r = lane >> 2;
    const int c2 = 2 * (lane & 3);
    const float spanv = span[h];
    float mx0 = -1e30f, mx1 = -1e30f;
#pragma unroll
    for (int nt8 = 0; nt8 < 16; nt8++) {
#pragma unroll
        for (int e = 0; e < 2; e++) {
            const int c = 8 * nt8 + c2 + e;
            const int mv = smk[w * 16 + c];
            const int s0 = c - r;
            const int s1 = c - r - 8;
            const bool v0 = (s0 >= 0) && (s0 < SPAN_) && (mv != 0);
            const bool v1 = (s1 >= 0) && (s1 < SPAN_) && (mv != 0);
            const float x0 = v0 ? sacc[nt8][e]     * 0.125f : -1e30f;
            const float x1 = v1 ? sacc[nt8][2 + e] * 0.125f : -1e30f;
            sacc[nt8][e] = x0;
            sacc[nt8][2 + e] = x1;
            mx0 = fmaxf(mx0, x0);
            mx1 = fmaxf(mx1, x1);
        }
    }
    mx0 = fmaxf(mx0, __shfl_xor_sync(0xffffffffu, mx0, 1));
    mx0 = fmaxf(mx0, __shfl_xor_sync(0xffffffffu, mx0, 2));
    mx1 = fmaxf(mx1, __shfl_xor_sync(0xffffffffu, mx1, 1));
    mx1 = fmaxf(mx1, __shfl_xor_sync(0xffffffffu, mx1, 2));

    float E0 = 0.f, S0 = 0.f, E1 = 0.f, S1 = 0.f;
#pragma unroll
    for (int nt8 = 0; nt8 < 16; nt8++) {
#pragma unroll
        for (int e = 0; e < 2; e++) {
            const int c = 8 * nt8 + c2 + e;
            const int s0 = c - r;
            const int s1 = c - r - 8;
            const float sf0 = fminf(fmaxf(((float)s0 - 99.0f + spanv * 100.0f) * 0.5f + 1.0f, 0.f), 1.f);
            const float sf1 = fminf(fmaxf(((float)s1 - 99.0f + spanv * 100.0f) * 0.5f + 1.0f, 0.f), 1.f);
            const float e0 = __expf(sacc[nt8][e] - mx0);
            const float e1 = __expf(sacc[nt8][2 + e] - mx1);
            E0 += e0; S0 += e0 * sf0;
            E1 += e1; S1 += e1 * sf1;
            sacc[nt8][e] = e0 * sf0;
            sacc[nt8][2 + e] = e1 * sf1;
        }
    }
    E0 += __shfl_xor_sync(0xffffffffu, E0, 1);  E0 += __shfl_xor_sync(0xffffffffu, E0, 2);
    S0 += __shfl_xor_sync(0xffffffffu, S0, 1);  S0 += __shfl_xor_sync(0xffffffffu, S0, 2);
    E1 += __shfl_xor_sync(0xffffffffu, E1, 1);  E1 += __shfl_xor_sync(0xffffffffu, E1, 2);
    S1 += __shfl_xor_sync(0xffffffffu, S1, 1);  S1 += __shfl_xor_sync(0xffffffffu, S1, 2);
    const float inv0 = (mx0 > -1e29f) ? 1.0f / (S0 + 1e-8f * E0) : 0.f;
    const float inv1 = (mx1 > -1e29f) ? 1.0f / (S1 + 1e-8f * E1) : 0.f;

    unsigned pah[8][4], pal[8][4];
#pragma unroll
    for (int j8 = 0; j8 < 8; j8++) {
        pah[j8][0] = pack_split_hi(sacc[2*j8][0]*inv0,   sacc[2*j8][1]*inv0,   pal[j8][0]);
        pah[j8][1] = pack_split_hi(sacc[2*j8][2]*inv1,   sacc[2*j8][3]*inv1,   pal[j8][1]);
        pah[j8][2] = pack_split_hi(sacc[2*j8+1][0]*inv0, sacc[2*j8+1][1]*inv0, pal[j8][2]);
        pah[j8][3] = pack_split_hi(sacc[2*j8+1][2]*inv1, sacc[2*j8+1][3]*inv1, pal[j8][3]);
    }

    float oacc[8][4] = {};
#pragma unroll
    for (int kk2 = 0; kk2 < 8; kk2++) {
        const unsigned krow = (unsigned)(w * 16 + kk2 * 16 + (q3 & 1) * 8 + l7);
#pragma unroll
        for (int nt = 0; nt < 4; nt++) {
            const unsigned off = (krow * ASTR_ + (unsigned)(nt * 16 + (q3 >> 1) * 8)) * 2;
            unsigned vbh[4], vbl[4];
            ldsm4t(vbh, uVh + off);
            ldsm4t(vbl, uVl + off);
            mma_bf16(oacc[2*nt],   pah[kk2], &vbh[0]);
            mma_bf16(oacc[2*nt],   pah[kk2], &vbl[0]);
            mma_bf16(oacc[2*nt],   pal[kk2], &vbh[0]);
            mma_bf16(oacc[2*nt+1], pah[kk2], &vbh[2]);
            mma_bf16(oacc[2*nt+1], pah[kk2], &vbl[2]);
            mma_bf16(oacc[2*nt+1], pal[kk2], &vbh[2]);
        }
    }

    const int tr = t0 + w * 16 + r;
#pragma unroll
    for (int nf = 0; nf < 8; nf++) {
        const int col = 8 * nf + c2;
        const size_t i0 = (size_t)(b * T_ + tr) * FEAT_ + h * DK_ + col;
        const size_t i1 = (size_t)(b * T_ + tr + 8) * FEAT_ + h * DK_ + col;
        unsigned lo;
        unsigned hi = pack_split_hi(oacc[nf][0], oacc[nf][1], lo);
        *(unsigned*)(g_xh + i0) = hi;  *(unsigned*)(g_xl + i0) = lo;
        hi = pack_split_hi(oacc[nf][2], oacc[nf][3], lo);
        *(unsigned*)(g_xh + i1) = hi;  *(unsigned*)(g_xl + i1) = lo;
    }
}

// ---------------------------------------------------------------------------
// Launch
// ---------------------------------------------------------------------------
extern "C" void kernel_launch(void* const* d_in, const int* in_sizes, int n_in,
                              void* d_out, int out_size)
{
    (void)in_sizes; (void)n_in; (void)out_size;
    const float* query = (const float*)d_in[0];
    const float* key   = (const float*)d_in[1];
    const float* value = (const float*)d_in[2];
    const int*   mask  = (const int*)  d_in[3];
    const float* Wq    = (const float*)d_in[4];
    const float* bq    = (const float*)d_in[5];
    const float* Wk    = (const float*)d_in[6];
    const float* bk    = (const float*)d_in[7];
    const float* Wv    = (const float*)d_in[8];
    const float* bv    = (const float*)d_in[9];
    const float* Wo    = (const float*)d_in[10];
    const float* bo    = (const float*)d_in[11];
    const float* span  = (const float*)d_in[12];
    float* out = (float*)d_out;

    static int attr_set = 0;
    if (!attr_set) {
        cudaFuncSetAttribute(attn_mma_kernel, cudaFuncAttributeMaxDynamicSharedMemorySize, ATT_SMEM);
        cudaFuncSetAttribute(hmma_gemm_qkv, cudaFuncAttributeMaxDynamicSharedMemorySize, GEMM_SMEM);
        cudaFuncSetAttribute(hmma_gemm_out, cudaFuncAttributeMaxDynamicSharedMemorySize, GEMM_SMEM);
        attr_set = 1;
    }

    split_inputs_kernel<<<dim3(256, 3), 256>>>(query, key, value);
    split_weights_kernel<<<dim3(16, 16, 4), dim3(32, 8)>>>(Wq, Wk, Wv, Wo);
    hmma_gemm_qkv<<<dim3(NTOK_/GBM_, FEAT_/GBN_, 3), 256, GEMM_SMEM>>>(bq, bk, bv);
    attn_mma_kernel<<<dim3(T_/ABT_, B_*H_), 256, ATT_SMEM>>>(mask, span);
    hmma_gemm_out<<<dim3(NTOK_/GBM_, FEAT_/GBN_), 256, GEMM_SMEM>>>(bo, out);
}

// round 11
// speedup vs baseline: 2.7471x; 1.0284x over previous
#include <cuda_runtime.h>
#include <cuda_bf16.h>
#include <cstdint>
#include <stdint.h>
#include <float.h>
#include <math.h>

// Problem constants
#define B_    4
#define T_    1024
#define FEAT_ 512
#define H_    8
#define DK_   64
#define SPAN_ 100
#define PADL_ 50
#define NTOK_ (B_*T_)
#define NEL_  (NTOK_*FEAT_)

// HMMA GEMM tiling: 128x64 block tile, BK=32, double-buffered cp.async
#define GBM_  128
#define GBN_  64
#define BKg   32
#define PADK  40
#define SA_BYTES (GBM_*PADK*2)
#define SW_BYTES (GBN_*PADK*2)
#define BUF_BYTES (2*SA_BYTES + 2*SW_BYTES)
#define GEMM_SMEM (2*BUF_BYTES)

// MMA attention tiling — V aliases K's smem (staged after scores)
#define ABT_   128
#define AROWS_ 240
#define ASTR_  72
#define SQH_OFF  0
#define SQL_OFF  (SQH_OFF + ABT_*ASTR_*2)        // 18432
#define SKVH_OFF (SQL_OFF + ABT_*ASTR_*2)        // 36864  (K hi, later V hi)
#define SKVL_OFF (SKVH_OFF + AROWS_*ASTR_*2)     // 71424  (K lo, later V lo)
#define SMK_OFF  (SKVL_OFF + AROWS_*ASTR_*2)     // 105984
#define ATT_SMEM (SMK_OFF + AROWS_*4)            // 106944 -> 2 CTAs/SM

// ---------------------------------------------------------------------------
// Device scratch
// ---------------------------------------------------------------------------
__device__ __nv_bfloat16 g_qh[NEL_];
__device__ __nv_bfloat16 g_ql[NEL_];
__device__ __nv_bfloat16 g_kh[NEL_];
__device__ __nv_bfloat16 g_kl[NEL_];
__device__ __nv_bfloat16 g_vh[NEL_];
__device__ __nv_bfloat16 g_vl[NEL_];
__device__ __nv_bfloat16 g_pqh[NEL_];
__device__ __nv_bfloat16 g_pql[NEL_];
__device__ __nv_bfloat16 g_pkh[NEL_];
__device__ __nv_bfloat16 g_pkl[NEL_];
__device__ __nv_bfloat16 g_pvh[NEL_];
__device__ __nv_bfloat16 g_pvl[NEL_];
__device__ __nv_bfloat16 g_xh[NEL_];
__device__ __nv_bfloat16 g_xl[NEL_];
__device__ __nv_bfloat16 g_wth[4 * FEAT_ * FEAT_];
__device__ __nv_bfloat16 g_wtl[4 * FEAT_ * FEAT_];

// ---------------------------------------------------------------------------
// PTX helpers
// ---------------------------------------------------------------------------
__device__ __forceinline__ unsigned smem_u32(const void* p) {
    unsigned a;
    asm("{ .reg .u64 t; cvta.to.shared.u64 t, %1; cvt.u32.u64 %0, t; }" : "=r"(a) : "l"(p));
    return a;
}
__device__ __forceinline__ void mma_bf16(float* c, const unsigned* a, const unsigned* b) {
    asm volatile(
        "mma.sync.aligned.m16n8k16.row.col.f32.bf16.bf16.f32 "
        "{%0,%1,%2,%3}, {%4,%5,%6,%7}, {%8,%9}, {%0,%1,%2,%3};"
        : "+f"(c[0]), "+f"(c[1]), "+f"(c[2]), "+f"(c[3])
        : "r"(a[0]), "r"(a[1]), "r"(a[2]), "r"(a[3]), "r"(b[0]), "r"(b[1]));
}
__device__ __forceinline__ void ldsm4(unsigned* r, unsigned addr) {
    asm volatile("ldmatrix.sync.aligned.m8n8.x4.shared.b16 {%0,%1,%2,%3}, [%4];"
        : "=r"(r[0]), "=r"(r[1]), "=r"(r[2]), "=r"(r[3]) : "r"(addr));
}
__device__ __forceinline__ void ldsm4t(unsigned* r, unsigned addr) {
    asm volatile("ldmatrix.sync.aligned.m8n8.x4.trans.shared.b16 {%0,%1,%2,%3}, [%4];"
        : "=r"(r[0]), "=r"(r[1]), "=r"(r[2]), "=r"(r[3]) : "r"(addr));
}
__device__ __forceinline__ void cp16(unsigned dst, const void* src) {
    asm volatile("cp.async.cg.shared.global [%0], [%1], 16;" :: "r"(dst), "l"(src));
}
__device__ __forceinline__ void cp_commit() {
    asm volatile("cp.async.commit_group;" ::: "memory");
}
__device__ __forceinline__ void cp_wait1() {
    asm volatile("cp.async.wait_group 1;" ::: "memory");
}
__device__ __forceinline__ void cp_wait0() {
    asm volatile("cp.async.wait_group 0;" ::: "memory");
}
__device__ __forceinline__ unsigned pack_split_hi(float a, float b, unsigned& lo_out) {
    __nv_bfloat162 hp, lp;
    hp.x = __float2bfloat16_rn(a);
    hp.y = __float2bfloat16_rn(b);
    lp.x = __float2bfloat16_rn(a - __bfloat162float(hp.x));
    lp.y = __float2bfloat16_rn(b - __bfloat162float(hp.y));
    lo_out = *(unsigned*)&lp;
    return *(unsigned*)&hp;
}

// ---------------------------------------------------------------------------
// Split fp32 -> bf16 hi/lo (GEMM inputs). blockIdx.y selects q/k/v.
// ---------------------------------------------------------------------------
__global__ __launch_bounds__(256)
void split_inputs_kernel(const float* __restrict__ q, const float* __restrict__ k,
                         const float* __restrict__ v)
{
    const float* src;
    __nv_bfloat16 *dh, *dl;
    if (blockIdx.y == 0)      { src = q; dh = g_qh; dl = g_ql; }
    else if (blockIdx.y == 1) { src = k; dh = g_kh; dl = g_kl; }
    else                      { src = v; dh = g_vh; dl = g_vl; }

    const int n4 = NEL_ / 4;
    for (int i = blockIdx.x * blockDim.x + threadIdx.x; i < n4; i += gridDim.x * blockDim.x) {
        float4 x = ((const float4*)src)[i];
        unsigned lA, lB;
        unsigned hA = pack_split_hi(x.x, x.y, lA);
        unsigned hB = pack_split_hi(x.z, x.w, lB);
        ((unsigned*)dh)[i*2]   = hA;
        ((unsigned*)dh)[i*2+1] = hB;
        ((unsigned*)dl)[i*2]   = lA;
        ((unsigned*)dl)[i*2+1] = lB;
    }
}

// ---------------------------------------------------------------------------
// Transpose + split weights: W[k][n] fp32 -> Wt[n][k] bf16 hi/lo.
// ---------------------------------------------------------------------------
__global__ __launch_bounds__(256)
void split_weights_kernel(const float* __restrict__ Wq, const float* __restrict__ Wk,
                          const float* __restrict__ Wv, const float* __restrict__ Wo)
{
    const int z = blockIdx.z;
    const float* W = (z == 0) ? Wq : (z == 1) ? Wk : (z == 2) ? Wv : Wo;
    __nv_bfloat16* Th = g_wth + (size_t)z * FEAT_ * FEAT_;
    __nv_bfloat16* Tl = g_wtl + (size_t)z * FEAT_ * FEAT_;

    __shared__ float tile[32][33];
    const int tx = threadIdx.x, ty = threadIdx.y;
    const int kb = blockIdx.y * 32, nb = blockIdx.x * 32;
#pragma unroll
    for (int i = 0; i < 4; i++)
        tile[ty + i*8][tx] = W[(size_t)(kb + ty + i*8) * FEAT_ + nb + tx];
    __syncthreads();
#pragma unroll
    for (int i = 0; i < 4; i++) {
        const int n = nb + ty + i*8;
        const int kk = kb + tx;
        float x = tile[tx][ty + i*8];
        __nv_bfloat16 h = __float2bfloat16_rn(x);
        Th[(size_t)n * FEAT_ + kk] = h;
        Tl[(size_t)n * FEAT_ + kk] = __float2bfloat16_rn(x - __bfloat162float(h));
    }
}

// ---------------------------------------------------------------------------
// bf16-split HMMA GEMM, 128x64 tile, cp.async double-buffered (proven R10).
// ---------------------------------------------------------------------------
template<bool SPLIT_OUT>
__device__ __forceinline__
void hmma_gemm_body(const __nv_bfloat16* __restrict__ Ah, const __nv_bfloat16* __restrict__ Al,
                    const __nv_bfloat16* __restrict__ Wh, const __nv_bfloat16* __restrict__ Wl,
                    const float* __restrict__ bias, float* __restrict__ C,
                    __nv_bfloat16* __restrict__ Ch, __nv_bfloat16* __restrict__ Cl,
                    int bm, int bn)
{
    extern __shared__ char smg[];
    const unsigned sb = smem_u32(smg);

    const int tid = threadIdx.x;
    const int wid = tid >> 5;
    const int lane = tid & 31;
    const int wm = (wid & 3) * 32;
    const int wn = (wid >> 2) * 32;

    const int q3 = lane >> 3;
    const int l7 = lane & 7;

    const int ar0 = tid >> 2, as0 = tid & 3;
    const int ar1 = (tid + 256) >> 2;
    const int wr0 = tid >> 2, ws0 = tid & 3;

    float acc[2][4][4] = {};

    {
        const unsigned base = sb;
        cp16(base + (unsigned)(ar0 * PADK + as0 * 8) * 2,
             Ah + (size_t)(bm * GBM_ + ar0) * FEAT_ + as0 * 8);
        cp16(base + (unsigned)(ar1 * PADK + as0 * 8) * 2,
             Ah + (size_t)(bm * GBM_ + ar1) * FEAT_ + as0 * 8);
        cp16(base + SA_BYTES + (unsigned)(ar0 * PADK + as0 * 8) * 2,
             Al + (size_t)(bm * GBM_ + ar0) * FEAT_ + as0 * 8);
        cp16(base + SA_BYTES + (unsigned)(ar1 * PADK + as0 * 8) * 2,
             Al + (size_t)(bm * GBM_ + ar1) * FEAT_ + as0 * 8);
        cp16(base + 2 * SA_BYTES + (unsigned)(wr0 * PADK + ws0 * 8) * 2,
             Wh + (size_t)(bn * GBN_ + wr0) * FEAT_ + ws0 * 8);
        cp16(base + 2 * SA_BYTES + SW_BYTES + (unsigned)(wr0 * PADK + ws0 * 8) * 2,
             Wl + (size_t)(bn * GBN_ + wr0) * FEAT_ + ws0 * 8);
        cp_commit();
    }

    const int NIT = FEAT_ / BKg;
    for (int it = 0; it < NIT; it++) {
        if (it + 1 < NIT) {
            const int kt = (it + 1) * BKg;
            const unsigned base = sb + (unsigned)(((it + 1) & 1) * BUF_BYTES);
            cp16(base + (unsigned)(ar0 * PADK + as0 * 8) * 2,
                 Ah + (size_t)(bm * GBM_ + ar0) * FEAT_ + kt + as0 * 8);
            cp16(base + (unsigned)(ar1 * PADK + as0 * 8) * 2,
                 Ah + (size_t)(bm * GBM_ + ar1) * FEAT_ + kt + as0 * 8);
            cp16(base + SA_BYTES + (unsigned)(ar0 * PADK + as0 * 8) * 2,
                 Al + (size_t)(bm * GBM_ + ar0) * FEAT_ + kt + as0 * 8);
            cp16(base + SA_BYTES + (unsigned)(ar1 * PADK + as0 * 8) * 2,
                 Al + (size_t)(bm * GBM_ + ar1) * FEAT_ + kt + as0 * 8);
            cp16(base + 2 * SA_BYTES + (unsigned)(wr0 * PADK + ws0 * 8) * 2,
                 Wh + (size_t)(bn * GBN_ + wr0) * FEAT_ + kt + ws0 * 8);
            cp16(base + 2 * SA_BYTES + SW_BYTES + (unsigned)(wr0 * PADK + ws0 * 8) * 2,
                 Wl + (size_t)(bn * GBN_ + wr0) * FEAT_ + kt + ws0 * 8);
            cp_commit();
            cp_wait1();
        } else {
            cp_wait0();
        }
        __syncthreads();

        const unsigned uA = sb + (unsigned)((it & 1) * BUF_BYTES);
        const unsigned uAh = uA;
        const unsigned uAl = uA + SA_BYTES;
        const unsigned uWh = uA + 2 * SA_BYTES;
        const unsigned uWl = uA + 2 * SA_BYTES + SW_BYTES;

#pragma unroll
        for (int ks = 0; ks < 2; ks++) {
            const int ko = ks * 16;
            unsigned ah[2][4], al[2][4];
            unsigned bh[8], bl[8];
#pragma unroll
            for (int mf = 0; mf < 2; mf++) {
                const unsigned arow = (unsigned)(wm + mf * 16 + (q3 & 1) * 8 + l7);
                const unsigned ab = (arow * PADK + (unsigned)(ko + (q3 >> 1) * 8)) * 2;
                ldsm4(ah[mf], uAh + ab);
                ldsm4(al[mf], uAl + ab);
            }
            {
                const unsigned nrow = (unsigned)(wn + (q3 >> 1) * 8 + l7);
                const unsigned bb = (nrow * PADK + (unsigned)(ko + (q3 & 1) * 8)) * 2;
                ldsm4(bh, uWh + bb);
                ldsm4(bl, uWl + bb);
                const unsigned bb2 = ((nrow + 16) * PADK + (unsigned)(ko + (q3 & 1) * 8)) * 2;
                ldsm4(bh + 4, uWh + bb2);
                ldsm4(bl + 4, uWl + bb2);
            }
#pragma unroll
            for (int mf = 0; mf < 2; mf++)
#pragma unroll
                for (int nf = 0; nf < 4; nf++) {
                    mma_bf16(acc[mf][nf], ah[mf], bh + 2 * nf);
                    mma_bf16(acc[mf][nf], ah[mf], bl + 2 * nf);
                    mma_bf16(acc[mf][nf], al[mf], bh + 2 * nf);
                }
        }
        __syncthreads();
    }

#pragma unroll
    for (int mf = 0; mf < 2; mf++) {
        const int r0 = bm * GBM_ + wm + mf * 16 + (lane >> 2);
#pragma unroll
        for (int nf = 0; nf < 4; nf++) {
            const int col = bn * GBN_ + wn + nf * 8 + 2 * (lane & 3);
            const float b0 = bias[col], b1 = bias[col + 1];
            const float v00 = acc[mf][nf][0] + b0, v01 = acc[mf][nf][1] + b1;
            const float v10 = acc[mf][nf][2] + b0, v11 = acc[mf][nf][3] + b1;
            if (SPLIT_OUT) {
                const size_t i0 = (size_t)r0 * FEAT_ + col;
                const size_t i1 = (size_t)(r0 + 8) * FEAT_ + col;
                unsigned lo;
                unsigned hi = pack_split_hi(v00, v01, lo);
                *(unsigned*)(Ch + i0) = hi;  *(unsigned*)(Cl + i0) = lo;
                hi = pack_split_hi(v10, v11, lo);
                *(unsigned*)(Ch + i1) = hi;  *(unsigned*)(Cl + i1) = lo;
            } else {
                *(float2*)(C + (size_t)r0 * FEAT_ + col) = make_float2(v00, v01);
                *(float2*)(C + (size_t)(r0 + 8) * FEAT_ + col) = make_float2(v10, v11);
            }
        }
    }
}

__global__ __launch_bounds__(256, 2)
void hmma_gemm_qkv(const float* __restrict__ bq, const float* __restrict__ bk,
                   const float* __restrict__ bv)
{
    const __nv_bfloat16 *Ah, *Al;
    const float* bi;
    __nv_bfloat16 *Ch, *Cl;
    int wz;
    if (blockIdx.z == 0)      { Ah = g_qh; Al = g_ql; bi = bq; Ch = g_pqh; Cl = g_pql; wz = 0; }
    else if (blockIdx.z == 1) { Ah = g_kh; Al = g_kl; bi = bk; Ch = g_pkh; Cl = g_pkl; wz = 1; }
    else                      { Ah = g_vh; Al = g_vl; bi = bv; Ch = g_pvh; Cl = g_pvl; wz = 2; }
    hmma_gemm_body<true>(Ah, Al,
                         g_wth + (size_t)wz * FEAT_ * FEAT_,
                         g_wtl + (size_t)wz * FEAT_ * FEAT_,
                         bi, nullptr, Ch, Cl, blockIdx.x, blockIdx.y);
}

__global__ __launch_bounds__(256, 2)
void hmma_gemm_out(const float* __restrict__ bo, float* __restrict__ out)
{
    hmma_gemm_body<false>(g_xh, g_xl,
                          g_wth + (size_t)3 * FEAT_ * FEAT_,
                          g_wtl + (size_t)3 * FEAT_ * FEAT_,
                          bo, out, nullptr, nullptr, blockIdx.x, blockIdx.y);
}

// ---------------------------------------------------------------------------
// MMA band attention. V aliases K's smem (staged between score and PV phases).
// Smem 107KB + 128-reg cap -> 2 CTAs/SM.
// ---------------------------------------------------------------------------
__global__ __launch_bounds__(256, 2)
void attn_mma_kernel(const int* __restrict__ mask, const float* __restrict__ span)
{
    extern __shared__ char sm[];
    const unsigned uQh  = smem_u32(sm + SQH_OFF);
    const unsigned uQl  = smem_u32(sm + SQL_OFF);
    const unsigned uKVh = smem_u32(sm + SKVH_OFF);
    const unsigned uKVl = smem_u32(sm + SKVL_OFF);
    int* smk = (int*)(sm + SMK_OFF);

    const int bx = blockIdx.x, bhz = blockIdx.y;
    const int b = bhz >> 3, h = bhz & 7;
    const int t0 = bx * ABT_;
    const int j0 = t0 - PADL_;
    const int tid = threadIdx.x;
    const int w = tid >> 5, lane = tid & 31;

    __nv_bfloat16* sQh  = (__nv_bfloat16*)(sm + SQH_OFF);
    __nv_bfloat16* sQl  = (__nv_bfloat16*)(sm + SQL_OFF);
    __nv_bfloat16* sKVh = (__nv_bfloat16*)(sm + SKVH_OFF);
    __nv_bfloat16* sKVl = (__nv_bfloat16*)(sm + SKVL_OFF);

    // Stage Q + K (+mask)
    for (int u = tid; u < ABT_ * 8; u += 256) {
        const int rr = u >> 3, g = u & 7;
        const size_t gi = (size_t)(b * T_ + t0 + rr) * FEAT_ + h * DK_ + g * 8;
        *(uint4*)(sQh + rr * ASTR_ + g * 8) = *(const uint4*)(g_pqh + gi);
        *(uint4*)(sQl + rr * ASTR_ + g * 8) = *(const uint4*)(g_pql + gi);
    }
    for (int u = tid; u < AROWS_ * 8; u += 256) {
        const int rr = u >> 3, g = u & 7;
        const int j = j0 + rr;
        uint4 kh4 = {0,0,0,0}, kl4 = {0,0,0,0};
        if (j >= 0 && j < T_) {
            const size_t gi = (size_t)(b * T_ + j) * FEAT_ + h * DK_ + g * 8;
            kh4 = *(const uint4*)(g_pkh + gi);
            kl4 = *(const uint4*)(g_pkl + gi);
        }
        *(uint4*)(sKVh + rr * ASTR_ + g * 8) = kh4;
        *(uint4*)(sKVl + rr * ASTR_ + g * 8) = kl4;
    }
    for (int rr = tid; rr < AROWS_; rr += 256) {
        const int j = j0 + rr;
        smk[rr] = (j >= 0 && j < T_) ? mask[b * T_ + j] : 0;
    }
    __syncthreads();

    const int q3 = lane >> 3;
    const int l7 = lane & 7;

    // Q fragments
    unsigned qfh[4][4], qfl[4][4];
    {
        const unsigned rbase = (unsigned)(w * 16 + (q3 & 1) * 8 + l7);
#pragma unroll
        for (int kk = 0; kk < 4; kk++) {
            const unsigned off = (rbase * ASTR_ + (unsigned)(kk * 16 + (q3 >> 1) * 8)) * 2;
            ldsm4(qfh[kk], uQh + off);
            ldsm4(qfl[kk], uQl + off);
        }
    }

    // Scores
    float sacc[16][4] = {};
#pragma unroll
    for (int nt = 0; nt < 8; nt++) {
        const unsigned nrow = (unsigned)(w * 16 + nt * 16 + (q3 >> 1) * 8 + l7);
#pragma unroll
        for (int kk = 0; kk < 4; kk++) {
            const unsigned off = (nrow * ASTR_ + (unsigned)(kk * 16 + (q3 & 1) * 8)) * 2;
            unsigned kbh[4], kbl[4];
            ldsm4(kbh, uKVh + off);
            ldsm4(kbl, uKVl + off);
            mma_bf16(sacc[2*nt],   qfh[kk], &kbh[0]);
            mma_bf16(sacc[2*nt],   qfh[kk], &kbl[0]);
            mma_bf16(sacc[2*nt],   qfl[kk], &kbh[0]);
            mma_bf16(sacc[2*nt+1], qfh[kk], &kbh[2]);
            mma_bf16(sacc[2*nt+1], qfh[kk], &kbl[2]);
            mma_bf16(sacc[2*nt+1], qfl[kk], &kbh[2]);
        }
    }

    // All warps done reading K — overwrite with V, softmax overlaps the stores
    __syncthreads();
    for (int u = tid; u < AROWS_ * 8; u += 256) {
        const int rr = u >> 3, g = u & 7;
        const int j = j0 + rr;
        uint4 vh4 = {0,0,0,0}, vl4 = {0,0,0,0};
        if (j >= 0 && j < T_) {
            const size_t gi = (size_t)(b * T_ + j) * FEAT_ + h * DK_ + g * 8;
            vh4 = *(const uint4*)(g_pvh + gi);
            vl4 = *(const uint4*)(g_pvl + gi);
        }
        *(uint4*)(sKVh + rr * ASTR_ + g * 8) = vh4;
        *(uint4*)(sKVl + rr * ASTR_ + g * 8) = vl4;
    }

    // Softmax + adaptive span (register-local; overlaps V staging)
    const int r = lane >> 2;
    const int c2 = 2 * (lane & 3);
    const float spanv = span[h];
    float mx0 = -1e30f, mx1 = -1e30f;
#pragma unroll
    for (int nt8 = 0; nt8 < 16; nt8++) {
#pragma unroll
        for (int e = 0; e < 2; e++) {
            const int c = 8 * nt8 + c2 + e;
            const int mv = smk[w * 16 + c];
            const int s0 = c - r;
            const int s1 = c - r - 8;
            const bool v0 = (s0 >= 0) && (s0 < SPAN_) && (mv != 0);
            const bool v1 = (s1 >= 0) && (s1 < SPAN_) && (mv != 0);
            const float x0 = v0 ? sacc[nt8][e]     * 0.125f : -1e30f;
            const float x1 = v1 ? sacc[nt8][2 + e] * 0.125f : -1e30f;
            sacc[nt8][e] = x0;
            sacc[nt8][2 + e] = x1;
            mx0 = fmaxf(mx0, x0);
            mx1 = fmaxf(mx1, x1);
        }
    }
    mx0 = fmaxf(mx0, __shfl_xor_sync(0xffffffffu, mx0, 1));
    mx0 = fmaxf(mx0, __shfl_xor_sync(0xffffffffu, mx0, 2));
    mx1 = fmaxf(mx1, __shfl_xor_sync(0xffffffffu, mx1, 1));
    mx1 = fmaxf(mx1, __shfl_xor_sync(0xffffffffu, mx1, 2));

    float E0 = 0.f, S0 = 0.f, E1 = 0.f, S1 = 0.f;
#pragma unroll
    for (int nt8 = 0; nt8 < 16; nt8++) {
#pragma unroll
        for (int e = 0; e < 2; e++) {
            const int c = 8 * nt8 + c2 + e;
            const int s0 = c - r;
            const int s1 = c - r - 8;
            const float sf0 = fminf(fmaxf(((float)s0 - 99.0f + spanv * 100.0f) * 0.5f + 1.0f, 0.f), 1.f);
            const float sf1 = fminf(fmaxf(((float)s1 - 99.0f + spanv * 100.0f) * 0.5f + 1.0f, 0.f), 1.f);
            const float e0 = __expf(sacc[nt8][e] - mx0);
            const float e1 = __expf(sacc[nt8][2 + e] - mx1);
            E0 += e0; S0 += e0 * sf0;
            E1 += e1; S1 += e1 * sf1;
            sacc[nt8][e] = e0 * sf0;
            sacc[nt8][2 + e] = e1 * sf1;
        }
    }
    E0 += __shfl_xor_sync(0xffffffffu, E0, 1);  E0 += __shfl_xor_sync(0xffffffffu, E0, 2);
    S0 += __shfl_xor_sync(0xffffffffu, S0, 1);  S0 += __shfl_xor_sync(0xffffffffu, S0, 2);
    E1 += __shfl_xor_sync(0xffffffffu, E1, 1);  E1 += __shfl_xor_sync(0xffffffffu, E1, 2);
    S1 += __shfl_xor_sync(0xffffffffu, S1, 1);  S1 += __shfl_xor_sync(0xffffffffu, S1, 2);
    const float inv0 = (mx0 > -1e29f) ? 1.0f / (S0 + 1e-8f * E0) : 0.f;
    const float inv1 = (mx1 > -1e29f) ? 1.0f / (S1 + 1e-8f * E1) : 0.f;

    // Repack P -> bf16-split A-fragments
    unsigned pah[8][4], pal[8][4];
#pragma unroll
    for (int j8 = 0; j8 < 8; j8++) {
        pah[j8][0] = pack_split_hi(sacc[2*j8][0]*inv0,   sacc[2*j8][1]*inv0,   pal[j8][0]);
        pah[j8][1] = pack_split_hi(sacc[2*j8][2]*inv1,   sacc[2*j8][3]*inv1,   pal[j8][1]);
        pah[j8][2] = pack_split_hi(sacc[2*j8+1][0]*inv0, sacc[2*j8+1][1]*inv0, pal[j8][2]);
        pah[j8][3] = pack_split_hi(sacc[2*j8+1][2]*inv1, sacc[2*j8+1][3]*inv1, pal[j8][3]);
    }

    // V staging complete before PV reads
    __syncthreads();

    // O = P · V
    float oacc[8][4] = {};
#pragma unroll
    for (int kk2 = 0; kk2 < 8; kk2++) {
        const unsigned krow = (unsigned)(w * 16 + kk2 * 16 + (q3 & 1) * 8 + l7);
#pragma unroll
        for (int nt = 0; nt < 4; nt++) {
            const unsigned off = (krow * ASTR_ + (unsigned)(nt * 16 + (q3 >> 1) * 8)) * 2;
            unsigned vbh[4], vbl[4];
            ldsm4t(vbh, uKVh + off);
            ldsm4t(vbl, uKVl + off);
            mma_bf16(oacc[2*nt],   pah[kk2], &vbh[0]);
            mma_bf16(oacc[2*nt],   pah[kk2], &vbl[0]);
            mma_bf16(oacc[2*nt],   pal[kk2], &vbh[0]);
            mma_bf16(oacc[2*nt+1], pah[kk2], &vbh[2]);
            mma_bf16(oacc[2*nt+1], pah[kk2], &vbl[2]);
            mma_bf16(oacc[2*nt+1], pal[kk2], &vbh[2]);
        }
    }

    const int tr = t0 + w * 16 + r;
#pragma unroll
    for (int nf = 0; nf < 8; nf++) {
        const int col = 8 * nf + c2;
        const size_t i0 = (size_t)(b * T_ + tr) * FEAT_ + h * DK_ + col;
        const size_t i1 = (size_t)(b * T_ + tr + 8) * FEAT_ + h * DK_ + col;
        unsigned lo;
        unsigned hi = pack_split_hi(oacc[nf][0], oacc[nf][1], lo);
        *(unsigned*)(g_xh + i0) = hi;  *(unsigned*)(g_xl + i0) = lo;
        hi = pack_split_hi(oacc[nf][2], oacc[nf][3], lo);
        *(unsigned*)(g_xh + i1) = hi;  *(unsigned*)(g_xl + i1) = lo;
    }
}

// ---------------------------------------------------------------------------
// Launch
// ---------------------------------------------------------------------------
extern "C" void kernel_launch(void* const* d_in, const int* in_sizes, int n_in,
                              void* d_out, int out_size)
{
    (void)in_sizes; (void)n_in; (void)out_size;
    const float* query = (const float*)d_in[0];
    const float* key   = (const float*)d_in[1];
    const float* value = (const float*)d_in[2];
    const int*   mask  = (const int*)  d_in[3];
    const float* Wq    = (const float*)d_in[4];
    const float* bq    = (const float*)d_in[5];
    const float* Wk    = (const float*)d_in[6];
    const float* bk    = (const float*)d_in[7];
    const float* Wv    = (const float*)d_in[8];
    const float* bv    = (const float*)d_in[9];
    const float* Wo    = (const float*)d_in[10];
    const float* bo    = (const float*)d_in[11];
    const float* span  = (const float*)d_in[12];
    float* out = (float*)d_out;

    static int attr_set = 0;
    if (!attr_set) {
        cudaFuncSetAttribute(attn_mma_kernel, cudaFuncAttributeMaxDynamicSharedMemorySize, ATT_SMEM);
        cudaFuncSetAttribute(hmma_gemm_qkv, cudaFuncAttributeMaxDynamicSharedMemorySize, GEMM_SMEM);
        cudaFuncSetAttribute(hmma_gemm_out, cudaFuncAttributeMaxDynamicSharedMemorySize, GEMM_SMEM);
        attr_set = 1;
    }

    split_inputs_kernel<<<dim3(256, 3), 256>>>(query, key, value);
    split_weights_kernel<<<dim3(16, 16, 4), dim3(32, 8)>>>(Wq, Wk, Wv, Wo);
    hmma_gemm_qkv<<<dim3(NTOK_/GBM_, FEAT_/GBN_, 3), 256, GEMM_SMEM>>>(bq, bk, bv);
    attn_mma_kernel<<<dim3(T_/ABT_, B_*H_), 256, ATT_SMEM>>>(mask, span);
    hmma_gemm_out<<<dim3(NTOK_/GBM_, FEAT_/GBN_), 256, GEMM_SMEM>>>(bo, out);
}

// round 13
// speedup vs baseline: 3.5893x; 1.3066x over previous
#include <cuda_runtime.h>
#include <cuda_bf16.h>
#include <cuda_fp16.h>
#include <cstdint>
#include <stdint.h>
#include <float.h>
#include <math.h>

// Problem constants
#define B_    4
#define T_    1024
#define FEAT_ 512
#define H_    8
#define DK_   64
#define SPAN_ 100
#define PADL_ 50
#define NTOK_ (B_*T_)
#define NEL_  (NTOK_*FEAT_)

// HMMA GEMM tiling: 128x64 tile, BK=32, cp.async double-buffered.
// A = single fp16, W = fp16 hi/lo (2 MMAs per k-step pair).
// [Resubmission of R12 — prior round was a broker/container failure, kernel never ran.]
#define GBM_  128
#define GBN_  64
#define BKg   32
#define PADK  40
#define SAF_BYTES (GBM_*PADK*2)              // 10240 (A fp16 single)
#define SW_BYTES  (GBN_*PADK*2)              // 5120 per W array
#define BUF_BYTES (SAF_BYTES + 2*SW_BYTES)   // 20480
#define GEMM_SMEM (2*BUF_BYTES)              // 40960

// MMA attention tiling (V aliases K smem)
#define ABT_   128
#define AROWS_ 240
#define ASTR_  72
#define SQH_OFF  0
#define SQL_OFF  (SQH_OFF + ABT_*ASTR_*2)
#define SKVH_OFF (SQL_OFF + ABT_*ASTR_*2)
#define SKVL_OFF (SKVH_OFF + AROWS_*ASTR_*2)
#define SMK_OFF  (SKVL_OFF + AROWS_*ASTR_*2)
#define ATT_SMEM (SMK_OFF + AROWS_*4)

// ---------------------------------------------------------------------------
// Device scratch
// ---------------------------------------------------------------------------
__device__ __half g_qf[NEL_];                 // inputs, single fp16
__device__ __half g_kf[NEL_];
__device__ __half g_vf[NEL_];
__device__ __nv_bfloat16 g_pqh[NEL_];         // projected q/k/v, bf16 split (attn)
__device__ __nv_bfloat16 g_pql[NEL_];
__device__ __nv_bfloat16 g_pkh[NEL_];
__device__ __nv_bfloat16 g_pkl[NEL_];
__device__ __nv_bfloat16 g_pvh[NEL_];
__device__ __nv_bfloat16 g_pvl[NEL_];
__device__ __half g_xf[NEL_];                 // context, single fp16
__device__ __half g_wth[4 * FEAT_ * FEAT_];   // transposed weights, fp16 hi
__device__ __half g_wtl[4 * FEAT_ * FEAT_];   // transposed weights, fp16 lo

// ---------------------------------------------------------------------------
// PTX helpers
// ---------------------------------------------------------------------------
__device__ __forceinline__ unsigned smem_u32(const void* p) {
    unsigned a;
    asm("{ .reg .u64 t; cvta.to.shared.u64 t, %1; cvt.u32.u64 %0, t; }" : "=r"(a) : "l"(p));
    return a;
}
__device__ __forceinline__ void mma_bf16(float* c, const unsigned* a, const unsigned* b) {
    asm volatile(
        "mma.sync.aligned.m16n8k16.row.col.f32.bf16.bf16.f32 "
        "{%0,%1,%2,%3}, {%4,%5,%6,%7}, {%8,%9}, {%0,%1,%2,%3};"
        : "+f"(c[0]), "+f"(c[1]), "+f"(c[2]), "+f"(c[3])
        : "r"(a[0]), "r"(a[1]), "r"(a[2]), "r"(a[3]), "r"(b[0]), "r"(b[1]));
}
__device__ __forceinline__ void mma_fp16(float* c, const unsigned* a, const unsigned* b) {
    asm volatile(
        "mma.sync.aligned.m16n8k16.row.col.f32.f16.f16.f32 "
        "{%0,%1,%2,%3}, {%4,%5,%6,%7}, {%8,%9}, {%0,%1,%2,%3};"
        : "+f"(c[0]), "+f"(c[1]), "+f"(c[2]), "+f"(c[3])
        : "r"(a[0]), "r"(a[1]), "r"(a[2]), "r"(a[3]), "r"(b[0]), "r"(b[1]));
}
__device__ __forceinline__ void ldsm4(unsigned* r, unsigned addr) {
    asm volatile("ldmatrix.sync.aligned.m8n8.x4.shared.b16 {%0,%1,%2,%3}, [%4];"
        : "=r"(r[0]), "=r"(r[1]), "=r"(r[2]), "=r"(r[3]) : "r"(addr));
}
__device__ __forceinline__ void ldsm4t(unsigned* r, unsigned addr) {
    asm volatile("ldmatrix.sync.aligned.m8n8.x4.trans.shared.b16 {%0,%1,%2,%3}, [%4];"
        : "=r"(r[0]), "=r"(r[1]), "=r"(r[2]), "=r"(r[3]) : "r"(addr));
}
__device__ __forceinline__ void cp16(unsigned dst, const void* src) {
    asm volatile("cp.async.cg.shared.global [%0], [%1], 16;" :: "r"(dst), "l"(src));
}
__device__ __forceinline__ void cp_commit() {
    asm volatile("cp.async.commit_group;" ::: "memory");
}
__device__ __forceinline__ void cp_wait1() {
    asm volatile("cp.async.wait_group 1;" ::: "memory");
}
__device__ __forceinline__ void cp_wait0() {
    asm volatile("cp.async.wait_group 0;" ::: "memory");
}
// bf16 hi/lo pack (attention inputs)
__device__ __forceinline__ unsigned pack_split_hi(float a, float b, unsigned& lo_out) {
    __nv_bfloat162 hp, lp;
    hp.x = __float2bfloat16_rn(a);
    hp.y = __float2bfloat16_rn(b);
    lp.x = __float2bfloat16_rn(a - __bfloat162float(hp.x));
    lp.y = __float2bfloat16_rn(b - __bfloat162float(hp.y));
    lo_out = *(unsigned*)&lp;
    return *(unsigned*)&hp;
}

// ---------------------------------------------------------------------------
// Convert inputs fp32 -> single fp16. blockIdx.y selects q/k/v.
// ---------------------------------------------------------------------------
__global__ __launch_bounds__(256)
void convert_inputs_kernel(const float* __restrict__ q, const float* __restrict__ k,
                           const float* __restrict__ v)
{
    const float* src;
    __half* dst;
    if (blockIdx.y == 0)      { src = q; dst = g_qf; }
    else if (blockIdx.y == 1) { src = k; dst = g_kf; }
    else                      { src = v; dst = g_vf; }

    const int n4 = NEL_ / 4;
    for (int i = blockIdx.x * blockDim.x + threadIdx.x; i < n4; i += gridDim.x * blockDim.x) {
        float4 x = ((const float4*)src)[i];
        __half2 a = __floats2half2_rn(x.x, x.y);
        __half2 b = __floats2half2_rn(x.z, x.w);
        ((__half2*)dst)[i*2]   = a;
        ((__half2*)dst)[i*2+1] = b;
    }
}

// ---------------------------------------------------------------------------
// Transpose + split weights: W[k][n] fp32 -> Wt[n][k] fp16 hi/lo.
// ---------------------------------------------------------------------------
__global__ __launch_bounds__(256)
void split_weights_kernel(const float* __restrict__ Wq, const float* __restrict__ Wk,
                          const float* __restrict__ Wv, const float* __restrict__ Wo)
{
    const int z = blockIdx.z;
    const float* W = (z == 0) ? Wq : (z == 1) ? Wk : (z == 2) ? Wv : Wo;
    __half* Th = g_wth + (size_t)z * FEAT_ * FEAT_;
    __half* Tl = g_wtl + (size_t)z * FEAT_ * FEAT_;

    __shared__ float tile[32][33];
    const int tx = threadIdx.x, ty = threadIdx.y;
    const int kb = blockIdx.y * 32, nb = blockIdx.x * 32;
#pragma unroll
    for (int i = 0; i < 4; i++)
        tile[ty + i*8][tx] = W[(size_t)(kb + ty + i*8) * FEAT_ + nb + tx];
    __syncthreads();
#pragma unroll
    for (int i = 0; i < 4; i++) {
        const int n = nb + ty + i*8;
        const int kk = kb + tx;
        float x = tile[tx][ty + i*8];
        __half h = __float2half_rn(x);
        Th[(size_t)n * FEAT_ + kk] = h;
        Tl[(size_t)n * FEAT_ + kk] = __float2half_rn(x - __half2float(h));
    }
}

// ---------------------------------------------------------------------------
// fp16 2-MMA HMMA GEMM: C = A(fp16) @ (Wh+Wl)^T + bias.
// 128x64 tile, cp.async double-buffered, 8 warps 4Mx2N.
// SPLIT_OUT: write bf16 hi/lo (attn operands); else fp32.
// ---------------------------------------------------------------------------
template<bool SPLIT_OUT>
__device__ __forceinline__
void hmma_gemm_body(const __half* __restrict__ Af,
                    const __half* __restrict__ Wh, const __half* __restrict__ Wl,
                    const float* __restrict__ bias, float* __restrict__ C,
                    __nv_bfloat16* __restrict__ Ch, __nv_bfloat16* __restrict__ Cl,
                    int bm, int bn)
{
    extern __shared__ char smg[];
    const unsigned sb = smem_u32(smg);

    const int tid = threadIdx.x;
    const int wid = tid >> 5;
    const int lane = tid & 31;
    const int wm = (wid & 3) * 32;
    const int wn = (wid >> 2) * 32;

    const int q3 = lane >> 3;
    const int l7 = lane & 7;

    const int ar0 = tid >> 2, as0 = tid & 3;
    const int ar1 = (tid + 256) >> 2;
    const int wr0 = tid >> 2, ws0 = tid & 3;

    float acc[2][4][4] = {};

    {
        const unsigned base = sb;
        cp16(base + (unsigned)(ar0 * PADK + as0 * 8) * 2,
             Af + (size_t)(bm * GBM_ + ar0) * FEAT_ + as0 * 8);
        cp16(base + (unsigned)(ar1 * PADK + as0 * 8) * 2,
             Af + (size_t)(bm * GBM_ + ar1) * FEAT_ + as0 * 8);
        cp16(base + SAF_BYTES + (unsigned)(wr0 * PADK + ws0 * 8) * 2,
             Wh + (size_t)(bn * GBN_ + wr0) * FEAT_ + ws0 * 8);
        cp16(base + SAF_BYTES + SW_BYTES + (unsigned)(wr0 * PADK + ws0 * 8) * 2,
             Wl + (size_t)(bn * GBN_ + wr0) * FEAT_ + ws0 * 8);
        cp_commit();
    }

    const int NIT = FEAT_ / BKg;
    for (int it = 0; it < NIT; it++) {
        if (it + 1 < NIT) {
            const int kt = (it + 1) * BKg;
            const unsigned base = sb + (unsigned)(((it + 1) & 1) * BUF_BYTES);
            cp16(base + (unsigned)(ar0 * PADK + as0 * 8) * 2,
                 Af + (size_t)(bm * GBM_ + ar0) * FEAT_ + kt + as0 * 8);
            cp16(base + (unsigned)(ar1 * PADK + as0 * 8) * 2,
                 Af + (size_t)(bm * GBM_ + ar1) * FEAT_ + kt + as0 * 8);
            cp16(base + SAF_BYTES + (unsigned)(wr0 * PADK + ws0 * 8) * 2,
                 Wh + (size_t)(bn * GBN_ + wr0) * FEAT_ + kt + ws0 * 8);
            cp16(base + SAF_BYTES + SW_BYTES + (unsigned)(wr0 * PADK + ws0 * 8) * 2,
                 Wl + (size_t)(bn * GBN_ + wr0) * FEAT_ + kt + ws0 * 8);
            cp_commit();
            cp_wait1();
        } else {
            cp_wait0();
        }
        __syncthreads();

        const unsigned uB = sb + (unsigned)((it & 1) * BUF_BYTES);
        const unsigned uAf = uB;
        const unsigned uWh = uB + SAF_BYTES;
        const unsigned uWl = uB + SAF_BYTES + SW_BYTES;

#pragma unroll
        for (int ks = 0; ks < 2; ks++) {
            const int ko = ks * 16;
            unsigned af[2][4];
            unsigned bh[8], bl[8];
#pragma unroll
            for (int mf = 0; mf < 2; mf++) {
                const unsigned arow = (unsigned)(wm + mf * 16 + (q3 & 1) * 8 + l7);
                const unsigned ab = (arow * PADK + (unsigned)(ko + (q3 >> 1) * 8)) * 2;
                ldsm4(af[mf], uAf + ab);
            }
            {
                const unsigned nrow = (unsigned)(wn + (q3 >> 1) * 8 + l7);
                const unsigned bb = (nrow * PADK + (unsigned)(ko + (q3 & 1) * 8)) * 2;
                ldsm4(bh, uWh + bb);
                ldsm4(bl, uWl + bb);
                const unsigned bb2 = ((nrow + 16) * PADK + (unsigned)(ko + (q3 & 1) * 8)) * 2;
                ldsm4(bh + 4, uWh + bb2);
                ldsm4(bl + 4, uWl + bb2);
            }
#pragma unroll
            for (int mf = 0; mf < 2; mf++)
#pragma unroll
                for (int nf = 0; nf < 4; nf++) {
                    mma_fp16(acc[mf][nf], af[mf], bh + 2 * nf);
                    mma_fp16(acc[mf][nf], af[mf], bl + 2 * nf);
                }
        }
        __syncthreads();
    }

#pragma unroll
    for (int mf = 0; mf < 2; mf++) {
        const int r0 = bm * GBM_ + wm + mf * 16 + (lane >> 2);
#pragma unroll
        for (int nf = 0; nf < 4; nf++) {
            const int col = bn * GBN_ + wn + nf * 8 + 2 * (lane & 3);
            const float b0 = bias[col], b1 = bias[col + 1];
            const float v00 = acc[mf][nf][0] + b0, v01 = acc[mf][nf][1] + b1;
            const float v10 = acc[mf][nf][2] + b0, v11 = acc[mf][nf][3] + b1;
            if (SPLIT_OUT) {
                const size_t i0 = (size_t)r0 * FEAT_ + col;
                const size_t i1 = (size_t)(r0 + 8) * FEAT_ + col;
                unsigned lo;
                unsigned hi = pack_split_hi(v00, v01, lo);
                *(unsigned*)(Ch + i0) = hi;  *(unsigned*)(Cl + i0) = lo;
                hi = pack_split_hi(v10, v11, lo);
                *(unsigned*)(Ch + i1) = hi;  *(unsigned*)(Cl + i1) = lo;
            } else {
                *(float2*)(C + (size_t)r0 * FEAT_ + col) = make_float2(v00, v01);
                *(float2*)(C + (size_t)(r0 + 8) * FEAT_ + col) = make_float2(v10, v11);
            }
        }
    }
}

__global__ __launch_bounds__(256, 2)
void hmma_gemm_qkv(const float* __restrict__ bq, const float* __restrict__ bk,
                   const float* __restrict__ bv)
{
    const __half* Af;
    const float* bi;
    __nv_bfloat16 *Ch, *Cl;
    int wz;
    if (blockIdx.z == 0)      { Af = g_qf; bi = bq; Ch = g_pqh; Cl = g_pql; wz = 0; }
    else if (blockIdx.z == 1) { Af = g_kf; bi = bk; Ch = g_pkh; Cl = g_pkl; wz = 1; }
    else                      { Af = g_vf; bi = bv; Ch = g_pvh; Cl = g_pvl; wz = 2; }
    hmma_gemm_body<true>(Af,
                         g_wth + (size_t)wz * FEAT_ * FEAT_,
                         g_wtl + (size_t)wz * FEAT_ * FEAT_,
                         bi, nullptr, Ch, Cl, blockIdx.x, blockIdx.y);
}

__global__ __launch_bounds__(256, 2)
void hmma_gemm_out(const float* __restrict__ bo, float* __restrict__ out)
{
    hmma_gemm_body<false>(g_xf,
                          g_wth + (size_t)3 * FEAT_ * FEAT_,
                          g_wtl + (size_t)3 * FEAT_ * FEAT_,
                          bo, out, nullptr, nullptr, blockIdx.x, blockIdx.y);
}

// ---------------------------------------------------------------------------
// MMA band attention (bf16-split math; x written fp16).
// ---------------------------------------------------------------------------
__global__ __launch_bounds__(256, 2)
void attn_mma_kernel(const int* __restrict__ mask, const float* __restrict__ span)
{
    extern __shared__ char sm[];
    const unsigned uQh  = smem_u32(sm + SQH_OFF);
    const unsigned uQl  = smem_u32(sm + SQL_OFF);
    const unsigned uKVh = smem_u32(sm + SKVH_OFF);
    const unsigned uKVl = smem_u32(sm + SKVL_OFF);
    int* smk = (int*)(sm + SMK_OFF);

    const int bx = blockIdx.x, bhz = blockIdx.y;
    const int b = bhz >> 3, h = bhz & 7;
    const int t0 = bx * ABT_;
    const int j0 = t0 - PADL_;
    const int tid = threadIdx.x;
    const int w = tid >> 5, lane = tid & 31;

    __nv_bfloat16* sQh  = (__nv_bfloat16*)(sm + SQH_OFF);
    __nv_bfloat16* sQl  = (__nv_bfloat16*)(sm + SQL_OFF);
    __nv_bfloat16* sKVh = (__nv_bfloat16*)(sm + SKVH_OFF);
    __nv_bfloat16* sKVl = (__nv_bfloat16*)(sm + SKVL_OFF);

    for (int u = tid; u < ABT_ * 8; u += 256) {
        const int rr = u >> 3, g = u & 7;
        const size_t gi = (size_t)(b * T_ + t0 + rr) * FEAT_ + h * DK_ + g * 8;
        *(uint4*)(sQh + rr * ASTR_ + g * 8) = *(const uint4*)(g_pqh + gi);
        *(uint4*)(sQl + rr * ASTR_ + g * 8) = *(const uint4*)(g_pql + gi);
    }
    for (int u = tid; u < AROWS_ * 8; u += 256) {
        const int rr = u >> 3, g = u & 7;
        const int j = j0 + rr;
        uint4 kh4 = {0,0,0,0}, kl4 = {0,0,0,0};
        if (j >= 0 && j < T_) {
            const size_t gi = (size_t)(b * T_ + j) * FEAT_ + h * DK_ + g * 8;
            kh4 = *(const uint4*)(g_pkh + gi);
            kl4 = *(const uint4*)(g_pkl + gi);
        }
        *(uint4*)(sKVh + rr * ASTR_ + g * 8) = kh4;
        *(uint4*)(sKVl + rr * ASTR_ + g * 8) = kl4;
    }
    for (int rr = tid; rr < AROWS_; rr += 256) {
        const int j = j0 + rr;
        smk[rr] = (j >= 0 && j < T_) ? mask[b * T_ + j] : 0;
    }
    __syncthreads();

    const int q3 = lane >> 3;
    const int l7 = lane & 7;

    unsigned qfh[4][4], qfl[4][4];
    {
        const unsigned rbase = (unsigned)(w * 16 + (q3 & 1) * 8 + l7);
#pragma unroll
        for (int kk = 0; kk < 4; kk++) {
            const unsigned off = (rbase * ASTR_ + (unsigned)(kk * 16 + (q3 >> 1) * 8)) * 2;
            ldsm4(qfh[kk], uQh + off);
            ldsm4(qfl[kk], uQl + off);
        }
    }

    float sacc[16][4] = {};
#pragma unroll
    for (int nt = 0; nt < 8; nt++) {
        const unsigned nrow = (unsigned)(w * 16 + nt * 16 + (q3 >> 1) * 8 + l7);
#pragma unroll
        for (int kk = 0; kk < 4; kk++) {
            const unsigned off = (nrow * ASTR_ + (unsigned)(kk * 16 + (q3 & 1) * 8)) * 2;
            unsigned kbh[4], kbl[4];
            ldsm4(kbh, uKVh + off);
            ldsm4(kbl, uKVl + off);
            mma_bf16(sacc[2*nt],   qfh[kk], &kbh[0]);
            mma_bf16(sacc[2*nt],   qfh[kk], &kbl[0]);
            mma_bf16(sacc[2*nt],   qfl[kk], &kbh[0]);
            mma_bf16(sacc[2*nt+1], qfh[kk], &kbh[2]);
            mma_bf16(sacc[2*nt+1], qfh[kk], &kbl[2]);
            mma_bf16(sacc[2*nt+1], qfl[kk], &kbh[2]);
        }
    }

    __syncthreads();
    for (int u = tid; u < AROWS_ * 8; u += 256) {
        const int rr = u >> 3, g = u & 7;
        const int j = j0 + rr;
        uint4 vh4 = {0,0,0,0}, vl4 = {0,0,0,0};
        if (j >= 0 && j < T_) {
            const size_t gi = (size_t)(b * T_ + j) * FEAT_ + h * DK_ + g * 8;
            vh4 = *(const uint4*)(g_pvh + gi);
            vl4 = *(const uint4*)(g_pvl + gi);
        }
        *(uint4*)(sKVh + rr * ASTR_ + g * 8) = vh4;
        *(uint4*)(sKVl + rr * ASTR_ + g * 8) = vl4;
    }

    const int r = lane >> 2;
    const int c2 = 2 * (lane & 3);
    const float spanv = span[h];
    float mx0 = -1e30f, mx1 = -1e30f;
#pragma unroll
    for (int nt8 = 0; nt8 < 16; nt8++) {
#pragma unroll
        for (int e = 0; e < 2; e++) {
            const int c = 8 * nt8 + c2 + e;
            const int mv = smk[w * 16 + c];
            const int s0 = c - r;
            const int s1 = c - r - 8;
            const bool v0 = (s0 >= 0) && (s0 < SPAN_) && (mv != 0);
            const bool v1 = (s1 >= 0) && (s1 < SPAN_) && (mv != 0);
            const float x0 = v0 ? sacc[nt8][e]     * 0.125f : -1e30f;
            const float x1 = v1 ? sacc[nt8][2 + e] * 0.125f : -1e30f;
            sacc[nt8][e] = x0;
            sacc[nt8][2 + e] = x1;
            mx0 = fmaxf(mx0, x0);
            mx1 = fmaxf(mx1, x1);
        }
    }
    mx0 = fmaxf(mx0, __shfl_xor_sync(0xffffffffu, mx0, 1));
    mx0 = fmaxf(mx0, __shfl_xor_sync(0xffffffffu, mx0, 2));
    mx1 = fmaxf(mx1, __shfl_xor_sync(0xffffffffu, mx1, 1));
    mx1 = fmaxf(mx1, __shfl_xor_sync(0xffffffffu, mx1, 2));

    float E0 = 0.f, S0 = 0.f, E1 = 0.f, S1 = 0.f;
#pragma unroll
    for (int nt8 = 0; nt8 < 16; nt8++) {
#pragma unroll
        for (int e = 0; e < 2; e++) {
            const int c = 8 * nt8 + c2 + e;
            const int s0 = c - r;
            const int s1 = c - r - 8;
            const float sf0 = fminf(fmaxf(((float)s0 - 99.0f + spanv * 100.0f) * 0.5f + 1.0f, 0.f), 1.f);
            const float sf1 = fminf(fmaxf(((float)s1 - 99.0f + spanv * 100.0f) * 0.5f + 1.0f, 0.f), 1.f);
            const float e0 = __expf(sacc[nt8][e] - mx0);
            const float e1 = __expf(sacc[nt8][2 + e] - mx1);
            E0 += e0; S0 += e0 * sf0;
            E1 += e1; S1 += e1 * sf1;
            sacc[nt8][e] = e0 * sf0;
            sacc[nt8][2 + e] = e1 * sf1;
        }
    }
    E0 += __shfl_xor_sync(0xffffffffu, E0, 1);  E0 += __shfl_xor_sync(0xffffffffu, E0, 2);
    S0 += __shfl_xor_sync(0xffffffffu, S0, 1);  S0 += __shfl_xor_sync(0xffffffffu, S0, 2);
    E1 += __shfl_xor_sync(0xffffffffu, E1, 1);  E1 += __shfl_xor_sync(0xffffffffu, E1, 2);
    S1 += __shfl_xor_sync(0xffffffffu, S1, 1);  S1 += __shfl_xor_sync(0xffffffffu, S1, 2);
    const float inv0 = (mx0 > -1e29f) ? 1.0f / (S0 + 1e-8f * E0) : 0.f;
    const float inv1 = (mx1 > -1e29f) ? 1.0f / (S1 + 1e-8f * E1) : 0.f;

    unsigned pah[8][4], pal[8][4];
#pragma unroll
    for (int j8 = 0; j8 < 8; j8++) {
        pah[j8][0] = pack_split_hi(sacc[2*j8][0]*inv0,   sacc[2*j8][1]*inv0,   pal[j8][0]);
        pah[j8][1] = pack_split_hi(sacc[2*j8][2]*inv1,   sacc[2*j8][3]*inv1,   pal[j8][1]);
        pah[j8][2] = pack_split_hi(sacc[2*j8+1][0]*inv0, sacc[2*j8+1][1]*inv0, pal[j8][2]);
        pah[j8][3] = pack_split_hi(sacc[2*j8+1][2]*inv1, sacc[2*j8+1][3]*inv1, pal[j8][3]);
    }

    __syncthreads();

    float oacc[8][4] = {};
#pragma unroll
    for (int kk2 = 0; kk2 < 8; kk2++) {
        const unsigned krow = (unsigned)(w * 16 + kk2 * 16 + (q3 & 1) * 8 + l7);
#pragma unroll
        for (int nt = 0; nt < 4; nt++) {
            const unsigned off = (krow * ASTR_ + (unsigned)(nt * 16 + (q3 >> 1) * 8)) * 2;
            unsigned vbh[4], vbl[4];
            ldsm4t(vbh, uKVh + off);
            ldsm4t(vbl, uKVl + off);
            mma_bf16(oacc[2*nt],   pah[kk2], &vbh[0]);
            mma_bf16(oacc[2*nt],   pah[kk2], &vbl[0]);
            mma_bf16(oacc[2*nt],   pal[kk2], &vbh[0]);
            mma_bf16(oacc[2*nt+1], pah[kk2], &vbh[2]);
            mma_bf16(oacc[2*nt+1], pah[kk2], &vbl[2]);
            mma_bf16(oacc[2*nt+1], pal[kk2], &vbh[2]);
        }
    }

    // Write context as single fp16 (A-operand of the 2-MMA out projection)
    const int tr = t0 + w * 16 + r;
#pragma unroll
    for (int nf = 0; nf < 8; nf++) {
        const int col = 8 * nf + c2;
        const size_t i0 = (size_t)(b * T_ + tr) * FEAT_ + h * DK_ + col;
        const size_t i1 = (size_t)(b * T_ + tr + 8) * FEAT_ + h * DK_ + col;
        __half2 p0 = __floats2half2_rn(oacc[nf][0], oacc[nf][1]);
        __half2 p1 = __floats2half2_rn(oacc[nf][2], oacc[nf][3]);
        *(__half2*)(g_xf + i0) = p0;
        *(__half2*)(g_xf + i1) = p1;
    }
}

// ---------------------------------------------------------------------------
// Launch
// ---------------------------------------------------------------------------
extern "C" void kernel_launch(void* const* d_in, const int* in_sizes, int n_in,
                              void* d_out, int out_size)
{
    (void)in_sizes; (void)n_in; (void)out_size;
    const float* query = (const float*)d_in[0];
    const float* key   = (const float*)d_in[1];
    const float* value = (const float*)d_in[2];
    const int*   mask  = (const int*)  d_in[3];
    const float* Wq    = (const float*)d_in[4];
    const float* bq    = (const float*)d_in[5];
    const float* Wk    = (const float*)d_in[6];
    const float* bk    = (const float*)d_in[7];
    const float* Wv    = (const float*)d_in[8];
    const float* bv    = (const float*)d_in[9];
    const float* Wo    = (const float*)d_in[10];
    const float* bo    = (const float*)d_in[11];
    const float* span  = (const float*)d_in[12];
    float* out = (float*)d_out;

    static int attr_set = 0;
    if (!attr_set) {
        cudaFuncSetAttribute(attn_mma_kernel, cudaFuncAttributeMaxDynamicSharedMemorySize, ATT_SMEM);
        cudaFuncSetAttribute(hmma_gemm_qkv, cudaFuncAttributeMaxDynamicSharedMemorySize, GEMM_SMEM);
        cudaFuncSetAttribute(hmma_gemm_out, cudaFuncAttributeMaxDynamicSharedMemorySize, GEMM_SMEM);
        attr_set = 1;
    }

    convert_inputs_kernel<<<dim3(256, 3), 256>>>(query, key, value);
    split_weights_kernel<<<dim3(16, 16, 4), dim3(32, 8)>>>(Wq, Wk, Wv, Wo);
    hmma_gemm_qkv<<<dim3(NTOK_/GBM_, FEAT_/GBN_, 3), 256, GEMM_SMEM>>>(bq, bk, bv);
    attn_mma_kernel<<<dim3(T_/ABT_, B_*H_), 256, ATT_SMEM>>>(mask, span);
    hmma_gemm_out<<<dim3(NTOK_/GBM_, FEAT_/GBN_), 256, GEMM_SMEM>>>(bo, out);
}

// round 14
// speedup vs baseline: 4.7006x; 1.3096x over previous
#include <cuda_runtime.h>
#include <cuda_bf16.h>
#include <cuda_fp16.h>
#include <cstdint>
#include <stdint.h>
#include <float.h>
#include <math.h>

// Problem constants
#define B_    4
#define T_    1024
#define FEAT_ 512
#define H_    8
#define DK_   64
#define SPAN_ 100
#define PADL_ 50
#define NTOK_ (B_*T_)
#define NEL_  (NTOK_*FEAT_)

// HMMA GEMM tiling: 128x64 tile, BK=32, cp.async double-buffered.
// A = single fp16, W = single fp16 (1 MMA per fragment pair).
#define GBM_  128
#define GBN_  64
#define BKg   32
#define PADK  40
#define SAF_BYTES (GBM_*PADK*2)              // 10240 (A fp16)
#define SW_BYTES  (GBN_*PADK*2)              // 5120  (W fp16)
#define BUF_BYTES (SAF_BYTES + SW_BYTES)     // 15360
#define GEMM_SMEM (2*BUF_BYTES)              // 30720

// MMA attention tiling (V aliases K smem) — unchanged, bf16-split math
#define ABT_   128
#define AROWS_ 240
#define ASTR_  72
#define SQH_OFF  0
#define SQL_OFF  (SQH_OFF + ABT_*ASTR_*2)
#define SKVH_OFF (SQL_OFF + ABT_*ASTR_*2)
#define SKVL_OFF (SKVH_OFF + AROWS_*ASTR_*2)
#define SMK_OFF  (SKVL_OFF + AROWS_*ASTR_*2)
#define ATT_SMEM (SMK_OFF + AROWS_*4)

// ---------------------------------------------------------------------------
// Device scratch
// ---------------------------------------------------------------------------
__device__ __half g_qf[NEL_];                 // inputs, single fp16
__device__ __half g_kf[NEL_];
__device__ __half g_vf[NEL_];
__device__ __nv_bfloat16 g_pqh[NEL_];         // projected q/k/v, bf16 split (attn)
__device__ __nv_bfloat16 g_pql[NEL_];
__device__ __nv_bfloat16 g_pkh[NEL_];
__device__ __nv_bfloat16 g_pkl[NEL_];
__device__ __nv_bfloat16 g_pvh[NEL_];
__device__ __nv_bfloat16 g_pvl[NEL_];
__device__ __half g_xf[NEL_];                 // context, single fp16
__device__ __half g_wt[4 * FEAT_ * FEAT_];    // transposed weights, single fp16

// ---------------------------------------------------------------------------
// PTX helpers
// ---------------------------------------------------------------------------
__device__ __forceinline__ unsigned smem_u32(const void* p) {
    unsigned a;
    asm("{ .reg .u64 t; cvta.to.shared.u64 t, %1; cvt.u32.u64 %0, t; }" : "=r"(a) : "l"(p));
    return a;
}
__device__ __forceinline__ void mma_bf16(float* c, const unsigned* a, const unsigned* b) {
    asm volatile(
        "mma.sync.aligned.m16n8k16.row.col.f32.bf16.bf16.f32 "
        "{%0,%1,%2,%3}, {%4,%5,%6,%7}, {%8,%9}, {%0,%1,%2,%3};"
        : "+f"(c[0]), "+f"(c[1]), "+f"(c[2]), "+f"(c[3])
        : "r"(a[0]), "r"(a[1]), "r"(a[2]), "r"(a[3]), "r"(b[0]), "r"(b[1]));
}
__device__ __forceinline__ void mma_fp16(float* c, const unsigned* a, const unsigned* b) {
    asm volatile(
        "mma.sync.aligned.m16n8k16.row.col.f32.f16.f16.f32 "
        "{%0,%1,%2,%3}, {%4,%5,%6,%7}, {%8,%9}, {%0,%1,%2,%3};"
        : "+f"(c[0]), "+f"(c[1]), "+f"(c[2]), "+f"(c[3])
        : "r"(a[0]), "r"(a[1]), "r"(a[2]), "r"(a[3]), "r"(b[0]), "r"(b[1]));
}
__device__ __forceinline__ void ldsm4(unsigned* r, unsigned addr) {
    asm volatile("ldmatrix.sync.aligned.m8n8.x4.shared.b16 {%0,%1,%2,%3}, [%4];"
        : "=r"(r[0]), "=r"(r[1]), "=r"(r[2]), "=r"(r[3]) : "r"(addr));
}
__device__ __forceinline__ void ldsm4t(unsigned* r, unsigned addr) {
    asm volatile("ldmatrix.sync.aligned.m8n8.x4.trans.shared.b16 {%0,%1,%2,%3}, [%4];"
        : "=r"(r[0]), "=r"(r[1]), "=r"(r[2]), "=r"(r[3]) : "r"(addr));
}
__device__ __forceinline__ void cp16(unsigned dst, const void* src) {
    asm volatile("cp.async.cg.shared.global [%0], [%1], 16;" :: "r"(dst), "l"(src));
}
__device__ __forceinline__ void cp_commit() {
    asm volatile("cp.async.commit_group;" ::: "memory");
}
__device__ __forceinline__ void cp_wait1() {
    asm volatile("cp.async.wait_group 1;" ::: "memory");
}
__device__ __forceinline__ void cp_wait0() {
    asm volatile("cp.async.wait_group 0;" ::: "memory");
}
// bf16 hi/lo pack (attention inputs)
__device__ __forceinline__ unsigned pack_split_hi(float a, float b, unsigned& lo_out) {
    __nv_bfloat162 hp, lp;
    hp.x = __float2bfloat16_rn(a);
    hp.y = __float2bfloat16_rn(b);
    lp.x = __float2bfloat16_rn(a - __bfloat162float(hp.x));
    lp.y = __float2bfloat16_rn(b - __bfloat162float(hp.y));
    lo_out = *(unsigned*)&lp;
    return *(unsigned*)&hp;
}

// ---------------------------------------------------------------------------
// Convert inputs fp32 -> single fp16. blockIdx.y selects q/k/v.
// ---------------------------------------------------------------------------
__global__ __launch_bounds__(256)
void convert_inputs_kernel(const float* __restrict__ q, const float* __restrict__ k,
                           const float* __restrict__ v)
{
    const float* src;
    __half* dst;
    if (blockIdx.y == 0)      { src = q; dst = g_qf; }
    else if (blockIdx.y == 1) { src = k; dst = g_kf; }
    else                      { src = v; dst = g_vf; }

    const int n4 = NEL_ / 4;
    for (int i = blockIdx.x * blockDim.x + threadIdx.x; i < n4; i += gridDim.x * blockDim.x) {
        float4 x = ((const float4*)src)[i];
        __half2 a = __floats2half2_rn(x.x, x.y);
        __half2 b = __floats2half2_rn(x.z, x.w);
        ((__half2*)dst)[i*2]   = a;
        ((__half2*)dst)[i*2+1] = b;
    }
}

// ---------------------------------------------------------------------------
// Transpose + convert weights: W[k][n] fp32 -> Wt[n][k] single fp16.
// ---------------------------------------------------------------------------
__global__ __launch_bounds__(256)
void convert_weights_kernel(const float* __restrict__ Wq, const float* __restrict__ Wk,
                            const float* __restrict__ Wv, const float* __restrict__ Wo)
{
    const int z = blockIdx.z;
    const float* W = (z == 0) ? Wq : (z == 1) ? Wk : (z == 2) ? Wv : Wo;
    __half* Tw = g_wt + (size_t)z * FEAT_ * FEAT_;

    __shared__ float tile[32][33];
    const int tx = threadIdx.x, ty = threadIdx.y;
    const int kb = blockIdx.y * 32, nb = blockIdx.x * 32;
#pragma unroll
    for (int i = 0; i < 4; i++)
        tile[ty + i*8][tx] = W[(size_t)(kb + ty + i*8) * FEAT_ + nb + tx];
    __syncthreads();
#pragma unroll
    for (int i = 0; i < 4; i++) {
        const int n = nb + ty + i*8;
        const int kk = kb + tx;
        Tw[(size_t)n * FEAT_ + kk] = __float2half_rn(tile[tx][ty + i*8]);
    }
}

// ---------------------------------------------------------------------------
// fp16 single-MMA HMMA GEMM: C = A(fp16) @ W(fp16)^T + bias.
// 128x64 tile, cp.async double-buffered, 8 warps 4Mx2N.
// SPLIT_OUT: write bf16 hi/lo (attn operands); else fp32.
// ---------------------------------------------------------------------------
template<bool SPLIT_OUT>
__device__ __forceinline__
void hmma_gemm_body(const __half* __restrict__ Af,
                    const __half* __restrict__ Wt,
                    const float* __restrict__ bias, float* __restrict__ C,
                    __nv_bfloat16* __restrict__ Ch, __nv_bfloat16* __restrict__ Cl,
                    int bm, int bn)
{
    extern __shared__ char smg[];
    const unsigned sb = smem_u32(smg);

    const int tid = threadIdx.x;
    const int wid = tid >> 5;
    const int lane = tid & 31;
    const int wm = (wid & 3) * 32;
    const int wn = (wid >> 2) * 32;

    const int q3 = lane >> 3;
    const int l7 = lane & 7;

    const int ar0 = tid >> 2, as0 = tid & 3;
    const int ar1 = (tid + 256) >> 2;
    const int wr0 = tid >> 2, ws0 = tid & 3;

    float acc[2][4][4] = {};

    {
        const unsigned base = sb;
        cp16(base + (unsigned)(ar0 * PADK + as0 * 8) * 2,
             Af + (size_t)(bm * GBM_ + ar0) * FEAT_ + as0 * 8);
        cp16(base + (unsigned)(ar1 * PADK + as0 * 8) * 2,
             Af + (size_t)(bm * GBM_ + ar1) * FEAT_ + as0 * 8);
        cp16(base + SAF_BYTES + (unsigned)(wr0 * PADK + ws0 * 8) * 2,
             Wt + (size_t)(bn * GBN_ + wr0) * FEAT_ + ws0 * 8);
        cp_commit();
    }

    const int NIT = FEAT_ / BKg;
    for (int it = 0; it < NIT; it++) {
        if (it + 1 < NIT) {
            const int kt = (it + 1) * BKg;
            const unsigned base = sb + (unsigned)(((it + 1) & 1) * BUF_BYTES);
            cp16(base + (unsigned)(ar0 * PADK + as0 * 8) * 2,
                 Af + (size_t)(bm * GBM_ + ar0) * FEAT_ + kt + as0 * 8);
            cp16(base + (unsigned)(ar1 * PADK + as0 * 8) * 2,
                 Af + (size_t)(bm * GBM_ + ar1) * FEAT_ + kt + as0 * 8);
            cp16(base + SAF_BYTES + (unsigned)(wr0 * PADK + ws0 * 8) * 2,
                 Wt + (size_t)(bn * GBN_ + wr0) * FEAT_ + kt + ws0 * 8);
            cp_commit();
            cp_wait1();
        } else {
            cp_wait0();
        }
        __syncthreads();

        const unsigned uB = sb + (unsigned)((it & 1) * BUF_BYTES);
        const unsigned uAf = uB;
        const unsigned uW  = uB + SAF_BYTES;

#pragma unroll
        for (int ks = 0; ks < 2; ks++) {
            const int ko = ks * 16;
            unsigned af[2][4];
            unsigned bw[8];
#pragma unroll
            for (int mf = 0; mf < 2; mf++) {
                const unsigned arow = (unsigned)(wm + mf * 16 + (q3 & 1) * 8 + l7);
                const unsigned ab = (arow * PADK + (unsigned)(ko + (q3 >> 1) * 8)) * 2;
                ldsm4(af[mf], uAf + ab);
            }
            {
                const unsigned nrow = (unsigned)(wn + (q3 >> 1) * 8 + l7);
                const unsigned bb = (nrow * PADK + (unsigned)(ko + (q3 & 1) * 8)) * 2;
                ldsm4(bw, uW + bb);
                const unsigned bb2 = ((nrow + 16) * PADK + (unsigned)(ko + (q3 & 1) * 8)) * 2;
                ldsm4(bw + 4, uW + bb2);
            }
#pragma unroll
            for (int mf = 0; mf < 2; mf++)
#pragma unroll
                for (int nf = 0; nf < 4; nf++)
                    mma_fp16(acc[mf][nf], af[mf], bw + 2 * nf);
        }
        __syncthreads();
    }

#pragma unroll
    for (int mf = 0; mf < 2; mf++) {
        const int r0 = bm * GBM_ + wm + mf * 16 + (lane >> 2);
#pragma unroll
        for (int nf = 0; nf < 4; nf++) {
            const int col = bn * GBN_ + wn + nf * 8 + 2 * (lane & 3);
            const float b0 = bias[col], b1 = bias[col + 1];
            const float v00 = acc[mf][nf][0] + b0, v01 = acc[mf][nf][1] + b1;
            const float v10 = acc[mf][nf][2] + b0, v11 = acc[mf][nf][3] + b1;
            if (SPLIT_OUT) {
                const size_t i0 = (size_t)r0 * FEAT_ + col;
                const size_t i1 = (size_t)(r0 + 8) * FEAT_ + col;
                unsigned lo;
                unsigned hi = pack_split_hi(v00, v01, lo);
                *(unsigned*)(Ch + i0) = hi;  *(unsigned*)(Cl + i0) = lo;
                hi = pack_split_hi(v10, v11, lo);
                *(unsigned*)(Ch + i1) = hi;  *(unsigned*)(Cl + i1) = lo;
            } else {
                *(float2*)(C + (size_t)r0 * FEAT_ + col) = make_float2(v00, v01);
                *(float2*)(C + (size_t)(r0 + 8) * FEAT_ + col) = make_float2(v10, v11);
            }
        }
    }
}

__global__ __launch_bounds__(256, 2)
void hmma_gemm_qkv(const float* __restrict__ bq, const float* __restrict__ bk,
                   const float* __restrict__ bv)
{
    const __half* Af;
    const float* bi;
    __nv_bfloat16 *Ch, *Cl;
    int wz;
    if (blockIdx.z == 0)      { Af = g_qf; bi = bq; Ch = g_pqh; Cl = g_pql; wz = 0; }
    else if (blockIdx.z == 1) { Af = g_kf; bi = bk; Ch = g_pkh; Cl = g_pkl; wz = 1; }
    else                      { Af = g_vf; bi = bv; Ch = g_pvh; Cl = g_pvl; wz = 2; }
    hmma_gemm_body<true>(Af, g_wt + (size_t)wz * FEAT_ * FEAT_,
                         bi, nullptr, Ch, Cl, blockIdx.x, blockIdx.y);
}

__global__ __launch_bounds__(256, 2)
void hmma_gemm_out(const float* __restrict__ bo, float* __restrict__ out)
{
    hmma_gemm_body<false>(g_xf, g_wt + (size_t)3 * FEAT_ * FEAT_,
                          bo, out, nullptr, nullptr, blockIdx.x, blockIdx.y);
}

// ---------------------------------------------------------------------------
// MMA band attention (bf16-split math, proven; x written fp16).
// ---------------------------------------------------------------------------
__global__ __launch_bounds__(256, 2)
void attn_mma_kernel(const int* __restrict__ mask, const float* __restrict__ span)
{
    extern __shared__ char sm[];
    const unsigned uQh  = smem_u32(sm + SQH_OFF);
    const unsigned uQl  = smem_u32(sm + SQL_OFF);
    const unsigned uKVh = smem_u32(sm + SKVH_OFF);
    const unsigned uKVl = smem_u32(sm + SKVL_OFF);
    int* smk = (int*)(sm + SMK_OFF);

    const int bx = blockIdx.x, bhz = blockIdx.y;
    const int b = bhz >> 3, h = bhz & 7;
    const int t0 = bx * ABT_;
    const int j0 = t0 - PADL_;
    const int tid = threadIdx.x;
    const int w = tid >> 5, lane = tid & 31;

    __nv_bfloat16* sQh  = (__nv_bfloat16*)(sm + SQH_OFF);
    __nv_bfloat16* sQl  = (__nv_bfloat16*)(sm + SQL_OFF);
    __nv_bfloat16* sKVh = (__nv_bfloat16*)(sm + SKVH_OFF);
    __nv_bfloat16* sKVl = (__nv_bfloat16*)(sm + SKVL_OFF);

    for (int u = tid; u < ABT_ * 8; u += 256) {
        const int rr = u >> 3, g = u & 7;
        const size_t gi = (size_t)(b * T_ + t0 + rr) * FEAT_ + h * DK_ + g * 8;
        *(uint4*)(sQh + rr * ASTR_ + g * 8) = *(const uint4*)(g_pqh + gi);
        *(uint4*)(sQl + rr * ASTR_ + g * 8) = *(const uint4*)(g_pql + gi);
    }
    for (int u = tid; u < AROWS_ * 8; u += 256) {
        const int rr = u >> 3, g = u & 7;
        const int j = j0 + rr;
        uint4 kh4 = {0,0,0,0}, kl4 = {0,0,0,0};
        if (j >= 0 && j < T_) {
            const size_t gi = (size_t)(b * T_ + j) * FEAT_ + h * DK_ + g * 8;
            kh4 = *(const uint4*)(g_pkh + gi);
            kl4 = *(const uint4*)(g_pkl + gi);
        }
        *(uint4*)(sKVh + rr * ASTR_ + g * 8) = kh4;
        *(uint4*)(sKVl + rr * ASTR_ + g * 8) = kl4;
    }
    for (int rr = tid; rr < AROWS_; rr += 256) {
        const int j = j0 + rr;
        smk[rr] = (j >= 0 && j < T_) ? mask[b * T_ + j] : 0;
    }
    __syncthreads();

    const int q3 = lane >> 3;
    const int l7 = lane & 7;

    unsigned qfh[4][4], qfl[4][4];
    {
        const unsigned rbase = (unsigned)(w * 16 + (q3 & 1) * 8 + l7);
#pragma unroll
        for (int kk = 0; kk < 4; kk++) {
            const unsigned off = (rbase * ASTR_ + (unsigned)(kk * 16 + (q3 >> 1) * 8)) * 2;
            ldsm4(qfh[kk], uQh + off);
            ldsm4(qfl[kk], uQl + off);
        }
    }

    float sacc[16][4] = {};
#pragma unroll
    for (int nt = 0; nt < 8; nt++) {
        const unsigned nrow = (unsigned)(w * 16 + nt * 16 + (q3 >> 1) * 8 + l7);
#pragma unroll
        for (int kk = 0; kk < 4; kk++) {
            const unsigned off = (nrow * ASTR_ + (unsigned)(kk * 16 + (q3 & 1) * 8)) * 2;
            unsigned kbh[4], kbl[4];
            ldsm4(kbh, uKVh + off);
            ldsm4(kbl, uKVl + off);
            mma_bf16(sacc[2*nt],   qfh[kk], &kbh[0]);
            mma_bf16(sacc[2*nt],   qfh[kk], &kbl[0]);
            mma_bf16(sacc[2*nt],   qfl[kk], &kbh[0]);
            mma_bf16(sacc[2*nt+1], qfh[kk], &kbh[2]);
            mma_bf16(sacc[2*nt+1], qfh[kk], &kbl[2]);
            mma_bf16(sacc[2*nt+1], qfl[kk], &kbh[2]);
        }
    }

    __syncthreads();
    for (int u = tid; u < AROWS_ * 8; u += 256) {
        const int rr = u >> 3, g = u & 7;
        const int j = j0 + rr;
        uint4 vh4 = {0,0,0,0}, vl4 = {0,0,0,0};
        if (j >= 0 && j < T_) {
            const size_t gi = (size_t)(b * T_ + j) * FEAT_ + h * DK_ + g * 8;
            vh4 = *(const uint4*)(g_pvh + gi);
            vl4 = *(const uint4*)(g_pvl + gi);
        }
        *(uint4*)(sKVh + rr * ASTR_ + g * 8) = vh4;
        *(uint4*)(sKVl + rr * ASTR_ + g * 8) = vl4;
    }

    const int r = lane >> 2;
    const int c2 = 2 * (lane & 3);
    const float spanv = span[h];
    float mx0 = -1e30f, mx1 = -1e30f;
#pragma unroll
    for (int nt8 = 0; nt8 < 16; nt8++) {
#pragma unroll
        for (int e = 0; e < 2; e++) {
            const int c = 8 * nt8 + c2 + e;
            const int mv = smk[w * 16 + c];
            const int s0 = c - r;
            const int s1 = c - r - 8;
            const bool v0 = (s0 >= 0) && (s0 < SPAN_) && (mv != 0);
            const bool v1 = (s1 >= 0) && (s1 < SPAN_) && (mv != 0);
            const float x0 = v0 ? sacc[nt8][e]     * 0.125f : -1e30f;
            const float x1 = v1 ? sacc[nt8][2 + e] * 0.125f : -1e30f;
            sacc[nt8][e] = x0;
            sacc[nt8][2 + e] = x1;
            mx0 = fmaxf(mx0, x0);
            mx1 = fmaxf(mx1, x1);
        }
    }
    mx0 = fmaxf(mx0, __shfl_xor_sync(0xffffffffu, mx0, 1));
    mx0 = fmaxf(mx0, __shfl_xor_sync(0xffffffffu, mx0, 2));
    mx1 = fmaxf(mx1, __shfl_xor_sync(0xffffffffu, mx1, 1));
    mx1 = fmaxf(mx1, __shfl_xor_sync(0xffffffffu, mx1, 2));

    float E0 = 0.f, S0 = 0.f, E1 = 0.f, S1 = 0.f;
#pragma unroll
    for (int nt8 = 0; nt8 < 16; nt8++) {
#pragma unroll
        for (int e = 0; e < 2; e++) {
            const int c = 8 * nt8 + c2 + e;
            const int s0 = c - r;
            const int s1 = c - r - 8;
            const float sf0 = fminf(fmaxf(((float)s0 - 99.0f + spanv * 100.0f) * 0.5f + 1.0f, 0.f), 1.f);
            const float sf1 = fminf(fmaxf(((float)s1 - 99.0f + spanv * 100.0f) * 0.5f + 1.0f, 0.f), 1.f);
            const float e0 = __expf(sacc[nt8][e] - mx0);
            const float e1 = __expf(sacc[nt8][2 + e] - mx1);
            E0 += e0; S0 += e0 * sf0;
            E1 += e1; S1 += e1 * sf1;
            sacc[nt8][e] = e0 * sf0;
            sacc[nt8][2 + e] = e1 * sf1;
        }
    }
    E0 += __shfl_xor_sync(0xffffffffu, E0, 1);  E0 += __shfl_xor_sync(0xffffffffu, E0, 2);
    S0 += __shfl_xor_sync(0xffffffffu, S0, 1);  S0 += __shfl_xor_sync(0xffffffffu, S0, 2);
    E1 += __shfl_xor_sync(0xffffffffu, E1, 1);  E1 += __shfl_xor_sync(0xffffffffu, E1, 2);
    S1 += __shfl_xor_sync(0xffffffffu, S1, 1);  S1 += __shfl_xor_sync(0xffffffffu, S1, 2);
    const float inv0 = (mx0 > -1e29f) ? 1.0f / (S0 + 1e-8f * E0) : 0.f;
    const float inv1 = (mx1 > -1e29f) ? 1.0f / (S1 + 1e-8f * E1) : 0.f;

    unsigned pah[8][4], pal[8][4];
#pragma unroll
    for (int j8 = 0; j8 < 8; j8++) {
        pah[j8][0] = pack_split_hi(sacc[2*j8][0]*inv0,   sacc[2*j8][1]*inv0,   pal[j8][0]);
        pah[j8][1] = pack_split_hi(sacc[2*j8][2]*inv1,   sacc[2*j8][3]*inv1,   pal[j8][1]);
        pah[j8][2] = pack_split_hi(sacc[2*j8+1][0]*inv0, sacc[2*j8+1][1]*inv0, pal[j8][2]);
        pah[j8][3] = pack_split_hi(sacc[2*j8+1][2]*inv1, sacc[2*j8+1][3]*inv1, pal[j8][3]);
    }

    __syncthreads();

    float oacc[8][4] = {};
#pragma unroll
    for (int kk2 = 0; kk2 < 8; kk2++) {
        const unsigned krow = (unsigned)(w * 16 + kk2 * 16 + (q3 & 1) * 8 + l7);
#pragma unroll
        for (int nt = 0; nt < 4; nt++) {
            const unsigned off = (krow * ASTR_ + (unsigned)(nt * 16 + (q3 >> 1) * 8)) * 2;
            unsigned vbh[4], vbl[4];
            ldsm4t(vbh, uKVh + off);
            ldsm4t(vbl, uKVl + off);
            mma_bf16(oacc[2*nt],   pah[kk2], &vbh[0]);
            mma_bf16(oacc[2*nt],   pah[kk2], &vbl[0]);
            mma_bf16(oacc[2*nt],   pal[kk2], &vbh[0]);
            mma_bf16(oacc[2*nt+1], pah[kk2], &vbh[2]);
            mma_bf16(oacc[2*nt+1], pah[kk2], &vbl[2]);
            mma_bf16(oacc[2*nt+1], pal[kk2], &vbh[2]);
        }
    }

    // Write context as single fp16 (A-operand of the out projection)
    const int tr = t0 + w * 16 + r;
#pragma unroll
    for (int nf = 0; nf < 8; nf++) {
        const int col = 8 * nf + c2;
        const size_t i0 = (size_t)(b * T_ + tr) * FEAT_ + h * DK_ + col;
        const size_t i1 = (size_t)(b * T_ + tr + 8) * FEAT_ + h * DK_ + col;
        __half2 p0 = __floats2half2_rn(oacc[nf][0], oacc[nf][1]);
        __half2 p1 = __floats2half2_rn(oacc[nf][2], oacc[nf][3]);
        *(__half2*)(g_xf + i0) = p0;
        *(__half2*)(g_xf + i1) = p1;
    }
}

// ---------------------------------------------------------------------------
// Launch
// ---------------------------------------------------------------------------
extern "C" void kernel_launch(void* const* d_in, const int* in_sizes, int n_in,
                              void* d_out, int out_size)
{
    (void)in_sizes; (void)n_in; (void)out_size;
    const float* query = (const float*)d_in[0];
    const float* key   = (const float*)d_in[1];
    const float* value = (const float*)d_in[2];
    const int*   mask  = (const int*)  d_in[3];
    const float* Wq    = (const float*)d_in[4];
    const float* bq    = (const float*)d_in[5];
    const float* Wk    = (const float*)d_in[6];
    const float* bk    = (const float*)d_in[7];
    const float* Wv    = (const float*)d_in[8];
    const float* bv    = (const float*)d_in[9];
    const float* Wo    = (const float*)d_in[10];
    const float* bo    = (const float*)d_in[11];
    const float* span  = (const float*)d_in[12];
    float* out = (float*)d_out;

    static int attr_set = 0;
    if (!attr_set) {
        cudaFuncSetAttribute(attn_mma_kernel, cudaFuncAttributeMaxDynamicSharedMemorySize, ATT_SMEM);
        cudaFuncSetAttribute(hmma_gemm_qkv, cudaFuncAttributeMaxDynamicSharedMemorySize, GEMM_SMEM);
        cudaFuncSetAttribute(hmma_gemm_out, cudaFuncAttributeMaxDynamicSharedMemorySize, GEMM_SMEM);
        attr_set = 1;
    }

    convert_inputs_kernel<<<dim3(256, 3), 256>>>(query, key, value);
    convert_weights_kernel<<<dim3(16, 16, 4), dim3(32, 8)>>>(Wq, Wk, Wv, Wo);
    hmma_gemm_qkv<<<dim3(NTOK_/GBM_, FEAT_/GBN_, 3), 256, GEMM_SMEM>>>(bq, bk, bv);
    attn_mma_kernel<<<dim3(T_/ABT_, B_*H_), 256, ATT_SMEM>>>(mask, span);
    hmma_gemm_out<<<dim3(NTOK_/GBM_, FEAT_/GBN_), 256, GEMM_SMEM>>>(bo, out);
}

// round 15
// speedup vs baseline: 5.4167x; 1.1523x over previous
#include <cuda_runtime.h>
#include <cuda_bf16.h>
#include <cuda_fp16.h>
#include <cstdint>
#include <stdint.h>
#include <float.h>
#include <math.h>

// Problem constants
#define B_    4
#define T_    1024
#define FEAT_ 512
#define H_    8
#define DK_   64
#define SPAN_ 100
#define PADL_ 50
#define NTOK_ (B_*T_)
#define NEL_  (NTOK_*FEAT_)

// HMMA GEMM tiling: 128x64 tile, BK=32, cp.async double-buffered, fp16 x fp16.
#define GBM_  128
#define GBN_  64
#define BKg   32
#define PADK  40
#define SAF_BYTES (GBM_*PADK*2)
#define SW_BYTES  (GBN_*PADK*2)
#define BUF_BYTES (SAF_BYTES + SW_BYTES)
#define GEMM_SMEM (2*BUF_BYTES)

// MMA attention tiling — single fp16 operands, V aliases K smem
#define ABT_   128
#define AROWS_ 240
#define ASTR_  72
#define SQ_OFF   0
#define SKV_OFF  (SQ_OFF + ABT_*ASTR_*2)        // 18432
#define SMK_OFF  (SKV_OFF + AROWS_*ASTR_*2)     // 52992
#define ATT_SMEM (SMK_OFF + AROWS_*4)           // 53952

// ---------------------------------------------------------------------------
// Device scratch
// ---------------------------------------------------------------------------
__device__ __half g_qf[NEL_];               // inputs, fp16
__device__ __half g_kf[NEL_];
__device__ __half g_vf[NEL_];
__device__ __half g_pq[NEL_];               // projected q/k/v, fp16
__device__ __half g_pk[NEL_];
__device__ __half g_pv[NEL_];
__device__ __half g_xf[NEL_];               // context, fp16
__device__ __half g_wt[4 * FEAT_ * FEAT_];  // transposed weights, fp16

// ---------------------------------------------------------------------------
// PTX helpers
// ---------------------------------------------------------------------------
__device__ __forceinline__ unsigned smem_u32(const void* p) {
    unsigned a;
    asm("{ .reg .u64 t; cvta.to.shared.u64 t, %1; cvt.u32.u64 %0, t; }" : "=r"(a) : "l"(p));
    return a;
}
__device__ __forceinline__ void mma_fp16(float* c, const unsigned* a, const unsigned* b) {
    asm volatile(
        "mma.sync.aligned.m16n8k16.row.col.f32.f16.f16.f32 "
        "{%0,%1,%2,%3}, {%4,%5,%6,%7}, {%8,%9}, {%0,%1,%2,%3};"
        : "+f"(c[0]), "+f"(c[1]), "+f"(c[2]), "+f"(c[3])
        : "r"(a[0]), "r"(a[1]), "r"(a[2]), "r"(a[3]), "r"(b[0]), "r"(b[1]));
}
__device__ __forceinline__ void ldsm4(unsigned* r, unsigned addr) {
    asm volatile("ldmatrix.sync.aligned.m8n8.x4.shared.b16 {%0,%1,%2,%3}, [%4];"
        : "=r"(r[0]), "=r"(r[1]), "=r"(r[2]), "=r"(r[3]) : "r"(addr));
}
__device__ __forceinline__ void ldsm4t(unsigned* r, unsigned addr) {
    asm volatile("ldmatrix.sync.aligned.m8n8.x4.trans.shared.b16 {%0,%1,%2,%3}, [%4];"
        : "=r"(r[0]), "=r"(r[1]), "=r"(r[2]), "=r"(r[3]) : "r"(addr));
}
__device__ __forceinline__ void cp16(unsigned dst, const void* src) {
    asm volatile("cp.async.cg.shared.global [%0], [%1], 16;" :: "r"(dst), "l"(src));
}
__device__ __forceinline__ void cp_commit() {
    asm volatile("cp.async.commit_group;" ::: "memory");
}
__device__ __forceinline__ void cp_wait1() {
    asm volatile("cp.async.wait_group 1;" ::: "memory");
}
__device__ __forceinline__ void cp_wait0() {
    asm volatile("cp.async.wait_group 0;" ::: "memory");
}
__device__ __forceinline__ unsigned pack_h2(float a, float b) {
    __half2 p = __floats2half2_rn(a, b);
    return *(unsigned*)&p;
}

// ---------------------------------------------------------------------------
// Convert inputs fp32 -> fp16. blockIdx.y selects q/k/v.
// ---------------------------------------------------------------------------
__global__ __launch_bounds__(256)
void convert_inputs_kernel(const float* __restrict__ q, const float* __restrict__ k,
                           const float* __restrict__ v)
{
    const float* src;
    __half* dst;
    if (blockIdx.y == 0)      { src = q; dst = g_qf; }
    else if (blockIdx.y == 1) { src = k; dst = g_kf; }
    else                      { src = v; dst = g_vf; }

    const int n4 = NEL_ / 4;
    for (int i = blockIdx.x * blockDim.x + threadIdx.x; i < n4; i += gridDim.x * blockDim.x) {
        float4 x = ((const float4*)src)[i];
        ((unsigned*)dst)[i*2]   = pack_h2(x.x, x.y);
        ((unsigned*)dst)[i*2+1] = pack_h2(x.z, x.w);
    }
}

// ---------------------------------------------------------------------------
// Transpose + convert weights: W[k][n] fp32 -> Wt[n][k] fp16.
// ---------------------------------------------------------------------------
__global__ __launch_bounds__(256)
void convert_weights_kernel(const float* __restrict__ Wq, const float* __restrict__ Wk,
                            const float* __restrict__ Wv, const float* __restrict__ Wo)
{
    const int z = blockIdx.z;
    const float* W = (z == 0) ? Wq : (z == 1) ? Wk : (z == 2) ? Wv : Wo;
    __half* Tw = g_wt + (size_t)z * FEAT_ * FEAT_;

    __shared__ float tile[32][33];
    const int tx = threadIdx.x, ty = threadIdx.y;
    const int kb = blockIdx.y * 32, nb = blockIdx.x * 32;
#pragma unroll
    for (int i = 0; i < 4; i++)
        tile[ty + i*8][tx] = W[(size_t)(kb + ty + i*8) * FEAT_ + nb + tx];
    __syncthreads();
#pragma unroll
    for (int i = 0; i < 4; i++) {
        const int n = nb + ty + i*8;
        const int kk = kb + tx;
        Tw[(size_t)n * FEAT_ + kk] = __float2half_rn(tile[tx][ty + i*8]);
    }
}

// ---------------------------------------------------------------------------
// fp16 HMMA GEMM: C = A @ W^T + bias. 128x64 tile, double-buffered cp.async.
// HALF_OUT: write fp16 (projection outputs); else fp32 (final output).
// ---------------------------------------------------------------------------
template<bool HALF_OUT>
__device__ __forceinline__
void hmma_gemm_body(const __half* __restrict__ Af,
                    const __half* __restrict__ Wt,
                    const float* __restrict__ bias, float* __restrict__ C,
                    __half* __restrict__ Chf,
                    int bm, int bn)
{
    extern __shared__ char smg[];
    const unsigned sb = smem_u32(smg);

    const int tid = threadIdx.x;
    const int wid = tid >> 5;
    const int lane = tid & 31;
    const int wm = (wid & 3) * 32;
    const int wn = (wid >> 2) * 32;

    const int q3 = lane >> 3;
    const int l7 = lane & 7;

    const int ar0 = tid >> 2, as0 = tid & 3;
    const int ar1 = (tid + 256) >> 2;
    const int wr0 = tid >> 2, ws0 = tid & 3;

    float acc[2][4][4] = {};

    {
        const unsigned base = sb;
        cp16(base + (unsigned)(ar0 * PADK + as0 * 8) * 2,
             Af + (size_t)(bm * GBM_ + ar0) * FEAT_ + as0 * 8);
        cp16(base + (unsigned)(ar1 * PADK + as0 * 8) * 2,
             Af + (size_t)(bm * GBM_ + ar1) * FEAT_ + as0 * 8);
        cp16(base + SAF_BYTES + (unsigned)(wr0 * PADK + ws0 * 8) * 2,
             Wt + (size_t)(bn * GBN_ + wr0) * FEAT_ + ws0 * 8);
        cp_commit();
    }

    const int NIT = FEAT_ / BKg;
    for (int it = 0; it < NIT; it++) {
        if (it + 1 < NIT) {
            const int kt = (it + 1) * BKg;
            const unsigned base = sb + (unsigned)(((it + 1) & 1) * BUF_BYTES);
            cp16(base + (unsigned)(ar0 * PADK + as0 * 8) * 2,
                 Af + (size_t)(bm * GBM_ + ar0) * FEAT_ + kt + as0 * 8);
            cp16(base + (unsigned)(ar1 * PADK + as0 * 8) * 2,
                 Af + (size_t)(bm * GBM_ + ar1) * FEAT_ + kt + as0 * 8);
            cp16(base + SAF_BYTES + (unsigned)(wr0 * PADK + ws0 * 8) * 2,
                 Wt + (size_t)(bn * GBN_ + wr0) * FEAT_ + kt + ws0 * 8);
            cp_commit();
            cp_wait1();
        } else {
            cp_wait0();
        }
        __syncthreads();

        const unsigned uB = sb + (unsigned)((it & 1) * BUF_BYTES);
        const unsigned uAf = uB;
        const unsigned uW  = uB + SAF_BYTES;

#pragma unroll
        for (int ks = 0; ks < 2; ks++) {
            const int ko = ks * 16;
            unsigned af[2][4];
            unsigned bw[8];
#pragma unroll
            for (int mf = 0; mf < 2; mf++) {
                const unsigned arow = (unsigned)(wm + mf * 16 + (q3 & 1) * 8 + l7);
                const unsigned ab = (arow * PADK + (unsigned)(ko + (q3 >> 1) * 8)) * 2;
                ldsm4(af[mf], uAf + ab);
            }
            {
                const unsigned nrow = (unsigned)(wn + (q3 >> 1) * 8 + l7);
                const unsigned bb = (nrow * PADK + (unsigned)(ko + (q3 & 1) * 8)) * 2;
                ldsm4(bw, uW + bb);
                const unsigned bb2 = ((nrow + 16) * PADK + (unsigned)(ko + (q3 & 1) * 8)) * 2;
                ldsm4(bw + 4, uW + bb2);
            }
#pragma unroll
            for (int mf = 0; mf < 2; mf++)
#pragma unroll
                for (int nf = 0; nf < 4; nf++)
                    mma_fp16(acc[mf][nf], af[mf], bw + 2 * nf);
        }
        __syncthreads();
    }

#pragma unroll
    for (int mf = 0; mf < 2; mf++) {
        const int r0 = bm * GBM_ + wm + mf * 16 + (lane >> 2);
#pragma unroll
        for (int nf = 0; nf < 4; nf++) {
            const int col = bn * GBN_ + wn + nf * 8 + 2 * (lane & 3);
            const float b0 = bias[col], b1 = bias[col + 1];
            const float v00 = acc[mf][nf][0] + b0, v01 = acc[mf][nf][1] + b1;
            const float v10 = acc[mf][nf][2] + b0, v11 = acc[mf][nf][3] + b1;
            if (HALF_OUT) {
                *(unsigned*)(Chf + (size_t)r0 * FEAT_ + col)       = pack_h2(v00, v01);
                *(unsigned*)(Chf + (size_t)(r0 + 8) * FEAT_ + col) = pack_h2(v10, v11);
            } else {
                *(float2*)(C + (size_t)r0 * FEAT_ + col) = make_float2(v00, v01);
                *(float2*)(C + (size_t)(r0 + 8) * FEAT_ + col) = make_float2(v10, v11);
            }
        }
    }
}

__global__ __launch_bounds__(256, 2)
void hmma_gemm_qkv(const float* __restrict__ bq, const float* __restrict__ bk,
                   const float* __restrict__ bv)
{
    const __half* Af;
    const float* bi;
    __half* Ch;
    int wz;
    if (blockIdx.z == 0)      { Af = g_qf; bi = bq; Ch = g_pq; wz = 0; }
    else if (blockIdx.z == 1) { Af = g_kf; bi = bk; Ch = g_pk; wz = 1; }
    else                      { Af = g_vf; bi = bv; Ch = g_pv; wz = 2; }
    hmma_gemm_body<true>(Af, g_wt + (size_t)wz * FEAT_ * FEAT_,
                         bi, nullptr, Ch, blockIdx.x, blockIdx.y);
}

__global__ __launch_bounds__(256, 2)
void hmma_gemm_out(const float* __restrict__ bo, float* __restrict__ out)
{
    hmma_gemm_body<false>(g_xf, g_wt + (size_t)3 * FEAT_ * FEAT_,
                          bo, out, nullptr, blockIdx.x, blockIdx.y);
}

// ---------------------------------------------------------------------------
// MMA band attention — single fp16 operands. V aliases K smem.
// ---------------------------------------------------------------------------
__global__ __launch_bounds__(256, 2)
void attn_mma_kernel(const int* __restrict__ mask, const float* __restrict__ span)
{
    extern __shared__ char sm[];
    const unsigned uQ  = smem_u32(sm + SQ_OFF);
    const unsigned uKV = smem_u32(sm + SKV_OFF);
    int* smk = (int*)(sm + SMK_OFF);

    const int bx = blockIdx.x, bhz = blockIdx.y;
    const int b = bhz >> 3, h = bhz & 7;
    const int t0 = bx * ABT_;
    const int j0 = t0 - PADL_;
    const int tid = threadIdx.x;
    const int w = tid >> 5, lane = tid & 31;

    __half* sQ  = (__half*)(sm + SQ_OFF);
    __half* sKV = (__half*)(sm + SKV_OFF);

    // Stage Q + K (+mask)
    for (int u = tid; u < ABT_ * 8; u += 256) {
        const int rr = u >> 3, g = u & 7;
        const size_t gi = (size_t)(b * T_ + t0 + rr) * FEAT_ + h * DK_ + g * 8;
        *(uint4*)(sQ + rr * ASTR_ + g * 8) = *(const uint4*)(g_pq + gi);
    }
    for (int u = tid; u < AROWS_ * 8; u += 256) {
        const int rr = u >> 3, g = u & 7;
        const int j = j0 + rr;
        uint4 k4 = {0,0,0,0};
        if (j >= 0 && j < T_) {
            const size_t gi = (size_t)(b * T_ + j) * FEAT_ + h * DK_ + g * 8;
            k4 = *(const uint4*)(g_pk + gi);
        }
        *(uint4*)(sKV + rr * ASTR_ + g * 8) = k4;
    }
    for (int rr = tid; rr < AROWS_; rr += 256) {
        const int j = j0 + rr;
        smk[rr] = (j >= 0 && j < T_) ? mask[b * T_ + j] : 0;
    }
    __syncthreads();

    const int q3 = lane >> 3;
    const int l7 = lane & 7;

    // Q fragments (4 k-steps)
    unsigned qf[4][4];
    {
        const unsigned rbase = (unsigned)(w * 16 + (q3 & 1) * 8 + l7);
#pragma unroll
        for (int kk = 0; kk < 4; kk++) {
            const unsigned off = (rbase * ASTR_ + (unsigned)(kk * 16 + (q3 >> 1) * 8)) * 2;
            ldsm4(qf[kk], uQ + off);
        }
    }

    // Scores
    float sacc[16][4] = {};
#pragma unroll
    for (int nt = 0; nt < 8; nt++) {
        const unsigned nrow = (unsigned)(w * 16 + nt * 16 + (q3 >> 1) * 8 + l7);
#pragma unroll
        for (int kk = 0; kk < 4; kk++) {
            const unsigned off = (nrow * ASTR_ + (unsigned)(kk * 16 + (q3 & 1) * 8)) * 2;
            unsigned kb[4];
            ldsm4(kb, uKV + off);
            mma_fp16(sacc[2*nt],   qf[kk], &kb[0]);
            mma_fp16(sacc[2*nt+1], qf[kk], &kb[2]);
        }
    }

    // K dead — stage V over it; softmax overlaps
    __syncthreads();
    for (int u = tid; u < AROWS_ * 8; u += 256) {
        const int rr = u >> 3, g = u & 7;
        const int j = j0 + rr;
        uint4 v4 = {0,0,0,0};
        if (j >= 0 && j < T_) {
            const size_t gi = (size_t)(b * T_ + j) * FEAT_ + h * DK_ + g * 8;
            v4 = *(const uint4*)(g_pv + gi);
        }
        *(uint4*)(sKV + rr * ASTR_ + g * 8) = v4;
    }

    // Softmax + adaptive span
    const int r = lane >> 2;
    const int c2 = 2 * (lane & 3);
    const float spanv = span[h];
    float mx0 = -1e30f, mx1 = -1e30f;
#pragma unroll
    for (int nt8 = 0; nt8 < 16; nt8++) {
#pragma unroll
        for (int e = 0; e < 2; e++) {
            const int c = 8 * nt8 + c2 + e;
            const int mv = smk[w * 16 + c];
            const int s0 = c - r;
            const int s1 = c - r - 8;
            const bool v0 = (s0 >= 0) && (s0 < SPAN_) && (mv != 0);
            const bool v1 = (s1 >= 0) && (s1 < SPAN_) && (mv != 0);
            const float x0 = v0 ? sacc[nt8][e]     * 0.125f : -1e30f;
            const float x1 = v1 ? sacc[nt8][2 + e] * 0.125f : -1e30f;
            sacc[nt8][e] = x0;
            sacc[nt8][2 + e] = x1;
            mx0 = fmaxf(mx0, x0);
            mx1 = fmaxf(mx1, x1);
        }
    }
    mx0 = fmaxf(mx0, __shfl_xor_sync(0xffffffffu, mx0, 1));
    mx0 = fmaxf(mx0, __shfl_xor_sync(0xffffffffu, mx0, 2));
    mx1 = fmaxf(mx1, __shfl_xor_sync(0xffffffffu, mx1, 1));
    mx1 = fmaxf(mx1, __shfl_xor_sync(0xffffffffu, mx1, 2));

    float E0 = 0.f, S0 = 0.f, E1 = 0.f, S1 = 0.f;
#pragma unroll
    for (int nt8 = 0; nt8 < 16; nt8++) {
#pragma unroll
        for (int e = 0; e < 2; e++) {
            const int c = 8 * nt8 + c2 + e;
            const int s0 = c - r;
            const int s1 = c - r - 8;
            const float sf0 = fminf(fmaxf(((float)s0 - 99.0f + spanv * 100.0f) * 0.5f + 1.0f, 0.f), 1.f);
            const float sf1 = fminf(fmaxf(((float)s1 - 99.0f + spanv * 100.0f) * 0.5f + 1.0f, 0.f), 1.f);
            const float e0 = __expf(sacc[nt8][e] - mx0);
            const float e1 = __expf(sacc[nt8][2 + e] - mx1);
            E0 += e0; S0 += e0 * sf0;
            E1 += e1; S1 += e1 * sf1;
            sacc[nt8][e] = e0 * sf0;
            sacc[nt8][2 + e] = e1 * sf1;
        }
    }
    E0 += __shfl_xor_sync(0xffffffffu, E0, 1);  E0 += __shfl_xor_sync(0xffffffffu, E0, 2);
    S0 += __shfl_xor_sync(0xffffffffu, S0, 1);  S0 += __shfl_xor_sync(0xffffffffu, S0, 2);
    E1 += __shfl_xor_sync(0xffffffffu, E1, 1);  E1 += __shfl_xor_sync(0xffffffffu, E1, 2);
    S1 += __shfl_xor_sync(0xffffffffu, S1, 1);  S1 += __shfl_xor_sync(0xffffffffu, S1, 2);
    const float inv0 = (mx0 > -1e29f) ? 1.0f / (S0 + 1e-8f * E0) : 0.f;
    const float inv1 = (mx1 > -1e29f) ? 1.0f / (S1 + 1e-8f * E1) : 0.f;

    // Repack P -> fp16 A-fragments
    unsigned pa[8][4];
#pragma unroll
    for (int j8 = 0; j8 < 8; j8++) {
        pa[j8][0] = pack_h2(sacc[2*j8][0]*inv0,   sacc[2*j8][1]*inv0);
        pa[j8][1] = pack_h2(sacc[2*j8][2]*inv1,   sacc[2*j8][3]*inv1);
        pa[j8][2] = pack_h2(sacc[2*j8+1][0]*inv0, sacc[2*j8+1][1]*inv0);
        pa[j8][3] = pack_h2(sacc[2*j8+1][2]*inv1, sacc[2*j8+1][3]*inv1);
    }

    __syncthreads();   // V staging complete

    // O = P · V
    float oacc[8][4] = {};
#pragma unroll
    for (int kk2 = 0; kk2 < 8; kk2++) {
        const unsigned krow = (unsigned)(w * 16 + kk2 * 16 + (q3 & 1) * 8 + l7);
#pragma unroll
        for (int nt = 0; nt < 4; nt++) {
            const unsigned off = (krow * ASTR_ + (unsigned)(nt * 16 + (q3 >> 1) * 8)) * 2;
            unsigned vb[4];
            ldsm4t(vb, uKV + off);
            mma_fp16(oacc[2*nt],   pa[kk2], &vb[0]);
            mma_fp16(oacc[2*nt+1], pa[kk2], &vb[2]);
        }
    }

    // Write context fp16
    const int tr = t0 + w * 16 + r;
#pragma unroll
    for (int nf = 0; nf < 8; nf++) {
        const int col = 8 * nf + c2;
        const size_t i0 = (size_t)(b * T_ + tr) * FEAT_ + h * DK_ + col;
        const size_t i1 = (size_t)(b * T_ + tr + 8) * FEAT_ + h * DK_ + col;
        *(unsigned*)(g_xf + i0) = pack_h2(oacc[nf][0], oacc[nf][1]);
        *(unsigned*)(g_xf + i1) = pack_h2(oacc[nf][2], oacc[nf][3]);
    }
}

// ---------------------------------------------------------------------------
// Launch
// ---------------------------------------------------------------------------
extern "C" void kernel_launch(void* const* d_in, const int* in_sizes, int n_in,
                              void* d_out, int out_size)
{
    (void)in_sizes; (void)n_in; (void)out_size;
    const float* query = (const float*)d_in[0];
    const float* key   = (const float*)d_in[1];
    const float* value = (const float*)d_in[2];
    const int*   mask  = (const int*)  d_in[3];
    const float* Wq    = (const float*)d_in[4];
    const float* bq    = (const float*)d_in[5];
    const float* Wk    = (const float*)d_in[6];
    const float* bk    = (const float*)d_in[7];
    const float* Wv    = (const float*)d_in[8];
    const float* bv    = (const float*)d_in[9];
    const float* Wo    = (const float*)d_in[10];
    const float* bo    = (const float*)d_in[11];
    const float* span  = (const float*)d_in[12];
    float* out = (float*)d_out;

    static int attr_set = 0;
    if (!attr_set) {
        cudaFuncSetAttribute(attn_mma_kernel, cudaFuncAttributeMaxDynamicSharedMemorySize, ATT_SMEM);
        cudaFuncSetAttribute(hmma_gemm_qkv, cudaFuncAttributeMaxDynamicSharedMemorySize, GEMM_SMEM);
        cudaFuncSetAttribute(hmma_gemm_out, cudaFuncAttributeMaxDynamicSharedMemorySize, GEMM_SMEM);
        attr_set = 1;
    }

    convert_inputs_kernel<<<dim3(256, 3), 256>>>(query, key, value);
    convert_weights_kernel<<<dim3(16, 16, 4), dim3(32, 8)>>>(Wq, Wk, Wv, Wo);
    hmma_gemm_qkv<<<dim3(NTOK_/GBM_, FEAT_/GBN_, 3), 256, GEMM_SMEM>>>(bq, bk, bv);
    attn_mma_kernel<<<dim3(T_/ABT_, B_*H_), 256, ATT_SMEM>>>(mask, span);
    hmma_gemm_out<<<dim3(NTOK_/GBM_, FEAT_/GBN_), 256, GEMM_SMEM>>>(bo, out);
}